// round 6
// baseline (speedup 1.0000x reference)
#include <cuda_runtime.h>
#include <math.h>

#define Bd 2
#define Td 2048
#define Hd 1024
#define Ld 256
#define Fd 2048
#define Ed 7
#define BTd (Bd*Td)

// ---------------- scratch (device globals; no allocation) ----------------
__device__ float g_h[BTd*Hd];
__device__ float g_kvlat[BTd*Ld];
__device__ float g_qlat[BTd*Ld];
__device__ float g_v[BTd*Hd];
__device__ float g_q[BTd*Hd];
__device__ float g_k[BTd*Hd];
__device__ float g_scores[(size_t)Bd*Td*Td];
__device__ float g_y[BTd*Hd];
__device__ float g_x1[BTd*Hd];
__device__ float g_h2[BTd*Hd];
__device__ float g_gbuf[(size_t)8*BTd*Fd];   // per-expert slices (7 routed + 1 shared)
__device__ float g_shb[BTd*Hd];
__device__ float g_r0[BTd*Hd];
__device__ float g_r1[BTd*Hd];
__device__ int   g_cnt[Ed];
__device__ int   g_gidx[Ed*BTd];
__device__ float g_gwt[Ed*BTd];
__device__ int   g_gslot[Ed*BTd];

// ---------------- block reduce ----------------
template<bool DOMAX>
__device__ __forceinline__ float blockReduce(float v) {
    __shared__ float sh[8];
    __shared__ float res;
    int lane = threadIdx.x & 31, w = threadIdx.x >> 5;
    #pragma unroll
    for (int o = 16; o; o >>= 1) {
        float t = __shfl_xor_sync(0xffffffffu, v, o);
        v = DOMAX ? fmaxf(v, t) : v + t;
    }
    if (lane == 0) sh[w] = v;
    __syncthreads();
    if (w == 0) {
        v = (lane < (int)(blockDim.x >> 5)) ? sh[lane] : (DOMAX ? -3.4e38f : 0.f);
        #pragma unroll
        for (int o = 4; o; o >>= 1) {
            float t = __shfl_xor_sync(0xffffffffu, v, o);
            v = DOMAX ? fmaxf(v, t) : v + t;
        }
        if (lane == 0) res = v;
    }
    __syncthreads();
    return res;
}

// ---------------- layernorm ----------------
__global__ void ln_kernel(const float* __restrict__ x, const float* __restrict__ w,
                          float* __restrict__ out) {
    int row = blockIdx.x;
    const float* xr = x + (size_t)row * Hd;
    int t = threadIdx.x;
    float v[4];
    float s = 0.f;
    #pragma unroll
    for (int i = 0; i < 4; i++) { v[i] = xr[t + 256*i]; s += v[i]; }
    s = blockReduce<false>(s);
    float mu = s * (1.f / Hd);
    float q = 0.f;
    #pragma unroll
    for (int i = 0; i < 4; i++) { float d = v[i] - mu; q += d * d; }
    q = blockReduce<false>(q);
    float rs = rsqrtf(q * (1.f / Hd) + 1e-5f);
    float* o = out + (size_t)row * Hd;
    #pragma unroll
    for (int i = 0; i < 4; i++) o[t + 256*i] = (v[i] - mu) * rs * w[t + 256*i];
}

// ---------------- rope ----------------
__global__ void rope_kernel(float* __restrict__ q, float* __restrict__ k) {
    int row = blockIdx.x;
    int t = row % Td;
    size_t base = (size_t)row * Hd;
    #pragma unroll
    for (int it = 0; it < 2; it++) {
        int p = threadIdx.x + 256 * it;
        double invf = exp(-(double)(2 * p) / 1024.0 * 9.210340371976184);
        float f = (float)t * (float)invf;
        float c = cosf(f), s = sinf(f);
        float q1 = q[base + p], q2 = q[base + p + 512];
        q[base + p]       = q1 * c - q2 * s;
        q[base + p + 512] = q2 * c + q1 * s;
        float k1 = k[base + p], k2 = k[base + p + 512];
        k[base + p]       = k1 * c - k2 * s;
        k[base + p + 512] = k2 * c + k1 * s;
    }
}

// ---------------- softmax (causal) ----------------
__global__ void softmax_kernel(float* __restrict__ sc) {
    int b = blockIdx.y, i = blockIdx.x;
    float* row = sc + ((size_t)b * Td + i) * Td;
    int t = threadIdx.x;
    int n = i + 1;
    float mx = -3.4e38f;
    for (int j = t; j < n; j += 256) mx = fmaxf(mx, row[j]);
    mx = blockReduce<true>(mx);
    float s = 0.f;
    for (int j = t; j < n; j += 256) s += expf(row[j] - mx);
    s = blockReduce<false>(s);
    float inv = 1.f / s;
    for (int j = t; j < Td; j += 256)
        row[j] = (j < n) ? expf(row[j] - mx) * inv : 0.f;
}

// ---------------- router + top2 gather lists ----------------
__global__ void zero_cnt_kernel() {
    if (threadIdx.x < Ed) g_cnt[threadIdx.x] = 0;
}

__global__ void router_kernel(const float* __restrict__ h2, const float* __restrict__ rw,
                              const float* __restrict__ rb) {
    int m = blockIdx.x;
    int w = threadIdx.x >> 5, lane = threadIdx.x & 31;
    __shared__ float probs[Ed];
    if (w < Ed) {
        const float* hv = h2 + (size_t)m * Hd;
        const float* wv = rw + (size_t)w * Hd;
        float s = 0.f;
        for (int j = lane; j < Hd; j += 32) s += hv[j] * wv[j];
        #pragma unroll
        for (int o = 16; o; o >>= 1) s += __shfl_xor_sync(0xffffffffu, s, o);
        if (lane == 0) probs[w] = 1.f / (1.f + expf(-(s + rb[w])));
    }
    __syncthreads();
    if (threadIdx.x == 0) {
        int e0 = 0; float p0 = probs[0];
        for (int e = 1; e < Ed; e++) if (probs[e] > p0) { p0 = probs[e]; e0 = e; }
        int e1 = -1; float p1 = -3.4e38f;
        for (int e = 0; e < Ed; e++) if (e != e0 && probs[e] > p1) { p1 = probs[e]; e1 = e; }
        int pos = atomicAdd(&g_cnt[e0], 1);
        g_gidx[e0*BTd + pos] = m; g_gwt[e0*BTd + pos] = p0; g_gslot[e0*BTd + pos] = 0;
        pos = atomicAdd(&g_cnt[e1], 1);
        g_gidx[e1*BTd + pos] = m; g_gwt[e1*BTd + pos] = p1; g_gslot[e1*BTd + pos] = 1;
    }
}

// ---------------- tf32 helpers ----------------
__device__ __forceinline__ unsigned f2tf(float f) {
    unsigned u;
    asm("cvt.rna.tf32.f32 %0, %1;" : "=r"(u) : "f"(f));
    return u;
}

__device__ __forceinline__ void mma_tf32(float* d, const unsigned* a, const unsigned* b) {
    asm volatile(
        "mma.sync.aligned.m16n8k8.row.col.f32.tf32.tf32.f32 "
        "{%0,%1,%2,%3}, {%4,%5,%6,%7}, {%8,%9}, {%0,%1,%2,%3};"
        : "+f"(d[0]), "+f"(d[1]), "+f"(d[2]), "+f"(d[3])
        : "r"(a[0]), "r"(a[1]), "r"(a[2]), "r"(a[3]), "r"(b[0]), "r"(b[1]));
}

// per-z pointer tables for batched launches
struct GA {
    const float* A[8];
    const float* B[8];
    float*       C[8];
    const float* aux[8];
    float* r0; float* r1;
    int M, N, K, lda, ldb, ldc;
    const int* gcnt; const int* gidx; const float* gwt; const int* gslot;
};

// ---------------- tensor-core GEMM, 128x256 tile, KT=16, double-buffered ----
// 8 warps, 2x4 warp grid, 64x64 per warp. Smem: 16 k-slots per row, pair-
// permuted so (k, k+4) adjacent (LDS.64 frags), XOR-swizzled by row.
// Logical k -> slot: g = k>>3, slot = g*8 + 2*(k&3) + ((k&7)>>2), then
// slot ^= (row&7)<<1.
// MODE 0: C=v  1: silu  2: C=v*aux (in-place safe)  3: C=v+aux
//      4: scatter w*v to (r0|r1)[gidx]   5: C=v/32, causal tile skip
template<int MODE, bool BTRANS, bool GATHER>
__global__ void __launch_bounds__(256) gemm2(GA ga) {
    const int z = blockIdx.z;
    const int bm = blockIdx.y * 128;
    const int bn = blockIdx.x * 256;
    if (MODE == 5 && bn > bm + 127) return;

    int Meff = ga.M;
    const int* gidx = nullptr; const float* gwt = nullptr; const int* gslot = nullptr;
    if (GATHER || MODE == 4) {
        Meff = ga.gcnt[z];
        gidx = ga.gidx + z * BTd;
        gwt  = ga.gwt  + z * BTd;
        gslot= ga.gslot+ z * BTd;
    }
    if (bm >= Meff) return;

    const float* __restrict__ A   = ga.A[z];
    const float* __restrict__ Bm  = ga.B[z];
    float* __restrict__ C         = ga.C[z];
    const float* __restrict__ aux = ga.aux[z];
    const int K = ga.K, lda = ga.lda, ldb = ga.ldb, ldc = ga.ldc;

    __shared__ unsigned As[2][2048];   // 128 rows x 16 slots
    __shared__ unsigned Bs[2][4096];   // 256 rows x 16 slots

    const int tid = threadIdx.x;
    const int lane = tid & 31, wid = tid >> 5;
    const int wm = wid & 1, wn = wid >> 1;      // 2 x 4 warps, 64x64 each
    const int gid = lane >> 2, tig = lane & 3;

    // A loader: 2 threads/row, 8 k each
    const int arow = tid >> 1;
    const int ag = tid & 1;
    const int am = bm + arow;
    const bool aval = am < Meff;
    int asrc = 0;
    if (aval) asrc = GATHER ? gidx[am] : am;
    const float* Ap = A + (size_t)asrc * lda + ag * 8;

    // B loader
    const float* Bp;
    int brow = 0, bk = 0, bn16 = 0;
    if (BTRANS) {
        brow = tid;                       // 1 thread/row, 16 k each
        Bp = Bm + (size_t)(bn + brow) * ldb;
    } else {
        bk = tid >> 4; bn16 = (tid & 15) * 16;
        Bp = Bm + (size_t)bk * ldb + bn + bn16;
    }

    float acc[4][8][4];
    #pragma unroll
    for (int i = 0; i < 4; i++)
        #pragma unroll
        for (int j = 0; j < 8; j++)
            #pragma unroll
            for (int l = 0; l < 4; l++) acc[i][j][l] = 0.f;

    const float4 Z4 = make_float4(0.f, 0.f, 0.f, 0.f);
    float ra[8], rb[16];

    auto load_t = [&](int kt_) {
        *(float4*)ra     = aval ? *(const float4*)(Ap + kt_)     : Z4;
        *(float4*)(ra+4) = aval ? *(const float4*)(Ap + kt_ + 4) : Z4;
        if (BTRANS) {
            *(float4*)rb      = *(const float4*)(Bp + kt_);
            *(float4*)(rb+4)  = *(const float4*)(Bp + kt_ + 4);
            *(float4*)(rb+8)  = *(const float4*)(Bp + kt_ + 8);
            *(float4*)(rb+12) = *(const float4*)(Bp + kt_ + 12);
        } else {
            *(float4*)rb      = *(const float4*)(Bp + (size_t)kt_ * ldb);
            *(float4*)(rb+4)  = *(const float4*)(Bp + (size_t)kt_ * ldb + 4);
            *(float4*)(rb+8)  = *(const float4*)(Bp + (size_t)kt_ * ldb + 8);
            *(float4*)(rb+12) = *(const float4*)(Bp + (size_t)kt_ * ldb + 12);
        }
    };

    auto store_t = [&](int st_) {
        #pragma unroll
        for (int j = 0; j < 4; j++) {
            uint2 u; u.x = f2tf(ra[j]); u.y = f2tf(ra[j+4]);
            int col = (ag*8 + 2*j) ^ ((arow & 7) << 1);
            *(uint2*)&As[st_][arow*16 + col] = u;
        }
        if (BTRANS) {
            // rb[j] = k offset j (0..15); groups g=0 (k0..7), g=1 (k8..15)
            #pragma unroll
            for (int g = 0; g < 2; g++)
                #pragma unroll
                for (int j = 0; j < 4; j++) {
                    uint2 u; u.x = f2tf(rb[g*8 + j]); u.y = f2tf(rb[g*8 + j + 4]);
                    int col = (g*8 + 2*j) ^ ((brow & 7) << 1);
                    *(uint2*)&Bs[st_][brow*16 + col] = u;
                }
        } else {
            const int g_ = bk >> 3, kk_ = bk & 7;
            const int cb_ = g_*8 + 2*(kk_ & 3) + (kk_ >> 2);
            #pragma unroll
            for (int j = 0; j < 16; j++) {
                int row_ = bn16 + j;
                int col = cb_ ^ ((row_ & 7) << 1);
                Bs[st_][row_*16 + col] = f2tf(rb[j]);
            }
        }
    };

    // prologue: tile0 -> stage0, tile1 -> regs
    load_t(0);
    store_t(0);
    load_t(16);

    int st = 0;
    for (int kt = 0; kt < K; kt += 16) {
        __syncthreads();
        if (kt + 16 < K) {
            store_t(st ^ 1);
            if (kt + 32 < K) load_t(kt + 32);
        }
        // compute stage st: two k8 steps
        #pragma unroll
        for (int g8 = 0; g8 < 2; g8++) {
            uint2 af0[4], af1[4], bf[8];
            const int cfrag = (g8*8 + 2*tig) ^ (gid << 1);
            #pragma unroll
            for (int mt = 0; mt < 4; mt++) {
                int r = wm*64 + mt*16 + gid;
                af0[mt] = *(const uint2*)&As[st][r*16 + cfrag];
                af1[mt] = *(const uint2*)&As[st][(r+8)*16 + cfrag];
            }
            #pragma unroll
            for (int nt = 0; nt < 8; nt++) {
                int c = wn*64 + nt*8 + gid;
                bf[nt] = *(const uint2*)&Bs[st][c*16 + cfrag];
            }
            #pragma unroll
            for (int mt = 0; mt < 4; mt++) {
                unsigned a[4] = {af0[mt].x, af1[mt].x, af0[mt].y, af1[mt].y};
                #pragma unroll
                for (int nt = 0; nt < 8; nt++) {
                    unsigned b[2] = {bf[nt].x, bf[nt].y};
                    mma_tf32(acc[mt][nt], a, b);
                }
            }
        }
        st ^= 1;
    }

    // ---- epilogue ----
    #pragma unroll
    for (int mt = 0; mt < 4; mt++) {
        #pragma unroll
        for (int i2 = 0; i2 < 2; i2++) {
            int gm = bm + wm*64 + mt*16 + gid + i2*8;
            if (gm >= Meff) continue;
            int trow = 0; float wgt = 0.f;
            if (MODE == 4) { trow = gidx[gm]; wgt = gwt[gm]; }
            float* Ct = (MODE == 4) ? (gslot[gm] ? ga.r1 : ga.r0) : C;
            #pragma unroll
            for (int nt = 0; nt < 8; nt++) {
                #pragma unroll
                for (int j2 = 0; j2 < 2; j2++) {
                    int gn = bn + wn*64 + nt*8 + tig*2 + j2;
                    float v = acc[mt][nt][i2*2 + j2];
                    size_t o = (size_t)gm * ldc + gn;
                    if (MODE == 0)      C[o] = v;
                    else if (MODE == 1) C[o] = v / (1.f + expf(-v));
                    else if (MODE == 2) C[o] = v * aux[o];
                    else if (MODE == 3) C[o] = v + aux[o];
                    else if (MODE == 4) Ct[(size_t)trow * ldc + gn] = wgt * v;
                    else if (MODE == 5) C[o] = v * 0.03125f;
                }
            }
        }
    }
}

// ---------------- final add ----------------
__global__ void final_add_kernel(const float* __restrict__ a, const float* __restrict__ b,
                                 const float* __restrict__ c, const float* __restrict__ d,
                                 float* __restrict__ out) {
    size_t i = (size_t)blockIdx.x * blockDim.x + threadIdx.x;
    out[i] = a[i] + b[i] + c[i] + d[i];
}

// ---------------- launch ----------------
extern "C" void kernel_launch(void* const* d_in, const int* in_sizes, int n_in,
                              void* d_out, int out_size) {
    (void)in_sizes; (void)n_in; (void)out_size;
    const float* x         = (const float*)d_in[0];
    const float* ln1w      = (const float*)d_in[1];
    const float* ln2w      = (const float*)d_in[2];
    const float* kv_proj_d = (const float*)d_in[3];
    const float* q_proj_d  = (const float*)d_in[4];
    const float* v_proj_u  = (const float*)d_in[7];
    const float* rope_k    = (const float*)d_in[8];
    const float* rope_q    = (const float*)d_in[9];
    const float* o_proj    = (const float*)d_in[10];
    const float* router_w  = (const float*)d_in[11];
    const float* router_b  = (const float*)d_in[12];
    const float* sh_gate   = (const float*)d_in[13];
    const float* sh_up     = (const float*)d_in[14];
    const float* sh_down   = (const float*)d_in[15];
    const float* ex_gate   = (const float*)d_in[16];
    const float* ex_up     = (const float*)d_in[17];
    const float* ex_down   = (const float*)d_in[18];
    float* out = (float*)d_out;

    float *h,*kvlat,*qlat,*v,*q,*k,*scores,*y,*x1,*h2,*gbuf,*shb,*r0,*r1,*gwt;
    int *cnt,*gidx,*gslot;
    cudaGetSymbolAddress((void**)&h, g_h);
    cudaGetSymbolAddress((void**)&kvlat, g_kvlat);
    cudaGetSymbolAddress((void**)&qlat, g_qlat);
    cudaGetSymbolAddress((void**)&v, g_v);
    cudaGetSymbolAddress((void**)&q, g_q);
    cudaGetSymbolAddress((void**)&k, g_k);
    cudaGetSymbolAddress((void**)&scores, g_scores);
    cudaGetSymbolAddress((void**)&y, g_y);
    cudaGetSymbolAddress((void**)&x1, g_x1);
    cudaGetSymbolAddress((void**)&h2, g_h2);
    cudaGetSymbolAddress((void**)&gbuf, g_gbuf);
    cudaGetSymbolAddress((void**)&shb, g_shb);
    cudaGetSymbolAddress((void**)&r0, g_r0);
    cudaGetSymbolAddress((void**)&r1, g_r1);
    cudaGetSymbolAddress((void**)&cnt, g_cnt);
    cudaGetSymbolAddress((void**)&gidx, g_gidx);
    cudaGetSymbolAddress((void**)&gwt, g_gwt);
    cudaGetSymbolAddress((void**)&gslot, g_gslot);

    const size_t ESL = (size_t)BTd * Fd;   // per-expert gbuf slice

    zero_cnt_kernel<<<1, 32>>>();
    ln_kernel<<<BTd, 256>>>(x, ln1w, h);

    // qlat + kvlat (z=2)  N=256
    {
        GA ga = {};
        ga.A[0] = h;        ga.A[1] = h;
        ga.B[0] = q_proj_d; ga.B[1] = kv_proj_d;
        ga.C[0] = qlat;     ga.C[1] = kvlat;
        ga.M = BTd; ga.N = Ld; ga.K = Hd; ga.lda = Hd; ga.ldb = Hd; ga.ldc = Ld;
        gemm2<0,true,false><<<dim3(Ld/256, BTd/128, 2), 256>>>(ga);
    }
    // v + q_r (z=2)  N=1024
    {
        GA ga = {};
        ga.A[0] = kvlat;    ga.A[1] = qlat;
        ga.B[0] = v_proj_u; ga.B[1] = rope_q;
        ga.C[0] = v;        ga.C[1] = q;
        ga.M = BTd; ga.N = Hd; ga.K = Ld; ga.lda = Ld; ga.ldb = Ld; ga.ldc = Hd;
        gemm2<0,true,false><<<dim3(Hd/256, BTd/128, 2), 256>>>(ga);
    }
    // k_r
    {
        GA ga = {};
        ga.A[0] = h; ga.B[0] = rope_k; ga.C[0] = k;
        ga.M = BTd; ga.N = Hd; ga.K = Hd; ga.lda = Hd; ga.ldb = Hd; ga.ldc = Hd;
        gemm2<0,true,false><<<dim3(Hd/256, BTd/128, 1), 256>>>(ga);
    }

    rope_kernel<<<BTd, 256>>>(q, k);

    // scores (z=2, causal)
    {
        GA ga = {};
        for (int b = 0; b < Bd; b++) {
            ga.A[b] = q + (size_t)b*Td*Hd;
            ga.B[b] = k + (size_t)b*Td*Hd;
            ga.C[b] = scores + (size_t)b*Td*Td;
        }
        ga.M = Td; ga.N = Td; ga.K = Hd; ga.lda = Hd; ga.ldb = Hd; ga.ldc = Td;
        gemm2<5,true,false><<<dim3(Td/256, Td/128, Bd), 256>>>(ga);
    }
    softmax_kernel<<<dim3(Td, Bd), 256>>>(scores);
    // PV (z=2)
    {
        GA ga = {};
        for (int b = 0; b < Bd; b++) {
            ga.A[b] = scores + (size_t)b*Td*Td;
            ga.B[b] = v + (size_t)b*Td*Hd;
            ga.C[b] = y + (size_t)b*Td*Hd;
        }
        ga.M = Td; ga.N = Hd; ga.K = Td; ga.lda = Td; ga.ldb = Hd; ga.ldc = Hd;
        gemm2<0,false,false><<<dim3(Hd/256, Td/128, Bd), 256>>>(ga);
    }
    // x1 = x + y @ o_proj.T
    {
        GA ga = {};
        ga.A[0] = y; ga.B[0] = o_proj; ga.C[0] = x1; ga.aux[0] = x;
        ga.M = BTd; ga.N = Hd; ga.K = Hd; ga.lda = Hd; ga.ldb = Hd; ga.ldc = Hd;
        gemm2<3,true,false><<<dim3(Hd/256, BTd/128, 1), 256>>>(ga);
    }

    // ---- MoE ----
    ln_kernel<<<BTd, 256>>>(x1, ln2w, h2);
    router_kernel<<<BTd, 256>>>(h2, router_w, router_b);

    float* shg = gbuf + (size_t)7 * ESL;   // shared-expert slice
    // shared gate (silu)
    {
        GA ga = {};
        ga.A[0] = h2; ga.B[0] = sh_gate; ga.C[0] = shg;
        ga.M = BTd; ga.N = Fd; ga.K = Hd; ga.lda = Hd; ga.ldb = Hd; ga.ldc = Fd;
        gemm2<1,true,false><<<dim3(Fd/256, BTd/128, 1), 256>>>(ga);
    }
    // shared up (in-place multiply into shg)
    {
        GA ga = {};
        ga.A[0] = h2; ga.B[0] = sh_up; ga.C[0] = shg; ga.aux[0] = shg;
        ga.M = BTd; ga.N = Fd; ga.K = Hd; ga.lda = Hd; ga.ldb = Hd; ga.ldc = Fd;
        gemm2<2,true,false><<<dim3(Fd/256, BTd/128, 1), 256>>>(ga);
    }
    // shared down
    {
        GA ga = {};
        ga.A[0] = shg; ga.B[0] = sh_down; ga.C[0] = shb;
        ga.M = BTd; ga.N = Hd; ga.K = Fd; ga.lda = Fd; ga.ldb = Fd; ga.ldc = Hd;
        gemm2<0,true,false><<<dim3(Hd/256, BTd/128, 1), 256>>>(ga);
    }

    // routed experts, all 7 batched per stage
    {
        GA ga = {};
        for (int e = 0; e < Ed; e++) {
            ga.A[e] = h2;
            ga.B[e] = ex_gate + (size_t)e * Fd * Hd;
            ga.C[e] = gbuf + (size_t)e * ESL;
        }
        ga.M = BTd; ga.N = Fd; ga.K = Hd; ga.lda = Hd; ga.ldb = Hd; ga.ldc = Fd;
        ga.gcnt = cnt; ga.gidx = gidx; ga.gwt = gwt; ga.gslot = gslot;
        gemm2<1,true,true><<<dim3(Fd/256, BTd/128, Ed), 256>>>(ga);
    }
    {
        GA ga = {};
        for (int e = 0; e < Ed; e++) {
            ga.A[e] = h2;
            ga.B[e] = ex_up + (size_t)e * Fd * Hd;
            ga.C[e] = gbuf + (size_t)e * ESL;
            ga.aux[e] = gbuf + (size_t)e * ESL;
        }
        ga.M = BTd; ga.N = Fd; ga.K = Hd; ga.lda = Hd; ga.ldb = Hd; ga.ldc = Fd;
        ga.gcnt = cnt; ga.gidx = gidx; ga.gwt = gwt; ga.gslot = gslot;
        gemm2<2,true,true><<<dim3(Fd/256, BTd/128, Ed), 256>>>(ga);
    }
    {
        GA ga = {};
        for (int e = 0; e < Ed; e++) {
            ga.A[e] = gbuf + (size_t)e * ESL;
            ga.B[e] = ex_down + (size_t)e * Hd * Fd;
        }
        ga.r0 = r0; ga.r1 = r1;
        ga.M = BTd; ga.N = Hd; ga.K = Fd; ga.lda = Fd; ga.ldb = Fd; ga.ldc = Hd;
        ga.gcnt = cnt; ga.gidx = gidx; ga.gwt = gwt; ga.gslot = gslot;
        gemm2<4,true,false><<<dim3(Hd/256, BTd/128, Ed), 256>>>(ga);
    }

    final_add_kernel<<<(BTd * Hd) / 256, 256>>>(x1, shb, r0, r1, out);
}

// round 7
// speedup vs baseline: 1.0010x; 1.0010x over previous
#include <cuda_runtime.h>
#include <math.h>

#define Bd 2
#define Td 2048
#define Hd 1024
#define Ld 256
#define Fd 2048
#define Ed 7
#define BTd (Bd*Td)

// ---------------- scratch (device globals; no allocation) ----------------
__device__ float g_h[BTd*Hd];
__device__ float g_kvlat[BTd*Ld];
__device__ float g_qlat[BTd*Ld];
__device__ float g_v[BTd*Hd];
__device__ float g_q[BTd*Hd];
__device__ float g_k[BTd*Hd];
__device__ float g_scores[(size_t)Bd*Td*Td];
__device__ float g_y[BTd*Hd];
__device__ float g_x1[BTd*Hd];
__device__ float g_h2[BTd*Hd];
__device__ float g_gbuf[(size_t)8*BTd*Fd];   // per-expert slices (7 routed + 1 shared)
__device__ float g_shb[BTd*Hd];
__device__ float g_r0[BTd*Hd];
__device__ float g_r1[BTd*Hd];
__device__ int   g_cnt[Ed];
__device__ int   g_gidx[Ed*BTd];
__device__ float g_gwt[Ed*BTd];
__device__ int   g_gslot[Ed*BTd];

// ---------------- block reduce ----------------
template<bool DOMAX>
__device__ __forceinline__ float blockReduce(float v) {
    __shared__ float sh[8];
    __shared__ float res;
    int lane = threadIdx.x & 31, w = threadIdx.x >> 5;
    #pragma unroll
    for (int o = 16; o; o >>= 1) {
        float t = __shfl_xor_sync(0xffffffffu, v, o);
        v = DOMAX ? fmaxf(v, t) : v + t;
    }
    if (lane == 0) sh[w] = v;
    __syncthreads();
    if (w == 0) {
        v = (lane < (int)(blockDim.x >> 5)) ? sh[lane] : (DOMAX ? -3.4e38f : 0.f);
        #pragma unroll
        for (int o = 4; o; o >>= 1) {
            float t = __shfl_xor_sync(0xffffffffu, v, o);
            v = DOMAX ? fmaxf(v, t) : v + t;
        }
        if (lane == 0) res = v;
    }
    __syncthreads();
    return res;
}

// ---------------- layernorm ----------------
__global__ void ln_kernel(const float* __restrict__ x, const float* __restrict__ w,
                          float* __restrict__ out) {
    int row = blockIdx.x;
    const float* xr = x + (size_t)row * Hd;
    int t = threadIdx.x;
    float v[4];
    float s = 0.f;
    #pragma unroll
    for (int i = 0; i < 4; i++) { v[i] = xr[t + 256*i]; s += v[i]; }
    s = blockReduce<false>(s);
    float mu = s * (1.f / Hd);
    float q = 0.f;
    #pragma unroll
    for (int i = 0; i < 4; i++) { float d = v[i] - mu; q += d * d; }
    q = blockReduce<false>(q);
    float rs = rsqrtf(q * (1.f / Hd) + 1e-5f);
    float* o = out + (size_t)row * Hd;
    #pragma unroll
    for (int i = 0; i < 4; i++) o[t + 256*i] = (v[i] - mu) * rs * w[t + 256*i];
}

// ---------------- rope ----------------
__global__ void rope_kernel(float* __restrict__ q, float* __restrict__ k) {
    int row = blockIdx.x;
    int t = row % Td;
    size_t base = (size_t)row * Hd;
    #pragma unroll
    for (int it = 0; it < 2; it++) {
        int p = threadIdx.x + 256 * it;
        double invf = exp(-(double)(2 * p) / 1024.0 * 9.210340371976184);
        float f = (float)t * (float)invf;
        float c = cosf(f), s = sinf(f);
        float q1 = q[base + p], q2 = q[base + p + 512];
        q[base + p]       = q1 * c - q2 * s;
        q[base + p + 512] = q2 * c + q1 * s;
        float k1 = k[base + p], k2 = k[base + p + 512];
        k[base + p]       = k1 * c - k2 * s;
        k[base + p + 512] = k2 * c + k1 * s;
    }
}

// ---------------- softmax (causal) ----------------
__global__ void softmax_kernel(float* __restrict__ sc) {
    int b = blockIdx.y, i = blockIdx.x;
    float* row = sc + ((size_t)b * Td + i) * Td;
    int t = threadIdx.x;
    int n = i + 1;
    float mx = -3.4e38f;
    for (int j = t; j < n; j += 256) mx = fmaxf(mx, row[j]);
    mx = blockReduce<true>(mx);
    float s = 0.f;
    for (int j = t; j < n; j += 256) s += expf(row[j] - mx);
    s = blockReduce<false>(s);
    float inv = 1.f / s;
    for (int j = t; j < Td; j += 256)
        row[j] = (j < n) ? expf(row[j] - mx) * inv : 0.f;
}

// ---------------- router + top2 gather lists ----------------
__global__ void zero_cnt_kernel() {
    if (threadIdx.x < Ed) g_cnt[threadIdx.x] = 0;
}

__global__ void router_kernel(const float* __restrict__ h2, const float* __restrict__ rw,
                              const float* __restrict__ rb) {
    int m = blockIdx.x;
    int w = threadIdx.x >> 5, lane = threadIdx.x & 31;
    __shared__ float probs[Ed];
    if (w < Ed) {
        const float* hv = h2 + (size_t)m * Hd;
        const float* wv = rw + (size_t)w * Hd;
        float s = 0.f;
        for (int j = lane; j < Hd; j += 32) s += hv[j] * wv[j];
        #pragma unroll
        for (int o = 16; o; o >>= 1) s += __shfl_xor_sync(0xffffffffu, s, o);
        if (lane == 0) probs[w] = 1.f / (1.f + expf(-(s + rb[w])));
    }
    __syncthreads();
    if (threadIdx.x == 0) {
        int e0 = 0; float p0 = probs[0];
        for (int e = 1; e < Ed; e++) if (probs[e] > p0) { p0 = probs[e]; e0 = e; }
        int e1 = -1; float p1 = -3.4e38f;
        for (int e = 0; e < Ed; e++) if (e != e0 && probs[e] > p1) { p1 = probs[e]; e1 = e; }
        int pos = atomicAdd(&g_cnt[e0], 1);
        g_gidx[e0*BTd + pos] = m; g_gwt[e0*BTd + pos] = p0; g_gslot[e0*BTd + pos] = 0;
        pos = atomicAdd(&g_cnt[e1], 1);
        g_gidx[e1*BTd + pos] = m; g_gwt[e1*BTd + pos] = p1; g_gslot[e1*BTd + pos] = 1;
    }
}

// ---------------- tf32 helpers ----------------
__device__ __forceinline__ unsigned f2tf(float f) {
    unsigned u;
    asm("cvt.rna.tf32.f32 %0, %1;" : "=r"(u) : "f"(f));
    return u;
}

__device__ __forceinline__ void mma_tf32(float* d, const unsigned* a, const unsigned* b) {
    asm volatile(
        "mma.sync.aligned.m16n8k8.row.col.f32.tf32.tf32.f32 "
        "{%0,%1,%2,%3}, {%4,%5,%6,%7}, {%8,%9}, {%0,%1,%2,%3};"
        : "+f"(d[0]), "+f"(d[1]), "+f"(d[2]), "+f"(d[3])
        : "r"(a[0]), "r"(a[1]), "r"(a[2]), "r"(a[3]), "r"(b[0]), "r"(b[1]));
}

// per-z pointer tables for batched launches
struct GA {
    const float* A[8];
    const float* B[8];
    float*       C[8];
    const float* aux[8];
    float* r0; float* r1;
    int M, N, K, lda, ldb, ldc;
    const int* gcnt; const int* gidx; const float* gwt; const int* gslot;
};

// ---------------- tensor-core GEMM, 128x256 tile, KT=16, double-buffered ----
// 8 warps, 2x4 warp grid, 64x64 per warp. Smem: 16 k-slots per row, pair-
// permuted so (k, k+4) adjacent (LDS.64 frags), XOR-swizzled by row.
// Logical k -> slot: g = k>>3, slot = g*8 + 2*(k&3) + ((k&7)>>2), then
// slot ^= (row&7)<<1.
// MODE 0: C=v  1: silu  2: C=v*aux (in-place safe)  3: C=v+aux
//      4: scatter w*v to (r0|r1)[gidx]   5: C=v/32, causal tile skip
template<int MODE, bool BTRANS, bool GATHER>
__global__ void __launch_bounds__(256) gemm2(GA ga) {
    const int z = blockIdx.z;
    const int bm = blockIdx.y * 128;
    const int bn = blockIdx.x * 256;
    if (MODE == 5 && bn > bm + 127) return;

    int Meff = ga.M;
    const int* gidx = nullptr; const float* gwt = nullptr; const int* gslot = nullptr;
    if (GATHER || MODE == 4) {
        Meff = ga.gcnt[z];
        gidx = ga.gidx + z * BTd;
        gwt  = ga.gwt  + z * BTd;
        gslot= ga.gslot+ z * BTd;
    }
    if (bm >= Meff) return;

    const float* __restrict__ A   = ga.A[z];
    const float* __restrict__ Bm  = ga.B[z];
    float* __restrict__ C         = ga.C[z];
    const float* __restrict__ aux = ga.aux[z];
    const int K = ga.K, lda = ga.lda, ldb = ga.ldb, ldc = ga.ldc;

    __shared__ unsigned As[2][2048];   // 128 rows x 16 slots
    __shared__ unsigned Bs[2][4096];   // 256 rows x 16 slots

    const int tid = threadIdx.x;
    const int lane = tid & 31, wid = tid >> 5;
    const int wm = wid & 1, wn = wid >> 1;      // 2 x 4 warps, 64x64 each
    const int gid = lane >> 2, tig = lane & 3;

    // A loader: 2 threads/row, 8 k each
    const int arow = tid >> 1;
    const int ag = tid & 1;
    const int am = bm + arow;
    const bool aval = am < Meff;
    int asrc = 0;
    if (aval) asrc = GATHER ? gidx[am] : am;
    const float* Ap = A + (size_t)asrc * lda + ag * 8;

    // B loader
    const float* Bp;
    int brow = 0, bk = 0, bn16 = 0;
    if (BTRANS) {
        brow = tid;                       // 1 thread/row, 16 k each
        Bp = Bm + (size_t)(bn + brow) * ldb;
    } else {
        bk = tid >> 4; bn16 = (tid & 15) * 16;
        Bp = Bm + (size_t)bk * ldb + bn + bn16;
    }

    float acc[4][8][4];
    #pragma unroll
    for (int i = 0; i < 4; i++)
        #pragma unroll
        for (int j = 0; j < 8; j++)
            #pragma unroll
            for (int l = 0; l < 4; l++) acc[i][j][l] = 0.f;

    const float4 Z4 = make_float4(0.f, 0.f, 0.f, 0.f);
    float ra[8], rb[16];

    auto load_t = [&](int kt_) {
        *(float4*)ra     = aval ? *(const float4*)(Ap + kt_)     : Z4;
        *(float4*)(ra+4) = aval ? *(const float4*)(Ap + kt_ + 4) : Z4;
        if (BTRANS) {
            *(float4*)rb      = *(const float4*)(Bp + kt_);
            *(float4*)(rb+4)  = *(const float4*)(Bp + kt_ + 4);
            *(float4*)(rb+8)  = *(const float4*)(Bp + kt_ + 8);
            *(float4*)(rb+12) = *(const float4*)(Bp + kt_ + 12);
        } else {
            *(float4*)rb      = *(const float4*)(Bp + (size_t)kt_ * ldb);
            *(float4*)(rb+4)  = *(const float4*)(Bp + (size_t)kt_ * ldb + 4);
            *(float4*)(rb+8)  = *(const float4*)(Bp + (size_t)kt_ * ldb + 8);
            *(float4*)(rb+12) = *(const float4*)(Bp + (size_t)kt_ * ldb + 12);
        }
    };

    auto store_t = [&](int st_) {
        #pragma unroll
        for (int j = 0; j < 4; j++) {
            uint2 u; u.x = f2tf(ra[j]); u.y = f2tf(ra[j+4]);
            int col = (ag*8 + 2*j) ^ ((arow & 7) << 1);
            *(uint2*)&As[st_][arow*16 + col] = u;
        }
        if (BTRANS) {
            // rb[j] = k offset j (0..15); groups g=0 (k0..7), g=1 (k8..15)
            #pragma unroll
            for (int g = 0; g < 2; g++)
                #pragma unroll
                for (int j = 0; j < 4; j++) {
                    uint2 u; u.x = f2tf(rb[g*8 + j]); u.y = f2tf(rb[g*8 + j + 4]);
                    int col = (g*8 + 2*j) ^ ((brow & 7) << 1);
                    *(uint2*)&Bs[st_][brow*16 + col] = u;
                }
        } else {
            const int g_ = bk >> 3, kk_ = bk & 7;
            const int cb_ = g_*8 + 2*(kk_ & 3) + (kk_ >> 2);
            #pragma unroll
            for (int j = 0; j < 16; j++) {
                int row_ = bn16 + j;
                int col = cb_ ^ ((row_ & 7) << 1);
                Bs[st_][row_*16 + col] = f2tf(rb[j]);
            }
        }
    };

    // prologue: tile0 -> stage0, tile1 -> regs
    load_t(0);
    store_t(0);
    load_t(16);

    int st = 0;
    for (int kt = 0; kt < K; kt += 16) {
        __syncthreads();
        if (kt + 16 < K) {
            store_t(st ^ 1);
            if (kt + 32 < K) load_t(kt + 32);
        }
        // compute stage st: two k8 steps
        #pragma unroll
        for (int g8 = 0; g8 < 2; g8++) {
            uint2 af0[4], af1[4], bf[8];
            const int cfrag = (g8*8 + 2*tig) ^ (gid << 1);
            #pragma unroll
            for (int mt = 0; mt < 4; mt++) {
                int r = wm*64 + mt*16 + gid;
                af0[mt] = *(const uint2*)&As[st][r*16 + cfrag];
                af1[mt] = *(const uint2*)&As[st][(r+8)*16 + cfrag];
            }
            #pragma unroll
            for (int nt = 0; nt < 8; nt++) {
                int c = wn*64 + nt*8 + gid;
                bf[nt] = *(const uint2*)&Bs[st][c*16 + cfrag];
            }
            #pragma unroll
            for (int mt = 0; mt < 4; mt++) {
                unsigned a[4] = {af0[mt].x, af1[mt].x, af0[mt].y, af1[mt].y};
                #pragma unroll
                for (int nt = 0; nt < 8; nt++) {
                    unsigned b[2] = {bf[nt].x, bf[nt].y};
                    mma_tf32(acc[mt][nt], a, b);
                }
            }
        }
        st ^= 1;
    }

    // ---- epilogue ----
    #pragma unroll
    for (int mt = 0; mt < 4; mt++) {
        #pragma unroll
        for (int i2 = 0; i2 < 2; i2++) {
            int gm = bm + wm*64 + mt*16 + gid + i2*8;
            if (gm >= Meff) continue;
            int trow = 0; float wgt = 0.f;
            if (MODE == 4) { trow = gidx[gm]; wgt = gwt[gm]; }
            float* Ct = (MODE == 4) ? (gslot[gm] ? ga.r1 : ga.r0) : C;
            #pragma unroll
            for (int nt = 0; nt < 8; nt++) {
                #pragma unroll
                for (int j2 = 0; j2 < 2; j2++) {
                    int gn = bn + wn*64 + nt*8 + tig*2 + j2;
                    float v = acc[mt][nt][i2*2 + j2];
                    size_t o = (size_t)gm * ldc + gn;
                    if (MODE == 0)      C[o] = v;
                    else if (MODE == 1) C[o] = v / (1.f + expf(-v));
                    else if (MODE == 2) C[o] = v * aux[o];
                    else if (MODE == 3) C[o] = v + aux[o];
                    else if (MODE == 4) Ct[(size_t)trow * ldc + gn] = wgt * v;
                    else if (MODE == 5) C[o] = v * 0.03125f;
                }
            }
        }
    }
}

// ---------------- final add ----------------
__global__ void final_add_kernel(const float* __restrict__ a, const float* __restrict__ b,
                                 const float* __restrict__ c, const float* __restrict__ d,
                                 float* __restrict__ out) {
    size_t i = (size_t)blockIdx.x * blockDim.x + threadIdx.x;
    out[i] = a[i] + b[i] + c[i] + d[i];
}

// ---------------- launch ----------------
extern "C" void kernel_launch(void* const* d_in, const int* in_sizes, int n_in,
                              void* d_out, int out_size) {
    (void)in_sizes; (void)n_in; (void)out_size;
    const float* x         = (const float*)d_in[0];
    const float* ln1w      = (const float*)d_in[1];
    const float* ln2w      = (const float*)d_in[2];
    const float* kv_proj_d = (const float*)d_in[3];
    const float* q_proj_d  = (const float*)d_in[4];
    const float* v_proj_u  = (const float*)d_in[7];
    const float* rope_k    = (const float*)d_in[8];
    const float* rope_q    = (const float*)d_in[9];
    const float* o_proj    = (const float*)d_in[10];
    const float* router_w  = (const float*)d_in[11];
    const float* router_b  = (const float*)d_in[12];
    const float* sh_gate   = (const float*)d_in[13];
    const float* sh_up     = (const float*)d_in[14];
    const float* sh_down   = (const float*)d_in[15];
    const float* ex_gate   = (const float*)d_in[16];
    const float* ex_up     = (const float*)d_in[17];
    const float* ex_down   = (const float*)d_in[18];
    float* out = (float*)d_out;

    float *h,*kvlat,*qlat,*v,*q,*k,*scores,*y,*x1,*h2,*gbuf,*shb,*r0,*r1,*gwt;
    int *cnt,*gidx,*gslot;
    cudaGetSymbolAddress((void**)&h, g_h);
    cudaGetSymbolAddress((void**)&kvlat, g_kvlat);
    cudaGetSymbolAddress((void**)&qlat, g_qlat);
    cudaGetSymbolAddress((void**)&v, g_v);
    cudaGetSymbolAddress((void**)&q, g_q);
    cudaGetSymbolAddress((void**)&k, g_k);
    cudaGetSymbolAddress((void**)&scores, g_scores);
    cudaGetSymbolAddress((void**)&y, g_y);
    cudaGetSymbolAddress((void**)&x1, g_x1);
    cudaGetSymbolAddress((void**)&h2, g_h2);
    cudaGetSymbolAddress((void**)&gbuf, g_gbuf);
    cudaGetSymbolAddress((void**)&shb, g_shb);
    cudaGetSymbolAddress((void**)&r0, g_r0);
    cudaGetSymbolAddress((void**)&r1, g_r1);
    cudaGetSymbolAddress((void**)&cnt, g_cnt);
    cudaGetSymbolAddress((void**)&gidx, g_gidx);
    cudaGetSymbolAddress((void**)&gwt, g_gwt);
    cudaGetSymbolAddress((void**)&gslot, g_gslot);

    const size_t ESL = (size_t)BTd * Fd;   // per-expert gbuf slice

    zero_cnt_kernel<<<1, 32>>>();
    ln_kernel<<<BTd, 256>>>(x, ln1w, h);

    // qlat + kvlat (z=2)  N=256
    {
        GA ga = {};
        ga.A[0] = h;        ga.A[1] = h;
        ga.B[0] = q_proj_d; ga.B[1] = kv_proj_d;
        ga.C[0] = qlat;     ga.C[1] = kvlat;
        ga.M = BTd; ga.N = Ld; ga.K = Hd; ga.lda = Hd; ga.ldb = Hd; ga.ldc = Ld;
        gemm2<0,true,false><<<dim3(Ld/256, BTd/128, 2), 256>>>(ga);
    }
    // v + q_r (z=2)  N=1024
    {
        GA ga = {};
        ga.A[0] = kvlat;    ga.A[1] = qlat;
        ga.B[0] = v_proj_u; ga.B[1] = rope_q;
        ga.C[0] = v;        ga.C[1] = q;
        ga.M = BTd; ga.N = Hd; ga.K = Ld; ga.lda = Ld; ga.ldb = Ld; ga.ldc = Hd;
        gemm2<0,true,false><<<dim3(Hd/256, BTd/128, 2), 256>>>(ga);
    }
    // k_r
    {
        GA ga = {};
        ga.A[0] = h; ga.B[0] = rope_k; ga.C[0] = k;
        ga.M = BTd; ga.N = Hd; ga.K = Hd; ga.lda = Hd; ga.ldb = Hd; ga.ldc = Hd;
        gemm2<0,true,false><<<dim3(Hd/256, BTd/128, 1), 256>>>(ga);
    }

    rope_kernel<<<BTd, 256>>>(q, k);

    // scores (z=2, causal)
    {
        GA ga = {};
        for (int b = 0; b < Bd; b++) {
            ga.A[b] = q + (size_t)b*Td*Hd;
            ga.B[b] = k + (size_t)b*Td*Hd;
            ga.C[b] = scores + (size_t)b*Td*Td;
        }
        ga.M = Td; ga.N = Td; ga.K = Hd; ga.lda = Hd; ga.ldb = Hd; ga.ldc = Td;
        gemm2<5,true,false><<<dim3(Td/256, Td/128, Bd), 256>>>(ga);
    }
    softmax_kernel<<<dim3(Td, Bd), 256>>>(scores);
    // PV (z=2)
    {
        GA ga = {};
        for (int b = 0; b < Bd; b++) {
            ga.A[b] = scores + (size_t)b*Td*Td;
            ga.B[b] = v + (size_t)b*Td*Hd;
            ga.C[b] = y + (size_t)b*Td*Hd;
        }
        ga.M = Td; ga.N = Hd; ga.K = Td; ga.lda = Td; ga.ldb = Hd; ga.ldc = Hd;
        gemm2<0,false,false><<<dim3(Hd/256, Td/128, Bd), 256>>>(ga);
    }
    // x1 = x + y @ o_proj.T
    {
        GA ga = {};
        ga.A[0] = y; ga.B[0] = o_proj; ga.C[0] = x1; ga.aux[0] = x;
        ga.M = BTd; ga.N = Hd; ga.K = Hd; ga.lda = Hd; ga.ldb = Hd; ga.ldc = Hd;
        gemm2<3,true,false><<<dim3(Hd/256, BTd/128, 1), 256>>>(ga);
    }

    // ---- MoE ----
    ln_kernel<<<BTd, 256>>>(x1, ln2w, h2);
    router_kernel<<<BTd, 256>>>(h2, router_w, router_b);

    float* shg = gbuf + (size_t)7 * ESL;   // shared-expert slice
    // shared gate (silu)
    {
        GA ga = {};
        ga.A[0] = h2; ga.B[0] = sh_gate; ga.C[0] = shg;
        ga.M = BTd; ga.N = Fd; ga.K = Hd; ga.lda = Hd; ga.ldb = Hd; ga.ldc = Fd;
        gemm2<1,true,false><<<dim3(Fd/256, BTd/128, 1), 256>>>(ga);
    }
    // shared up (in-place multiply into shg)
    {
        GA ga = {};
        ga.A[0] = h2; ga.B[0] = sh_up; ga.C[0] = shg; ga.aux[0] = shg;
        ga.M = BTd; ga.N = Fd; ga.K = Hd; ga.lda = Hd; ga.ldb = Hd; ga.ldc = Fd;
        gemm2<2,true,false><<<dim3(Fd/256, BTd/128, 1), 256>>>(ga);
    }
    // shared down
    {
        GA ga = {};
        ga.A[0] = shg; ga.B[0] = sh_down; ga.C[0] = shb;
        ga.M = BTd; ga.N = Hd; ga.K = Fd; ga.lda = Fd; ga.ldb = Fd; ga.ldc = Hd;
        gemm2<0,true,false><<<dim3(Hd/256, BTd/128, 1), 256>>>(ga);
    }

    // routed experts, all 7 batched per stage
    {
        GA ga = {};
        for (int e = 0; e < Ed; e++) {
            ga.A[e] = h2;
            ga.B[e] = ex_gate + (size_t)e * Fd * Hd;
            ga.C[e] = gbuf + (size_t)e * ESL;
        }
        ga.M = BTd; ga.N = Fd; ga.K = Hd; ga.lda = Hd; ga.ldb = Hd; ga.ldc = Fd;
        ga.gcnt = cnt; ga.gidx = gidx; ga.gwt = gwt; ga.gslot = gslot;
        gemm2<1,true,true><<<dim3(Fd/256, BTd/128, Ed), 256>>>(ga);
    }
    {
        GA ga = {};
        for (int e = 0; e < Ed; e++) {
            ga.A[e] = h2;
            ga.B[e] = ex_up + (size_t)e * Fd * Hd;
            ga.C[e] = gbuf + (size_t)e * ESL;
            ga.aux[e] = gbuf + (size_t)e * ESL;
        }
        ga.M = BTd; ga.N = Fd; ga.K = Hd; ga.lda = Hd; ga.ldb = Hd; ga.ldc = Fd;
        ga.gcnt = cnt; ga.gidx = gidx; ga.gwt = gwt; ga.gslot = gslot;
        gemm2<2,true,true><<<dim3(Fd/256, BTd/128, Ed), 256>>>(ga);
    }
    {
        GA ga = {};
        for (int e = 0; e < Ed; e++) {
            ga.A[e] = gbuf + (size_t)e * ESL;
            ga.B[e] = ex_down + (size_t)e * Hd * Fd;
        }
        ga.r0 = r0; ga.r1 = r1;
        ga.M = BTd; ga.N = Hd; ga.K = Fd; ga.lda = Fd; ga.ldb = Fd; ga.ldc = Hd;
        ga.gcnt = cnt; ga.gidx = gidx; ga.gwt = gwt; ga.gslot = gslot;
        gemm2<4,true,false><<<dim3(Hd/256, BTd/128, Ed), 256>>>(ga);
    }

    final_add_kernel<<<(BTd * Hd) / 256, 256>>>(x1, shb, r0, r1, out);
}

// round 8
// speedup vs baseline: 1.7976x; 1.7957x over previous
#include <cuda_runtime.h>
#include <cuda_fp16.h>
#include <math.h>

#define Bd 2
#define Td 2048
#define Hd 1024
#define Ld 256
#define Fd 2048
#define Ed 7
#define BTd (Bd*Td)

// ---------------- scratch (device globals; no allocation) ----------------
__device__ float g_h[BTd*Hd];
__device__ float g_kvlat[BTd*Ld];
__device__ float g_qlat[BTd*Ld];
__device__ float g_v[BTd*Hd];        // holds vT: [Bd][Hd][Td]
__device__ float g_q[BTd*Hd];
__device__ float g_k[BTd*Hd];
__device__ float g_scores[(size_t)Bd*Td*Td];
__device__ float g_y[BTd*Hd];
__device__ float g_x1[BTd*Hd];
__device__ float g_h2[BTd*Hd];
__device__ float g_gbuf[(size_t)8*BTd*Fd];   // per-expert slices (7 routed + 1 shared)
__device__ float g_shb[BTd*Hd];
__device__ float g_r0[BTd*Hd];
__device__ float g_r1[BTd*Hd];
__device__ int   g_cnt[Ed];
__device__ int   g_gidx[Ed*BTd];
__device__ float g_gwt[Ed*BTd];
__device__ int   g_gslot[Ed*BTd];

// ---------------- block reduce ----------------
template<bool DOMAX>
__device__ __forceinline__ float blockReduce(float v) {
    __shared__ float sh[8];
    __shared__ float res;
    int lane = threadIdx.x & 31, w = threadIdx.x >> 5;
    #pragma unroll
    for (int o = 16; o; o >>= 1) {
        float t = __shfl_xor_sync(0xffffffffu, v, o);
        v = DOMAX ? fmaxf(v, t) : v + t;
    }
    if (lane == 0) sh[w] = v;
    __syncthreads();
    if (w == 0) {
        v = (lane < (int)(blockDim.x >> 5)) ? sh[lane] : (DOMAX ? -3.4e38f : 0.f);
        #pragma unroll
        for (int o = 4; o; o >>= 1) {
            float t = __shfl_xor_sync(0xffffffffu, v, o);
            v = DOMAX ? fmaxf(v, t) : v + t;
        }
        if (lane == 0) res = v;
    }
    __syncthreads();
    return res;
}

// ---------------- layernorm ----------------
__global__ void ln_kernel(const float* __restrict__ x, const float* __restrict__ w,
                          float* __restrict__ out) {
    int row = blockIdx.x;
    const float* xr = x + (size_t)row * Hd;
    int t = threadIdx.x;
    float v[4];
    float s = 0.f;
    #pragma unroll
    for (int i = 0; i < 4; i++) { v[i] = xr[t + 256*i]; s += v[i]; }
    s = blockReduce<false>(s);
    float mu = s * (1.f / Hd);
    float q = 0.f;
    #pragma unroll
    for (int i = 0; i < 4; i++) { float d = v[i] - mu; q += d * d; }
    q = blockReduce<false>(q);
    float rs = rsqrtf(q * (1.f / Hd) + 1e-5f);
    float* o = out + (size_t)row * Hd;
    #pragma unroll
    for (int i = 0; i < 4; i++) o[t + 256*i] = (v[i] - mu) * rs * w[t + 256*i];
}

// ---------------- rope ----------------
__global__ void rope_kernel(float* __restrict__ q, float* __restrict__ k) {
    int row = blockIdx.x;
    int t = row % Td;
    size_t base = (size_t)row * Hd;
    #pragma unroll
    for (int it = 0; it < 2; it++) {
        int p = threadIdx.x + 256 * it;
        double invf = exp(-(double)(2 * p) / 1024.0 * 9.210340371976184);
        float f = (float)t * (float)invf;
        float c = cosf(f), s = sinf(f);
        float q1 = q[base + p], q2 = q[base + p + 512];
        q[base + p]       = q1 * c - q2 * s;
        q[base + p + 512] = q2 * c + q1 * s;
        float k1 = k[base + p], k2 = k[base + p + 512];
        k[base + p]       = k1 * c - k2 * s;
        k[base + p + 512] = k2 * c + k1 * s;
    }
}

// ---------------- softmax (causal) ----------------
__global__ void softmax_kernel(float* __restrict__ sc) {
    int b = blockIdx.y, i = blockIdx.x;
    float* row = sc + ((size_t)b * Td + i) * Td;
    int t = threadIdx.x;
    int n = i + 1;
    float mx = -3.4e38f;
    for (int j = t; j < n; j += 256) mx = fmaxf(mx, row[j]);
    mx = blockReduce<true>(mx);
    float s = 0.f;
    for (int j = t; j < n; j += 256) s += expf(row[j] - mx);
    s = blockReduce<false>(s);
    float inv = 1.f / s;
    for (int j = t; j < Td; j += 256)
        row[j] = (j < n) ? expf(row[j] - mx) * inv : 0.f;
}

// ---------------- router + top2 gather lists ----------------
__global__ void zero_cnt_kernel() {
    if (threadIdx.x < Ed) g_cnt[threadIdx.x] = 0;
}

__global__ void router_kernel(const float* __restrict__ h2, const float* __restrict__ rw,
                              const float* __restrict__ rb) {
    int m = blockIdx.x;
    int w = threadIdx.x >> 5, lane = threadIdx.x & 31;
    __shared__ float probs[Ed];
    if (w < Ed) {
        const float* hv = h2 + (size_t)m * Hd;
        const float* wv = rw + (size_t)w * Hd;
        float s = 0.f;
        for (int j = lane; j < Hd; j += 32) s += hv[j] * wv[j];
        #pragma unroll
        for (int o = 16; o; o >>= 1) s += __shfl_xor_sync(0xffffffffu, s, o);
        if (lane == 0) probs[w] = 1.f / (1.f + expf(-(s + rb[w])));
    }
    __syncthreads();
    if (threadIdx.x == 0) {
        int e0 = 0; float p0 = probs[0];
        for (int e = 1; e < Ed; e++) if (probs[e] > p0) { p0 = probs[e]; e0 = e; }
        int e1 = -1; float p1 = -3.4e38f;
        for (int e = 0; e < Ed; e++) if (e != e0 && probs[e] > p1) { p1 = probs[e]; e1 = e; }
        int pos = atomicAdd(&g_cnt[e0], 1);
        g_gidx[e0*BTd + pos] = m; g_gwt[e0*BTd + pos] = p0; g_gslot[e0*BTd + pos] = 0;
        pos = atomicAdd(&g_cnt[e1], 1);
        g_gidx[e1*BTd + pos] = m; g_gwt[e1*BTd + pos] = p1; g_gslot[e1*BTd + pos] = 1;
    }
}

// ---------------- fp16 helpers ----------------
__device__ __forceinline__ unsigned f2h2(float lo, float hi) {
    __half2 h = __floats2half2_rn(lo, hi);   // lo -> low 16 bits
    return *(unsigned*)&h;
}

__device__ __forceinline__ void mma_f16(float* d, const unsigned* a, const unsigned* b) {
    asm volatile(
        "mma.sync.aligned.m16n8k16.row.col.f32.f16.f16.f32 "
        "{%0,%1,%2,%3}, {%4,%5,%6,%7}, {%8,%9}, {%0,%1,%2,%3};"
        : "+f"(d[0]), "+f"(d[1]), "+f"(d[2]), "+f"(d[3])
        : "r"(a[0]), "r"(a[1]), "r"(a[2]), "r"(a[3]), "r"(b[0]), "r"(b[1]));
}

// per-z pointer tables for batched launches
struct GA {
    const float* A[8];
    const float* B[8];
    float*       C[8];
    const float* aux[8];
    float* r0; float* r1;
    int M, N, K, lda, ldb, ldc;
    const int* gcnt; const int* gidx; const float* gwt; const int* gslot;
};

// ---------------- fp16 mma GEMM, 128x256 tile, KT=16, double-buffered ----
// All GEMMs are C = A @ B^T with A [M,K], B [N,K] row-major.
// Smem rows = 8 half2 slots (32B). Slot s holds k-pair t = 4*(s&1)+(s>>1),
// i.e. pairs (t, t+4) adjacent -> one LDS.64 per (a0,a2)/(a1,a3)/(b0,b1).
// Rows are 32B: 4 consecutive rows span all 32 banks -> conflict-free.
// MODE 0: C=v  1: silu  2: C=v*aux (in-place safe)  3: C=v+aux
//      4: scatter w*v to (r0|r1)[gidx]   5: C=v/32, causal tile skip
template<int MODE, bool GATHER>
__global__ void __launch_bounds__(256) gemm3(GA ga) {
    const int z = blockIdx.z;
    const int bm = blockIdx.y * 128;
    const int bn = blockIdx.x * 256;
    if (MODE == 5 && bn > bm + 127) return;

    int Meff = ga.M;
    const int* gidx = nullptr; const float* gwt = nullptr; const int* gslot = nullptr;
    if (GATHER || MODE == 4) {
        Meff = ga.gcnt[z];
        gidx = ga.gidx + z * BTd;
        gwt  = ga.gwt  + z * BTd;
        gslot= ga.gslot+ z * BTd;
    }
    if (bm >= Meff) return;

    const float* __restrict__ A   = ga.A[z];
    const float* __restrict__ Bm  = ga.B[z];
    float* __restrict__ C         = ga.C[z];
    const float* __restrict__ aux = ga.aux[z];
    const int K = ga.K, lda = ga.lda, ldb = ga.ldb, ldc = ga.ldc;

    __shared__ unsigned As[2][1024];   // 128 rows x 8 half2-slots
    __shared__ unsigned Bs[2][2048];   // 256 rows x 8 half2-slots

    const int tid = threadIdx.x;
    const int lane = tid & 31, wid = tid >> 5;
    const int wm = wid & 1, wn = wid >> 1;      // 2 x 4 warps, 64x64 each
    const int gid = lane >> 2, tig = lane & 3;

    // A loader: 2 threads/row; thread ag loads k = ag*4+[0,4) and 8+ag*4+[0,4)
    const int arow = tid >> 1;
    const int ag = tid & 1;
    const int am = bm + arow;
    const bool aval = am < Meff;
    int asrc = 0;
    if (aval) asrc = GATHER ? gidx[am] : am;
    const float* Ap = A + (size_t)asrc * lda + ag * 4;

    // B loader: 2 threads/row, covering rows brow and brow+128
    const int brow = tid >> 1;
    const int bg = tid & 1;
    const float* Bp0 = Bm + (size_t)(bn + brow) * ldb + bg * 4;
    const float* Bp1 = Bp0 + (size_t)128 * ldb;

    float acc[4][8][4];
    #pragma unroll
    for (int i = 0; i < 4; i++)
        #pragma unroll
        for (int j = 0; j < 8; j++)
            #pragma unroll
            for (int l = 0; l < 4; l++) acc[i][j][l] = 0.f;

    const float4 Z4 = make_float4(0.f, 0.f, 0.f, 0.f);
    float ra[8], rb[16];

    auto load_t = [&](int kt_) {
        *(float4*)ra      = aval ? *(const float4*)(Ap + kt_)     : Z4;
        *(float4*)(ra+4)  = aval ? *(const float4*)(Ap + kt_ + 8) : Z4;
        *(float4*)rb      = *(const float4*)(Bp0 + kt_);
        *(float4*)(rb+4)  = *(const float4*)(Bp0 + kt_ + 8);
        *(float4*)(rb+8)  = *(const float4*)(Bp1 + kt_);
        *(float4*)(rb+12) = *(const float4*)(Bp1 + kt_ + 8);
    };

    auto store_t = [&](int st_) {
        uint4 u;
        u.x = f2h2(ra[0], ra[1]); u.y = f2h2(ra[4], ra[5]);
        u.z = f2h2(ra[2], ra[3]); u.w = f2h2(ra[6], ra[7]);
        *(uint4*)&As[st_][arow*8 + ag*4] = u;
        u.x = f2h2(rb[0], rb[1]); u.y = f2h2(rb[4], rb[5]);
        u.z = f2h2(rb[2], rb[3]); u.w = f2h2(rb[6], rb[7]);
        *(uint4*)&Bs[st_][brow*8 + bg*4] = u;
        u.x = f2h2(rb[8], rb[9]);  u.y = f2h2(rb[12], rb[13]);
        u.z = f2h2(rb[10], rb[11]); u.w = f2h2(rb[14], rb[15]);
        *(uint4*)&Bs[st_][(brow+128)*8 + bg*4] = u;
    };

    // prologue: tile0 -> stage0, tile1 -> regs
    load_t(0);
    store_t(0);
    load_t(16);

    int st = 0;
    for (int kt = 0; kt < K; kt += 16) {
        __syncthreads();
        if (kt + 16 < K) {
            store_t(st ^ 1);
            if (kt + 32 < K) load_t(kt + 32);
        }
        // compute stage st: one k16 step
        uint2 a02[4], a13[4], b01[8];
        #pragma unroll
        for (int mt = 0; mt < 4; mt++) {
            int r = wm*64 + mt*16 + gid;
            a02[mt] = *(const uint2*)&As[st][r*8 + 2*tig];
            a13[mt] = *(const uint2*)&As[st][(r+8)*8 + 2*tig];
        }
        #pragma unroll
        for (int nt = 0; nt < 8; nt++) {
            int c = wn*64 + nt*8 + gid;
            b01[nt] = *(const uint2*)&Bs[st][c*8 + 2*tig];
        }
        #pragma unroll
        for (int mt = 0; mt < 4; mt++) {
            unsigned a[4] = {a02[mt].x, a13[mt].x, a02[mt].y, a13[mt].y};
            #pragma unroll
            for (int nt = 0; nt < 8; nt++) {
                unsigned b[2] = {b01[nt].x, b01[nt].y};
                mma_f16(acc[mt][nt], a, b);
            }
        }
        st ^= 1;
    }

    // ---- epilogue ----
    #pragma unroll
    for (int mt = 0; mt < 4; mt++) {
        #pragma unroll
        for (int i2 = 0; i2 < 2; i2++) {
            int gm = bm + wm*64 + mt*16 + gid + i2*8;
            if (gm >= Meff) continue;
            int trow = 0; float wgt = 0.f;
            if (MODE == 4) { trow = gidx[gm]; wgt = gwt[gm]; }
            float* Ct = (MODE == 4) ? (gslot[gm] ? ga.r1 : ga.r0) : C;
            #pragma unroll
            for (int nt = 0; nt < 8; nt++) {
                #pragma unroll
                for (int j2 = 0; j2 < 2; j2++) {
                    int gn = bn + wn*64 + nt*8 + tig*2 + j2;
                    float v = acc[mt][nt][i2*2 + j2];
                    size_t o = (size_t)gm * ldc + gn;
                    if (MODE == 0)      C[o] = v;
                    else if (MODE == 1) C[o] = v / (1.f + expf(-v));
                    else if (MODE == 2) C[o] = v * aux[o];
                    else if (MODE == 3) C[o] = v + aux[o];
                    else if (MODE == 4) Ct[(size_t)trow * ldc + gn] = wgt * v;
                    else if (MODE == 5) C[o] = v * 0.03125f;
                }
            }
        }
    }
}

// ---------------- final add ----------------
__global__ void final_add_kernel(const float* __restrict__ a, const float* __restrict__ b,
                                 const float* __restrict__ c, const float* __restrict__ d,
                                 float* __restrict__ out) {
    size_t i = (size_t)blockIdx.x * blockDim.x + threadIdx.x;
    out[i] = a[i] + b[i] + c[i] + d[i];
}

// ---------------- launch ----------------
extern "C" void kernel_launch(void* const* d_in, const int* in_sizes, int n_in,
                              void* d_out, int out_size) {
    (void)in_sizes; (void)n_in; (void)out_size;
    const float* x         = (const float*)d_in[0];
    const float* ln1w      = (const float*)d_in[1];
    const float* ln2w      = (const float*)d_in[2];
    const float* kv_proj_d = (const float*)d_in[3];
    const float* q_proj_d  = (const float*)d_in[4];
    const float* v_proj_u  = (const float*)d_in[7];
    const float* rope_k    = (const float*)d_in[8];
    const float* rope_q    = (const float*)d_in[9];
    const float* o_proj    = (const float*)d_in[10];
    const float* router_w  = (const float*)d_in[11];
    const float* router_b  = (const float*)d_in[12];
    const float* sh_gate   = (const float*)d_in[13];
    const float* sh_up     = (const float*)d_in[14];
    const float* sh_down   = (const float*)d_in[15];
    const float* ex_gate   = (const float*)d_in[16];
    const float* ex_up     = (const float*)d_in[17];
    const float* ex_down   = (const float*)d_in[18];
    float* out = (float*)d_out;

    float *h,*kvlat,*qlat,*v,*q,*k,*scores,*y,*x1,*h2,*gbuf,*shb,*r0,*r1,*gwt;
    int *cnt,*gidx,*gslot;
    cudaGetSymbolAddress((void**)&h, g_h);
    cudaGetSymbolAddress((void**)&kvlat, g_kvlat);
    cudaGetSymbolAddress((void**)&qlat, g_qlat);
    cudaGetSymbolAddress((void**)&v, g_v);
    cudaGetSymbolAddress((void**)&q, g_q);
    cudaGetSymbolAddress((void**)&k, g_k);
    cudaGetSymbolAddress((void**)&scores, g_scores);
    cudaGetSymbolAddress((void**)&y, g_y);
    cudaGetSymbolAddress((void**)&x1, g_x1);
    cudaGetSymbolAddress((void**)&h2, g_h2);
    cudaGetSymbolAddress((void**)&gbuf, g_gbuf);
    cudaGetSymbolAddress((void**)&shb, g_shb);
    cudaGetSymbolAddress((void**)&r0, g_r0);
    cudaGetSymbolAddress((void**)&r1, g_r1);
    cudaGetSymbolAddress((void**)&cnt, g_cnt);
    cudaGetSymbolAddress((void**)&gidx, g_gidx);
    cudaGetSymbolAddress((void**)&gwt, g_gwt);
    cudaGetSymbolAddress((void**)&gslot, g_gslot);

    const size_t ESL = (size_t)BTd * Fd;   // per-expert gbuf slice

    zero_cnt_kernel<<<1, 32>>>();
    ln_kernel<<<BTd, 256>>>(x, ln1w, h);

    // qlat + kvlat (z=2), N=256
    {
        GA ga = {};
        ga.A[0] = h;        ga.A[1] = h;
        ga.B[0] = q_proj_d; ga.B[1] = kv_proj_d;
        ga.C[0] = qlat;     ga.C[1] = kvlat;
        ga.M = BTd; ga.N = Ld; ga.K = Hd; ga.lda = Hd; ga.ldb = Hd; ga.ldc = Ld;
        gemm3<0,false><<<dim3(Ld/256, BTd/128, 2), 256>>>(ga);
    }
    // vT[b] = v_proj_u @ kvlat[b]^T   (M=Hd, N=Td, K=Ld) -> PV becomes BTRANS
    {
        GA ga = {};
        for (int b = 0; b < Bd; b++) {
            ga.A[b] = v_proj_u;
            ga.B[b] = kvlat + (size_t)b*Td*Ld;
            ga.C[b] = v + (size_t)b*Hd*Td;
        }
        ga.M = Hd; ga.N = Td; ga.K = Ld; ga.lda = Ld; ga.ldb = Ld; ga.ldc = Td;
        gemm3<0,false><<<dim3(Td/256, Hd/128, Bd), 256>>>(ga);
    }
    // q_r = qlat @ rope_q.T
    {
        GA ga = {};
        ga.A[0] = qlat; ga.B[0] = rope_q; ga.C[0] = q;
        ga.M = BTd; ga.N = Hd; ga.K = Ld; ga.lda = Ld; ga.ldb = Ld; ga.ldc = Hd;
        gemm3<0,false><<<dim3(Hd/256, BTd/128, 1), 256>>>(ga);
    }
    // k_r = h @ rope_k.T
    {
        GA ga = {};
        ga.A[0] = h; ga.B[0] = rope_k; ga.C[0] = k;
        ga.M = BTd; ga.N = Hd; ga.K = Hd; ga.lda = Hd; ga.ldb = Hd; ga.ldc = Hd;
        gemm3<0,false><<<dim3(Hd/256, BTd/128, 1), 256>>>(ga);
    }

    rope_kernel<<<BTd, 256>>>(q, k);

    // scores (z=2, causal)
    {
        GA ga = {};
        for (int b = 0; b < Bd; b++) {
            ga.A[b] = q + (size_t)b*Td*Hd;
            ga.B[b] = k + (size_t)b*Td*Hd;
            ga.C[b] = scores + (size_t)b*Td*Td;
        }
        ga.M = Td; ga.N = Td; ga.K = Hd; ga.lda = Hd; ga.ldb = Hd; ga.ldc = Td;
        gemm3<5,false><<<dim3(Td/256, Td/128, Bd), 256>>>(ga);
    }
    softmax_kernel<<<dim3(Td, Bd), 256>>>(scores);
    // PV (z=2): y[b] = attn[b] @ vT[b]^T
    {
        GA ga = {};
        for (int b = 0; b < Bd; b++) {
            ga.A[b] = scores + (size_t)b*Td*Td;
            ga.B[b] = v + (size_t)b*Hd*Td;
            ga.C[b] = y + (size_t)b*Td*Hd;
        }
        ga.M = Td; ga.N = Hd; ga.K = Td; ga.lda = Td; ga.ldb = Td; ga.ldc = Hd;
        gemm3<0,false><<<dim3(Hd/256, Td/128, Bd), 256>>>(ga);
    }
    // x1 = x + y @ o_proj.T
    {
        GA ga = {};
        ga.A[0] = y; ga.B[0] = o_proj; ga.C[0] = x1; ga.aux[0] = x;
        ga.M = BTd; ga.N = Hd; ga.K = Hd; ga.lda = Hd; ga.ldb = Hd; ga.ldc = Hd;
        gemm3<3,false><<<dim3(Hd/256, BTd/128, 1), 256>>>(ga);
    }

    // ---- MoE ----
    ln_kernel<<<BTd, 256>>>(x1, ln2w, h2);
    router_kernel<<<BTd, 256>>>(h2, router_w, router_b);

    float* shg = gbuf + (size_t)7 * ESL;   // shared-expert slice
    // shared gate (silu)
    {
        GA ga = {};
        ga.A[0] = h2; ga.B[0] = sh_gate; ga.C[0] = shg;
        ga.M = BTd; ga.N = Fd; ga.K = Hd; ga.lda = Hd; ga.ldb = Hd; ga.ldc = Fd;
        gemm3<1,false><<<dim3(Fd/256, BTd/128, 1), 256>>>(ga);
    }
    // shared up (in-place multiply into shg)
    {
        GA ga = {};
        ga.A[0] = h2; ga.B[0] = sh_up; ga.C[0] = shg; ga.aux[0] = shg;
        ga.M = BTd; ga.N = Fd; ga.K = Hd; ga.lda = Hd; ga.ldb = Hd; ga.ldc = Fd;
        gemm3<2,false><<<dim3(Fd/256, BTd/128, 1), 256>>>(ga);
    }
    // shared down
    {
        GA ga = {};
        ga.A[0] = shg; ga.B[0] = sh_down; ga.C[0] = shb;
        ga.M = BTd; ga.N = Hd; ga.K = Fd; ga.lda = Fd; ga.ldb = Fd; ga.ldc = Hd;
        gemm3<0,false><<<dim3(Hd/256, BTd/128, 1), 256>>>(ga);
    }

    // routed experts, all 7 batched per stage
    {
        GA ga = {};
        for (int e = 0; e < Ed; e++) {
            ga.A[e] = h2;
            ga.B[e] = ex_gate + (size_t)e * Fd * Hd;
            ga.C[e] = gbuf + (size_t)e * ESL;
        }
        ga.M = BTd; ga.N = Fd; ga.K = Hd; ga.lda = Hd; ga.ldb = Hd; ga.ldc = Fd;
        ga.gcnt = cnt; ga.gidx = gidx; ga.gwt = gwt; ga.gslot = gslot;
        gemm3<1,true><<<dim3(Fd/256, BTd/128, Ed), 256>>>(ga);
    }
    {
        GA ga = {};
        for (int e = 0; e < Ed; e++) {
            ga.A[e] = h2;
            ga.B[e] = ex_up + (size_t)e * Fd * Hd;
            ga.C[e] = gbuf + (size_t)e * ESL;
            ga.aux[e] = gbuf + (size_t)e * ESL;
        }
        ga.M = BTd; ga.N = Fd; ga.K = Hd; ga.lda = Hd; ga.ldb = Hd; ga.ldc = Fd;
        ga.gcnt = cnt; ga.gidx = gidx; ga.gwt = gwt; ga.gslot = gslot;
        gemm3<2,true><<<dim3(Fd/256, BTd/128, Ed), 256>>>(ga);
    }
    {
        GA ga = {};
        for (int e = 0; e < Ed; e++) {
            ga.A[e] = gbuf + (size_t)e * ESL;
            ga.B[e] = ex_down + (size_t)e * Hd * Fd;
        }
        ga.r0 = r0; ga.r1 = r1;
        ga.M = BTd; ga.N = Hd; ga.K = Fd; ga.lda = Fd; ga.ldb = Fd; ga.ldc = Hd;
        ga.gcnt = cnt; ga.gidx = gidx; ga.gwt = gwt; ga.gslot = gslot;
        gemm3<4,false><<<dim3(Hd/256, BTd/128, Ed), 256>>>(ga);
    }

    final_add_kernel<<<(BTd * Hd) / 256, 256>>>(x1, shb, r0, r1, out);
}

// round 9
// speedup vs baseline: 2.2228x; 1.2365x over previous
#include <cuda_runtime.h>
#include <cuda_fp16.h>
#include <math.h>

#define Bd 2
#define Td 2048
#define Hd 1024
#define Ld 256
#define Fd 2048
#define Ed 7
#define BTd (Bd*Td)

// weight fp16 pool offsets (in halves)
#define W_QPD 0
#define W_KVD 262144
#define W_VPU 524288
#define W_RQ  786432
#define W_RK  1048576
#define W_OPJ 2097152
#define W_SHG 3145728
#define W_SHU 5242880
#define W_SHD 7340032
#define W_EXG 9437184
#define W_EXU 24117248
#define W_EXD 38797312
#define W_TOT 53477376

// ---------------- scratch (device globals; no allocation) ----------------
__device__ __half g_w16[W_TOT];
__device__ __half g_h16[BTd*Hd];
__device__ __half g_qlat16[BTd*Ld];
__device__ __half g_kvlat16[BTd*Ld];
__device__ __half g_vT16[BTd*Hd];      // [Bd][Hd][Td]
__device__ __half g_q16[BTd*Hd];
__device__ __half g_k16[BTd*Hd];
__device__ __half g_sc16[(size_t)Bd*Td*Td];
__device__ __half g_y16[BTd*Hd];
__device__ __half g_h2_16[BTd*Hd];
__device__ __half g_gbuf16[(size_t)8*BTd*Fd];  // 7 routed + 1 shared slices
__device__ float  g_h2[BTd*Hd];
__device__ float  g_x1[BTd*Hd];
__device__ float  g_shb[BTd*Hd];
__device__ float  g_r0[BTd*Hd];
__device__ float  g_r1[BTd*Hd];
__device__ int    g_cnt[Ed];
__device__ int    g_gidx[Ed*BTd];
__device__ float  g_gwt[Ed*BTd];
__device__ int    g_gslot[Ed*BTd];

// ---------------- fp16 helpers ----------------
__device__ __forceinline__ unsigned f2h2(float lo, float hi) {
    __half2 h = __floats2half2_rn(lo, hi);
    return *(unsigned*)&h;
}

// ---------------- weight conversion ----------------
struct CVT {
    const float* src[12];
    __half* dst[12];
    int n[12];
};

__global__ void cvt_kernel(CVT cv) {
    int seg = blockIdx.y;
    int idx = blockIdx.x * 256 + threadIdx.x;
    int n8 = cv.n[seg] >> 3;
    if (idx >= n8) return;
    const float4* s = (const float4*)cv.src[seg];
    float4 f1 = s[2*idx], f2 = s[2*idx+1];
    uint4 o;
    o.x = f2h2(f1.x, f1.y); o.y = f2h2(f1.z, f1.w);
    o.z = f2h2(f2.x, f2.y); o.w = f2h2(f2.z, f2.w);
    ((uint4*)cv.dst[seg])[idx] = o;
}

// ---------------- block reduce ----------------
template<bool DOMAX>
__device__ __forceinline__ float blockReduce(float v) {
    __shared__ float sh[8];
    __shared__ float res;
    int lane = threadIdx.x & 31, w = threadIdx.x >> 5;
    #pragma unroll
    for (int o = 16; o; o >>= 1) {
        float t = __shfl_xor_sync(0xffffffffu, v, o);
        v = DOMAX ? fmaxf(v, t) : v + t;
    }
    if (lane == 0) sh[w] = v;
    __syncthreads();
    if (w == 0) {
        v = (lane < (int)(blockDim.x >> 5)) ? sh[lane] : (DOMAX ? -3.4e38f : 0.f);
        #pragma unroll
        for (int o = 4; o; o >>= 1) {
            float t = __shfl_xor_sync(0xffffffffu, v, o);
            v = DOMAX ? fmaxf(v, t) : v + t;
        }
        if (lane == 0) res = v;
    }
    __syncthreads();
    return res;
}

// ---------------- layernorm (fp16 out, optional fp32 copy) ----------------
__global__ void ln_kernel(const float* __restrict__ x, const float* __restrict__ w,
                          __half* __restrict__ o16, float* __restrict__ o32) {
    int row = blockIdx.x;
    const float* xr = x + (size_t)row * Hd;
    int t = threadIdx.x;
    float v[4];
    float s = 0.f;
    #pragma unroll
    for (int i = 0; i < 4; i++) { v[i] = xr[t + 256*i]; s += v[i]; }
    s = blockReduce<false>(s);
    float mu = s * (1.f / Hd);
    float q = 0.f;
    #pragma unroll
    for (int i = 0; i < 4; i++) { float d = v[i] - mu; q += d * d; }
    q = blockReduce<false>(q);
    float rs = rsqrtf(q * (1.f / Hd) + 1e-5f);
    #pragma unroll
    for (int i = 0; i < 4; i++) {
        float val = (v[i] - mu) * rs * w[t + 256*i];
        o16[(size_t)row*Hd + t + 256*i] = __float2half_rn(val);
        if (o32) o32[(size_t)row*Hd + t + 256*i] = val;
    }
}

// ---------------- rope (fp16 in/out) ----------------
__global__ void rope_kernel(__half* __restrict__ q, __half* __restrict__ k) {
    int row = blockIdx.x;
    int t = row % Td;
    size_t base = (size_t)row * Hd;
    #pragma unroll
    for (int it = 0; it < 2; it++) {
        int p = threadIdx.x + 256 * it;
        double invf = exp(-(double)(2 * p) / 1024.0 * 9.210340371976184);
        float f = (float)t * (float)invf;
        float c = cosf(f), s = sinf(f);
        float q1 = __half2float(q[base + p]), q2 = __half2float(q[base + p + 512]);
        q[base + p]       = __float2half_rn(q1 * c - q2 * s);
        q[base + p + 512] = __float2half_rn(q2 * c + q1 * s);
        float k1 = __half2float(k[base + p]), k2 = __half2float(k[base + p + 512]);
        k[base + p]       = __float2half_rn(k1 * c - k2 * s);
        k[base + p + 512] = __float2half_rn(k2 * c + k1 * s);
    }
}

// ---------------- softmax (causal, fp16 in/out, fp32 math) ----------------
__global__ void softmax_kernel(__half* __restrict__ sc) {
    int b = blockIdx.y, i = blockIdx.x;
    __half* row = sc + ((size_t)b * Td + i) * Td;
    int t = threadIdx.x;
    int n = i + 1;
    float mx = -3.4e38f;
    for (int j = t; j < n; j += 256) mx = fmaxf(mx, __half2float(row[j]));
    mx = blockReduce<true>(mx);
    float s = 0.f;
    for (int j = t; j < n; j += 256) s += expf(__half2float(row[j]) - mx);
    s = blockReduce<false>(s);
    float inv = 1.f / s;
    for (int j = t; j < Td; j += 256) {
        float v = (j < n) ? expf(__half2float(row[j]) - mx) * inv : 0.f;
        row[j] = __float2half_rn(v);
    }
}

// ---------------- router + top2 gather lists ----------------
__global__ void zero_cnt_kernel() {
    if (threadIdx.x < Ed) g_cnt[threadIdx.x] = 0;
}

__global__ void router_kernel(const float* __restrict__ h2, const float* __restrict__ rw,
                              const float* __restrict__ rb) {
    int m = blockIdx.x;
    int w = threadIdx.x >> 5, lane = threadIdx.x & 31;
    __shared__ float probs[Ed];
    if (w < Ed) {
        const float* hv = h2 + (size_t)m * Hd;
        const float* wv = rw + (size_t)w * Hd;
        float s = 0.f;
        for (int j = lane; j < Hd; j += 32) s += hv[j] * wv[j];
        #pragma unroll
        for (int o = 16; o; o >>= 1) s += __shfl_xor_sync(0xffffffffu, s, o);
        if (lane == 0) probs[w] = 1.f / (1.f + expf(-(s + rb[w])));
    }
    __syncthreads();
    if (threadIdx.x == 0) {
        int e0 = 0; float p0 = probs[0];
        for (int e = 1; e < Ed; e++) if (probs[e] > p0) { p0 = probs[e]; e0 = e; }
        int e1 = -1; float p1 = -3.4e38f;
        for (int e = 0; e < Ed; e++) if (e != e0 && probs[e] > p1) { p1 = probs[e]; e1 = e; }
        int pos = atomicAdd(&g_cnt[e0], 1);
        g_gidx[e0*BTd + pos] = m; g_gwt[e0*BTd + pos] = p0; g_gslot[e0*BTd + pos] = 0;
        pos = atomicAdd(&g_cnt[e1], 1);
        g_gidx[e1*BTd + pos] = m; g_gwt[e1*BTd + pos] = p1; g_gslot[e1*BTd + pos] = 1;
    }
}

// ---------------- mma ----------------
__device__ __forceinline__ void mma_f16(float* d, const unsigned* a, const unsigned* b) {
    asm volatile(
        "mma.sync.aligned.m16n8k16.row.col.f32.f16.f16.f32 "
        "{%0,%1,%2,%3}, {%4,%5,%6,%7}, {%8,%9}, {%0,%1,%2,%3};"
        : "+f"(d[0]), "+f"(d[1]), "+f"(d[2]), "+f"(d[3])
        : "r"(a[0]), "r"(a[1]), "r"(a[2]), "r"(a[3]), "r"(b[0]), "r"(b[1]));
}

// per-z pointer tables for batched launches
struct GA {
    const void* A[8];
    const void* B[8];
    void*       C[8];
    const void* aux[8];
    float* r0; float* r1;
    int M, N, K, lda, ldb, ldc;
    const int* gcnt; const int* gidx; const float* gwt; const int* gslot;
};

// ---------------- fp16 mma GEMM, 128x256 tile, KT=32, double-buffered ----
// C = A @ B^T, A [M,K] half, B [N,K] half, row-major.
// Smem: per stage, two k16 sub-buffers, rows of 8 half2 slots (32B).
// Slot order within sub: pairs (0,4,1,5,2,6,3,7) -> LDS.64 fragments.
// MODE 0: C=v  1: silu  2: C=v*aux  3: C=v+aux (fp32)
//      4: scatter w*v to (r0|r1)[gidx] (fp32)   5: C=v/32, causal tile skip
template<int MODE, bool GATHER, bool OHALF>
__global__ void __launch_bounds__(256) gemm4(GA ga) {
    const int z = blockIdx.z;
    const int bm = blockIdx.y * 128;
    const int bn = blockIdx.x * 256;
    if (MODE == 5 && bn > bm + 127) return;

    int Meff = ga.M;
    const int* gidx = nullptr; const float* gwt = nullptr; const int* gslot = nullptr;
    if (GATHER || MODE == 4) {
        Meff = ga.gcnt[z];
        gidx = ga.gidx + z * BTd;
        gwt  = ga.gwt  + z * BTd;
        gslot= ga.gslot+ z * BTd;
    }
    if (bm >= Meff) return;

    const __half* __restrict__ A  = (const __half*)ga.A[z];
    const __half* __restrict__ Bm = (const __half*)ga.B[z];
    const int K = ga.K, lda = ga.lda, ldb = ga.ldb, ldc = ga.ldc;

    extern __shared__ unsigned sm[];   // 2 stages x (A 2x1024 + B 2x2048) = 12288 uints

    const int tid = threadIdx.x;
    const int lane = tid & 31, wid = tid >> 5;
    const int wm = wid & 1, wn = wid >> 1;      // 2 x 4 warps, 64x64 each
    const int gid = lane >> 2, tig = lane & 3;

    // A loader: 2 threads/row; thread ag loads k-sub ag (16 halves = 1x32B)
    const int arow = tid >> 1;
    const int ag = tid & 1;
    const int am = bm + arow;
    const bool aval = am < Meff;
    int asrc = 0;
    if (aval) asrc = GATHER ? gidx[am] : am;
    const __half* Ap = A + (size_t)asrc * lda + ag * 16;

    // B loader: 2 threads/row, rows brow and brow+128; thread bg loads k-sub bg
    const int brow = tid >> 1;
    const int bg = tid & 1;
    const __half* Bp0 = Bm + (size_t)(bn + brow) * ldb + bg * 16;
    const __half* Bp1 = Bp0 + (size_t)128 * ldb;

    float acc[4][8][4];
    #pragma unroll
    for (int i = 0; i < 4; i++)
        #pragma unroll
        for (int j = 0; j < 8; j++)
            #pragma unroll
            for (int l = 0; l < 4; l++) acc[i][j][l] = 0.f;

    const uint4 Zu = make_uint4(0u, 0u, 0u, 0u);
    uint4 ra4[2], rb4[4];

    auto load_t = [&](int it_) {
        int kt = it_ * 32;
        ra4[0] = aval ? *(const uint4*)(Ap + kt)     : Zu;
        ra4[1] = aval ? *(const uint4*)(Ap + kt + 8) : Zu;
        rb4[0] = *(const uint4*)(Bp0 + kt);
        rb4[1] = *(const uint4*)(Bp0 + kt + 8);
        rb4[2] = *(const uint4*)(Bp1 + kt);
        rb4[3] = *(const uint4*)(Bp1 + kt + 8);
    };

    // permute pairs (p0..p3),(p4..p7) -> slots (p0,p4,p1,p5),(p2,p6,p3,p7)
    auto store_t = [&](int st_) {
        unsigned* Asub = sm + st_*6144 + ag*1024;
        unsigned* Bsub = sm + st_*6144 + 2048 + bg*2048;
        uint4 u;
        u.x = ra4[0].x; u.y = ra4[1].x; u.z = ra4[0].y; u.w = ra4[1].y;
        *(uint4*)&Asub[arow*8 + 0] = u;
        u.x = ra4[0].z; u.y = ra4[1].z; u.z = ra4[0].w; u.w = ra4[1].w;
        *(uint4*)&Asub[arow*8 + 4] = u;
        u.x = rb4[0].x; u.y = rb4[1].x; u.z = rb4[0].y; u.w = rb4[1].y;
        *(uint4*)&Bsub[brow*8 + 0] = u;
        u.x = rb4[0].z; u.y = rb4[1].z; u.z = rb4[0].w; u.w = rb4[1].w;
        *(uint4*)&Bsub[brow*8 + 4] = u;
        u.x = rb4[2].x; u.y = rb4[3].x; u.z = rb4[2].y; u.w = rb4[3].y;
        *(uint4*)&Bsub[(brow+128)*8 + 0] = u;
        u.x = rb4[2].z; u.y = rb4[3].z; u.z = rb4[2].w; u.w = rb4[3].w;
        *(uint4*)&Bsub[(brow+128)*8 + 4] = u;
    };

    const int NT = K / 32;
    load_t(0);
    store_t(0);
    load_t(1);

    int st = 0;
    for (int it = 0; it < NT; it++) {
        __syncthreads();
        if (it + 1 < NT) {
            store_t(st ^ 1);
            if (it + 2 < NT) load_t(it + 2);
        }
        #pragma unroll
        for (int g8 = 0; g8 < 2; g8++) {
            const unsigned* Asub = sm + st*6144 + g8*1024;
            const unsigned* Bsub = sm + st*6144 + 2048 + g8*2048;
            uint2 a02[4], a13[4], b01[8];
            #pragma unroll
            for (int mt = 0; mt < 4; mt++) {
                int r = wm*64 + mt*16 + gid;
                a02[mt] = *(const uint2*)&Asub[r*8 + 2*tig];
                a13[mt] = *(const uint2*)&Asub[(r+8)*8 + 2*tig];
            }
            #pragma unroll
            for (int nt = 0; nt < 8; nt++) {
                int c = wn*64 + nt*8 + gid;
                b01[nt] = *(const uint2*)&Bsub[c*8 + 2*tig];
            }
            #pragma unroll
            for (int mt = 0; mt < 4; mt++) {
                unsigned a[4] = {a02[mt].x, a13[mt].x, a02[mt].y, a13[mt].y};
                #pragma unroll
                for (int nt = 0; nt < 8; nt++) {
                    unsigned b[2] = {b01[nt].x, b01[nt].y};
                    mma_f16(acc[mt][nt], a, b);
                }
            }
        }
        st ^= 1;
    }

    // ---- epilogue ----
    #pragma unroll
    for (int mt = 0; mt < 4; mt++) {
        #pragma unroll
        for (int i2 = 0; i2 < 2; i2++) {
            int gm = bm + wm*64 + mt*16 + gid + i2*8;
            if (gm >= Meff) continue;
            int trow = 0; float wgt = 0.f; float* Ct = nullptr;
            if (MODE == 4) { trow = gidx[gm]; wgt = gwt[gm]; Ct = gslot[gm] ? ga.r1 : ga.r0; }
            #pragma unroll
            for (int nt = 0; nt < 8; nt++) {
                int gn = bn + wn*64 + nt*8 + tig*2;
                float v0 = acc[mt][nt][i2*2 + 0];
                float v1 = acc[mt][nt][i2*2 + 1];
                size_t o = (size_t)gm * ldc + gn;
                if (MODE == 1) {
                    v0 = v0 / (1.f + expf(-v0));
                    v1 = v1 / (1.f + expf(-v1));
                } else if (MODE == 2) {
                    __half2 a2 = *(const __half2*)((const __half*)ga.aux[z] + o);
                    v0 *= __low2float(a2); v1 *= __high2float(a2);
                } else if (MODE == 3) {
                    float2 a2 = *(const float2*)((const float*)ga.aux[z] + o);
                    v0 += a2.x; v1 += a2.y;
                } else if (MODE == 5) {
                    v0 *= 0.03125f; v1 *= 0.03125f;
                }
                if (MODE == 4) {
                    float2 w2; w2.x = wgt*v0; w2.y = wgt*v1;
                    *(float2*)(Ct + (size_t)trow * ldc + gn) = w2;
                } else if (OHALF) {
                    *(__half2*)((__half*)ga.C[z] + o) = __floats2half2_rn(v0, v1);
                } else {
                    float2 w2; w2.x = v0; w2.y = v1;
                    *(float2*)((float*)ga.C[z] + o) = w2;
                }
            }
        }
    }
}

// ---------------- final add ----------------
__global__ void final_add_kernel(const float* __restrict__ a, const float* __restrict__ b,
                                 const float* __restrict__ c, const float* __restrict__ d,
                                 float* __restrict__ out) {
    size_t i = (size_t)blockIdx.x * blockDim.x + threadIdx.x;
    out[i] = a[i] + b[i] + c[i] + d[i];
}

// ---------------- launch ----------------
extern "C" void kernel_launch(void* const* d_in, const int* in_sizes, int n_in,
                              void* d_out, int out_size) {
    (void)in_sizes; (void)n_in; (void)out_size;
    const float* x         = (const float*)d_in[0];
    const float* ln1w      = (const float*)d_in[1];
    const float* ln2w      = (const float*)d_in[2];
    const float* kv_proj_d = (const float*)d_in[3];
    const float* q_proj_d  = (const float*)d_in[4];
    const float* v_proj_u  = (const float*)d_in[7];
    const float* rope_k    = (const float*)d_in[8];
    const float* rope_q    = (const float*)d_in[9];
    const float* o_proj    = (const float*)d_in[10];
    const float* router_w  = (const float*)d_in[11];
    const float* router_b  = (const float*)d_in[12];
    const float* sh_gate   = (const float*)d_in[13];
    const float* sh_up     = (const float*)d_in[14];
    const float* sh_down   = (const float*)d_in[15];
    const float* ex_gate   = (const float*)d_in[16];
    const float* ex_up     = (const float*)d_in[17];
    const float* ex_down   = (const float*)d_in[18];
    float* out = (float*)d_out;

    __half *w16,*h16,*qlat16,*kvlat16,*vT16,*q16,*k16,*sc16,*y16,*h2_16,*gbuf16;
    float *h2,*x1,*shb,*r0,*r1,*gwt;
    int *cnt,*gidx,*gslot;
    cudaGetSymbolAddress((void**)&w16, g_w16);
    cudaGetSymbolAddress((void**)&h16, g_h16);
    cudaGetSymbolAddress((void**)&qlat16, g_qlat16);
    cudaGetSymbolAddress((void**)&kvlat16, g_kvlat16);
    cudaGetSymbolAddress((void**)&vT16, g_vT16);
    cudaGetSymbolAddress((void**)&q16, g_q16);
    cudaGetSymbolAddress((void**)&k16, g_k16);
    cudaGetSymbolAddress((void**)&sc16, g_sc16);
    cudaGetSymbolAddress((void**)&y16, g_y16);
    cudaGetSymbolAddress((void**)&h2_16, g_h2_16);
    cudaGetSymbolAddress((void**)&gbuf16, g_gbuf16);
    cudaGetSymbolAddress((void**)&h2, g_h2);
    cudaGetSymbolAddress((void**)&x1, g_x1);
    cudaGetSymbolAddress((void**)&shb, g_shb);
    cudaGetSymbolAddress((void**)&r0, g_r0);
    cudaGetSymbolAddress((void**)&r1, g_r1);
    cudaGetSymbolAddress((void**)&cnt, g_cnt);
    cudaGetSymbolAddress((void**)&gidx, g_gidx);
    cudaGetSymbolAddress((void**)&gwt, g_gwt);
    cudaGetSymbolAddress((void**)&gslot, g_gslot);

    const size_t ESL = (size_t)BTd * Fd;   // per-expert gbuf16 slice
    const int SMEM = 49152;

    // ---- weight conversion (fp32 -> fp16 pool) ----
    {
        CVT cv;
        cv.src[0] = q_proj_d;  cv.dst[0] = w16 + W_QPD; cv.n[0] = Ld*Hd;
        cv.src[1] = kv_proj_d; cv.dst[1] = w16 + W_KVD; cv.n[1] = Ld*Hd;
        cv.src[2] = v_proj_u;  cv.dst[2] = w16 + W_VPU; cv.n[2] = Hd*Ld;
        cv.src[3] = rope_q;    cv.dst[3] = w16 + W_RQ;  cv.n[3] = Hd*Ld;
        cv.src[4] = rope_k;    cv.dst[4] = w16 + W_RK;  cv.n[4] = Hd*Hd;
        cv.src[5] = o_proj;    cv.dst[5] = w16 + W_OPJ; cv.n[5] = Hd*Hd;
        cv.src[6] = sh_gate;   cv.dst[6] = w16 + W_SHG; cv.n[6] = Fd*Hd;
        cv.src[7] = sh_up;     cv.dst[7] = w16 + W_SHU; cv.n[7] = Fd*Hd;
        cv.src[8] = sh_down;   cv.dst[8] = w16 + W_SHD; cv.n[8] = Hd*Fd;
        cv.src[9] = ex_gate;   cv.dst[9] = w16 + W_EXG; cv.n[9] = Ed*Fd*Hd;
        cv.src[10]= ex_up;     cv.dst[10]= w16 + W_EXU; cv.n[10]= Ed*Fd*Hd;
        cv.src[11]= ex_down;   cv.dst[11]= w16 + W_EXD; cv.n[11]= Ed*Hd*Fd;
        int mx = Ed*Fd*Hd/8;
        cvt_kernel<<<dim3((mx + 255)/256, 12), 256>>>(cv);
    }

    zero_cnt_kernel<<<1, 32>>>();
    ln_kernel<<<BTd, 256>>>(x, ln1w, h16, nullptr);

    // qlat + kvlat (z=2), N=256
    {
        GA ga = {};
        ga.A[0] = h16;           ga.A[1] = h16;
        ga.B[0] = w16 + W_QPD;   ga.B[1] = w16 + W_KVD;
        ga.C[0] = qlat16;        ga.C[1] = kvlat16;
        ga.M = BTd; ga.N = Ld; ga.K = Hd; ga.lda = Hd; ga.ldb = Hd; ga.ldc = Ld;
        gemm4<0,false,true><<<dim3(Ld/256, BTd/128, 2), 256, SMEM>>>(ga);
    }
    // vT[b] = v_proj_u @ kvlat[b]^T  (M=Hd, N=Td, K=Ld)
    {
        GA ga = {};
        for (int b = 0; b < Bd; b++) {
            ga.A[b] = w16 + W_VPU;
            ga.B[b] = kvlat16 + (size_t)b*Td*Ld;
            ga.C[b] = vT16 + (size_t)b*Hd*Td;
        }
        ga.M = Hd; ga.N = Td; ga.K = Ld; ga.lda = Ld; ga.ldb = Ld; ga.ldc = Td;
        gemm4<0,false,true><<<dim3(Td/256, Hd/128, Bd), 256, SMEM>>>(ga);
    }
    // q_r = qlat @ rope_q.T
    {
        GA ga = {};
        ga.A[0] = qlat16; ga.B[0] = w16 + W_RQ; ga.C[0] = q16;
        ga.M = BTd; ga.N = Hd; ga.K = Ld; ga.lda = Ld; ga.ldb = Ld; ga.ldc = Hd;
        gemm4<0,false,true><<<dim3(Hd/256, BTd/128, 1), 256, SMEM>>>(ga);
    }
    // k_r = h @ rope_k.T
    {
        GA ga = {};
        ga.A[0] = h16; ga.B[0] = w16 + W_RK; ga.C[0] = k16;
        ga.M = BTd; ga.N = Hd; ga.K = Hd; ga.lda = Hd; ga.ldb = Hd; ga.ldc = Hd;
        gemm4<0,false,true><<<dim3(Hd/256, BTd/128, 1), 256, SMEM>>>(ga);
    }

    rope_kernel<<<BTd, 256>>>(q16, k16);

    // scores (z=2, causal)
    {
        GA ga = {};
        for (int b = 0; b < Bd; b++) {
            ga.A[b] = q16 + (size_t)b*Td*Hd;
            ga.B[b] = k16 + (size_t)b*Td*Hd;
            ga.C[b] = sc16 + (size_t)b*Td*Td;
        }
        ga.M = Td; ga.N = Td; ga.K = Hd; ga.lda = Hd; ga.ldb = Hd; ga.ldc = Td;
        gemm4<5,false,true><<<dim3(Td/256, Td/128, Bd), 256, SMEM>>>(ga);
    }
    softmax_kernel<<<dim3(Td, Bd), 256>>>(sc16);
    // PV (z=2): y[b] = attn[b] @ vT[b]^T
    {
        GA ga = {};
        for (int b = 0; b < Bd; b++) {
            ga.A[b] = sc16 + (size_t)b*Td*Td;
            ga.B[b] = vT16 + (size_t)b*Hd*Td;
            ga.C[b] = y16 + (size_t)b*Td*Hd;
        }
        ga.M = Td; ga.N = Hd; ga.K = Td; ga.lda = Td; ga.ldb = Td; ga.ldc = Hd;
        gemm4<0,false,true><<<dim3(Hd/256, Td/128, Bd), 256, SMEM>>>(ga);
    }
    // x1 = x + y @ o_proj.T  (fp32 out)
    {
        GA ga = {};
        ga.A[0] = y16; ga.B[0] = w16 + W_OPJ; ga.C[0] = x1; ga.aux[0] = x;
        ga.M = BTd; ga.N = Hd; ga.K = Hd; ga.lda = Hd; ga.ldb = Hd; ga.ldc = Hd;
        gemm4<3,false,false><<<dim3(Hd/256, BTd/128, 1), 256, SMEM>>>(ga);
    }

    // ---- MoE ----
    ln_kernel<<<BTd, 256>>>(x1, ln2w, h2_16, h2);
    router_kernel<<<BTd, 256>>>(h2, router_w, router_b);

    __half* shg = gbuf16 + (size_t)7 * ESL;
    // shared gate (silu)
    {
        GA ga = {};
        ga.A[0] = h2_16; ga.B[0] = w16 + W_SHG; ga.C[0] = shg;
        ga.M = BTd; ga.N = Fd; ga.K = Hd; ga.lda = Hd; ga.ldb = Hd; ga.ldc = Fd;
        gemm4<1,false,true><<<dim3(Fd/256, BTd/128, 1), 256, SMEM>>>(ga);
    }
    // shared up (in-place multiply)
    {
        GA ga = {};
        ga.A[0] = h2_16; ga.B[0] = w16 + W_SHU; ga.C[0] = shg; ga.aux[0] = shg;
        ga.M = BTd; ga.N = Fd; ga.K = Hd; ga.lda = Hd; ga.ldb = Hd; ga.ldc = Fd;
        gemm4<2,false,true><<<dim3(Fd/256, BTd/128, 1), 256, SMEM>>>(ga);
    }
    // shared down (fp32 out)
    {
        GA ga = {};
        ga.A[0] = shg; ga.B[0] = w16 + W_SHD; ga.C[0] = shb;
        ga.M = BTd; ga.N = Hd; ga.K = Fd; ga.lda = Fd; ga.ldb = Fd; ga.ldc = Hd;
        gemm4<0,false,false><<<dim3(Hd/256, BTd/128, 1), 256, SMEM>>>(ga);
    }

    // routed experts, all 7 batched per stage
    {
        GA ga = {};
        for (int e = 0; e < Ed; e++) {
            ga.A[e] = h2_16;
            ga.B[e] = w16 + W_EXG + (size_t)e * Fd * Hd;
            ga.C[e] = gbuf16 + (size_t)e * ESL;
        }
        ga.M = BTd; ga.N = Fd; ga.K = Hd; ga.lda = Hd; ga.ldb = Hd; ga.ldc = Fd;
        ga.gcnt = cnt; ga.gidx = gidx; ga.gwt = gwt; ga.gslot = gslot;
        gemm4<1,true,true><<<dim3(Fd/256, BTd/128, Ed), 256, SMEM>>>(ga);
    }
    {
        GA ga = {};
        for (int e = 0; e < Ed; e++) {
            ga.A[e] = h2_16;
            ga.B[e] = w16 + W_EXU + (size_t)e * Fd * Hd;
            ga.C[e] = gbuf16 + (size_t)e * ESL;
            ga.aux[e] = gbuf16 + (size_t)e * ESL;
        }
        ga.M = BTd; ga.N = Fd; ga.K = Hd; ga.lda = Hd; ga.ldb = Hd; ga.ldc = Fd;
        ga.gcnt = cnt; ga.gidx = gidx; ga.gwt = gwt; ga.gslot = gslot;
        gemm4<2,true,true><<<dim3(Fd/256, BTd/128, Ed), 256, SMEM>>>(ga);
    }
    {
        GA ga = {};
        for (int e = 0; e < Ed; e++) {
            ga.A[e] = gbuf16 + (size_t)e * ESL;
            ga.B[e] = w16 + W_EXD + (size_t)e * Hd * Fd;
        }
        ga.r0 = r0; ga.r1 = r1;
        ga.M = BTd; ga.N = Hd; ga.K = Fd; ga.lda = Fd; ga.ldb = Fd; ga.ldc = Hd;
        ga.gcnt = cnt; ga.gidx = gidx; ga.gwt = gwt; ga.gslot = gslot;
        gemm4<4,false,false><<<dim3(Hd/256, BTd/128, Ed), 256, SMEM>>>(ga);
    }

    final_add_kernel<<<(BTd * Hd) / 256, 256>>>(x1, shb, r0, r1, out);
}

// round 10
// speedup vs baseline: 2.7827x; 1.2519x over previous
#include <cuda_runtime.h>
#include <cuda_fp16.h>
#include <math.h>

#define Bd 2
#define Td 2048
#define Hd 1024
#define Ld 256
#define Fd 2048
#define Ed 7
#define BTd (Bd*Td)

// weight fp16 pool offsets (in halves)
#define W_QPD 0
#define W_KVD 262144
#define W_VPU 524288
#define W_RQ  786432
#define W_RK  1048576
#define W_OPJ 2097152
#define W_SHG 3145728
#define W_SHU 5242880
#define W_SHD 7340032
#define W_EXG 9437184
#define W_EXU 24117248
#define W_EXD 38797312
#define W_TOT 53477376

#define SMEM_BYTES 98304   // 4 stages x (A 8KB + B 16KB)

// ---------------- scratch (device globals; no allocation) ----------------
__device__ __half g_w16[W_TOT];
__device__ __half g_h16[BTd*Hd];
__device__ __half g_qlat16[BTd*Ld];
__device__ __half g_kvlat16[BTd*Ld];
__device__ __half g_vT16[BTd*Hd];      // [Bd][Hd][Td]
__device__ __half g_q16[BTd*Hd];
__device__ __half g_k16[BTd*Hd];
__device__ __half g_sc16[(size_t)Bd*Td*Td];
__device__ __half g_y16[BTd*Hd];
__device__ __half g_h2_16[BTd*Hd];
__device__ __half g_gbuf16[(size_t)8*BTd*Fd];  // 7 routed + 1 shared slices
__device__ float  g_h2[BTd*Hd];
__device__ float  g_x1[BTd*Hd];
__device__ float  g_shb[BTd*Hd];
__device__ float  g_r0[BTd*Hd];
__device__ float  g_r1[BTd*Hd];
__device__ int    g_cnt[Ed];
__device__ int    g_gidx[Ed*BTd];
__device__ float  g_gwt[Ed*BTd];
__device__ int    g_gslot[Ed*BTd];

// ---------------- fp16 helpers ----------------
__device__ __forceinline__ unsigned f2h2(float lo, float hi) {
    __half2 h = __floats2half2_rn(lo, hi);
    return *(unsigned*)&h;
}

// ---------------- weight conversion ----------------
struct CVT {
    const float* src[12];
    __half* dst[12];
    int n[12];
};

__global__ void cvt_kernel(CVT cv) {
    int seg = blockIdx.y;
    int idx = blockIdx.x * 256 + threadIdx.x;
    int n8 = cv.n[seg] >> 3;
    if (idx >= n8) return;
    const float4* s = (const float4*)cv.src[seg];
    float4 f1 = s[2*idx], f2 = s[2*idx+1];
    uint4 o;
    o.x = f2h2(f1.x, f1.y); o.y = f2h2(f1.z, f1.w);
    o.z = f2h2(f2.x, f2.y); o.w = f2h2(f2.z, f2.w);
    ((uint4*)cv.dst[seg])[idx] = o;
}

// ---------------- block reduce ----------------
template<bool DOMAX>
__device__ __forceinline__ float blockReduce(float v) {
    __shared__ float sh[8];
    __shared__ float res;
    int lane = threadIdx.x & 31, w = threadIdx.x >> 5;
    #pragma unroll
    for (int o = 16; o; o >>= 1) {
        float t = __shfl_xor_sync(0xffffffffu, v, o);
        v = DOMAX ? fmaxf(v, t) : v + t;
    }
    if (lane == 0) sh[w] = v;
    __syncthreads();
    if (w == 0) {
        v = (lane < (int)(blockDim.x >> 5)) ? sh[lane] : (DOMAX ? -3.4e38f : 0.f);
        #pragma unroll
        for (int o = 4; o; o >>= 1) {
            float t = __shfl_xor_sync(0xffffffffu, v, o);
            v = DOMAX ? fmaxf(v, t) : v + t;
        }
        if (lane == 0) res = v;
    }
    __syncthreads();
    return res;
}

// ---------------- layernorm (fp16 out, optional fp32 copy) ----------------
__global__ void ln_kernel(const float* __restrict__ x, const float* __restrict__ w,
                          __half* __restrict__ o16, float* __restrict__ o32) {
    int row = blockIdx.x;
    const float* xr = x + (size_t)row * Hd;
    int t = threadIdx.x;
    float v[4];
    float s = 0.f;
    #pragma unroll
    for (int i = 0; i < 4; i++) { v[i] = xr[t + 256*i]; s += v[i]; }
    s = blockReduce<false>(s);
    float mu = s * (1.f / Hd);
    float q = 0.f;
    #pragma unroll
    for (int i = 0; i < 4; i++) { float d = v[i] - mu; q += d * d; }
    q = blockReduce<false>(q);
    float rs = rsqrtf(q * (1.f / Hd) + 1e-5f);
    #pragma unroll
    for (int i = 0; i < 4; i++) {
        float val = (v[i] - mu) * rs * w[t + 256*i];
        o16[(size_t)row*Hd + t + 256*i] = __float2half_rn(val);
        if (o32) o32[(size_t)row*Hd + t + 256*i] = val;
    }
}

// ---------------- rope (fp16 in/out) ----------------
__global__ void rope_kernel(__half* __restrict__ q, __half* __restrict__ k) {
    int row = blockIdx.x;
    int t = row % Td;
    size_t base = (size_t)row * Hd;
    #pragma unroll
    for (int it = 0; it < 2; it++) {
        int p = threadIdx.x + 256 * it;
        double invf = exp(-(double)(2 * p) / 1024.0 * 9.210340371976184);
        float f = (float)t * (float)invf;
        float c = cosf(f), s = sinf(f);
        float q1 = __half2float(q[base + p]), q2 = __half2float(q[base + p + 512]);
        q[base + p]       = __float2half_rn(q1 * c - q2 * s);
        q[base + p + 512] = __float2half_rn(q2 * c + q1 * s);
        float k1 = __half2float(k[base + p]), k2 = __half2float(k[base + p + 512]);
        k[base + p]       = __float2half_rn(k1 * c - k2 * s);
        k[base + p + 512] = __float2half_rn(k2 * c + k1 * s);
    }
}

// ---------------- softmax (causal, fp16 in/out, fp32 math) ----------------
__global__ void softmax_kernel(__half* __restrict__ sc) {
    int b = blockIdx.y, i = blockIdx.x;
    __half* row = sc + ((size_t)b * Td + i) * Td;
    int t = threadIdx.x;
    int n = i + 1;
    float mx = -3.4e38f;
    for (int j = t; j < n; j += 256) mx = fmaxf(mx, __half2float(row[j]));
    mx = blockReduce<true>(mx);
    float s = 0.f;
    for (int j = t; j < n; j += 256) s += expf(__half2float(row[j]) - mx);
    s = blockReduce<false>(s);
    float inv = 1.f / s;
    for (int j = t; j < Td; j += 256) {
        float v = (j < n) ? expf(__half2float(row[j]) - mx) * inv : 0.f;
        row[j] = __float2half_rn(v);
    }
}

// ---------------- router + top2 gather lists ----------------
__global__ void zero_cnt_kernel() {
    if (threadIdx.x < Ed) g_cnt[threadIdx.x] = 0;
}

__global__ void router_kernel(const float* __restrict__ h2, const float* __restrict__ rw,
                              const float* __restrict__ rb) {
    int m = blockIdx.x;
    int w = threadIdx.x >> 5, lane = threadIdx.x & 31;
    __shared__ float probs[Ed];
    if (w < Ed) {
        const float* hv = h2 + (size_t)m * Hd;
        const float* wv = rw + (size_t)w * Hd;
        float s = 0.f;
        for (int j = lane; j < Hd; j += 32) s += hv[j] * wv[j];
        #pragma unroll
        for (int o = 16; o; o >>= 1) s += __shfl_xor_sync(0xffffffffu, s, o);
        if (lane == 0) probs[w] = 1.f / (1.f + expf(-(s + rb[w])));
    }
    __syncthreads();
    if (threadIdx.x == 0) {
        int e0 = 0; float p0 = probs[0];
        for (int e = 1; e < Ed; e++) if (probs[e] > p0) { p0 = probs[e]; e0 = e; }
        int e1 = -1; float p1 = -3.4e38f;
        for (int e = 0; e < Ed; e++) if (e != e0 && probs[e] > p1) { p1 = probs[e]; e1 = e; }
        int pos = atomicAdd(&g_cnt[e0], 1);
        g_gidx[e0*BTd + pos] = m; g_gwt[e0*BTd + pos] = p0; g_gslot[e0*BTd + pos] = 0;
        pos = atomicAdd(&g_cnt[e1], 1);
        g_gidx[e1*BTd + pos] = m; g_gwt[e1*BTd + pos] = p1; g_gslot[e1*BTd + pos] = 1;
    }
}

// ---------------- mma / ldmatrix / cp.async ----------------
__device__ __forceinline__ void mma_f16(float* d, const unsigned* a, const unsigned* b) {
    asm volatile(
        "mma.sync.aligned.m16n8k16.row.col.f32.f16.f16.f32 "
        "{%0,%1,%2,%3}, {%4,%5,%6,%7}, {%8,%9}, {%0,%1,%2,%3};"
        : "+f"(d[0]), "+f"(d[1]), "+f"(d[2]), "+f"(d[3])
        : "r"(a[0]), "r"(a[1]), "r"(a[2]), "r"(a[3]), "r"(b[0]), "r"(b[1]));
}

__device__ __forceinline__ void ldsm4(unsigned* r, unsigned addr) {
    asm volatile("ldmatrix.sync.aligned.m8n8.x4.shared.b16 {%0,%1,%2,%3}, [%4];"
        : "=r"(r[0]), "=r"(r[1]), "=r"(r[2]), "=r"(r[3]) : "r"(addr));
}

__device__ __forceinline__ void cpa16(unsigned dst, const void* src, unsigned sz) {
    asm volatile("cp.async.cg.shared.global [%0], [%1], 16, %2;"
        :: "r"(dst), "l"(src), "r"(sz) : "memory");
}

__device__ __forceinline__ unsigned smem_u32(const void* p) {
    unsigned a;
    asm("{ .reg .u64 t; cvta.to.shared.u64 t, %1; cvt.u32.u64 %0, t; }" : "=r"(a) : "l"(p));
    return a;
}

// crosswise swizzle: 16B chunk (row, c) -> byte offset within a tile buffer
__device__ __forceinline__ unsigned swz(int row, int c) {
    int line = row >> 1;
    return (unsigned)(line*128 + (((((row & 1) << 2) | c) ^ (line & 7)) << 4));
}

// per-z pointer tables for batched launches
struct GA {
    const void* A[8];
    const void* B[8];
    void*       C[8];
    const void* aux[8];
    float* r0; float* r1;
    int M, N, K, lda, ldb, ldc;
    const int* gcnt; const int* gidx; const float* gwt; const int* gslot;
};

// ---------------- fp16 mma GEMM, 128x256 tile, KT=32, cp.async 4-stage ----
// C = A @ B^T, A [M,K] half, B [N,K] half, row-major.
// Smem per stage: A 128x64B + B 256x64B (crosswise-swizzled 16B chunks).
// Fragments via ldmatrix.x4. MODE 0: C=v  1: silu  2: C=v*aux  3: C=v+aux(f32)
//      4: scatter w*v to (r0|r1)[gidx] (f32)   5: C=v/32, causal tile skip
template<int MODE, bool GATHER, bool OHALF>
__global__ void __launch_bounds__(256) gemm5(GA ga) {
    const int z = blockIdx.z;
    const int bm = blockIdx.y * 128;
    const int bn = blockIdx.x * 256;
    if (MODE == 5 && bn > bm + 127) return;

    int Meff = ga.M;
    const int* gidx = nullptr; const float* gwt = nullptr; const int* gslot = nullptr;
    if (GATHER || MODE == 4) {
        Meff = ga.gcnt[z];
        gidx = ga.gidx + z * BTd;
        gwt  = ga.gwt  + z * BTd;
        gslot= ga.gslot+ z * BTd;
    }
    if (bm >= Meff) return;

    const __half* __restrict__ A  = (const __half*)ga.A[z];
    const __half* __restrict__ Bm = (const __half*)ga.B[z];
    const int K = ga.K, lda = ga.lda, ldb = ga.ldb, ldc = ga.ldc;

    extern __shared__ __align__(16) unsigned char smraw[];
    const unsigned sbase = smem_u32(smraw);

    const int tid = threadIdx.x;
    const int lane = tid & 31, wid = tid >> 5;
    const int wm = wid & 1, wn = wid >> 1;      // 2 x 4 warps, 64x64 each
    const int gid = lane >> 2, tig = lane & 3;

    // ---- cp.async source setup (chunk c = tid&3 covers halves c*8..c*8+7) ----
    const int tid4 = tid >> 2, cA = tid & 3;
    const __half* srcA[2]; unsigned szA[2]; unsigned dA[2];
    #pragma unroll
    for (int j = 0; j < 2; j++) {
        int lr = tid4 + 64*j;
        int gr = bm + lr;
        bool val = gr < Meff;
        int sr = val ? (GATHER ? gidx[gr] : gr) : 0;
        srcA[j] = A + (size_t)sr * lda + cA * 8;
        szA[j] = val ? 16u : 0u;
        dA[j] = swz(lr, cA);
    }
    const __half* srcB[4]; unsigned dB[4];
    #pragma unroll
    for (int j = 0; j < 4; j++) {
        int lr = tid4 + 64*j;
        srcB[j] = Bm + (size_t)(bn + lr) * ldb + cA * 8;
        dB[j] = swz(lr, cA);
    }

    // ---- ldmatrix per-lane offsets (stage-relative) ----
    unsigned offA[4][2], offB[4][2];
    #pragma unroll
    for (int mt = 0; mt < 4; mt++) {
        int row = wm*64 + mt*16 + ((lane >> 3) & 1)*8 + (lane & 7);
        #pragma unroll
        for (int g = 0; g < 2; g++)
            offA[mt][g] = swz(row, g*2 + ((lane >> 4) & 1));
    }
    #pragma unroll
    for (int q = 0; q < 4; q++) {
        int row = wn*64 + q*16 + ((lane >> 4) & 1)*8 + (lane & 7);
        #pragma unroll
        for (int g = 0; g < 2; g++)
            offB[q][g] = swz(row, g*2 + ((lane >> 3) & 1));
    }

    float acc[4][8][4];
    #pragma unroll
    for (int i = 0; i < 4; i++)
        #pragma unroll
        for (int j = 0; j < 8; j++)
            #pragma unroll
            for (int l = 0; l < 4; l++) acc[i][j][l] = 0.f;

    auto issue = [&](int it) {
        int s = it & 3;
        unsigned ab = sbase + s*24576;
        unsigned bb = ab + 8192;
        size_t ko = (size_t)it * 32;
        cpa16(ab + dA[0], srcA[0] + ko, szA[0]);
        cpa16(ab + dA[1], srcA[1] + ko, szA[1]);
        #pragma unroll
        for (int j = 0; j < 4; j++)
            cpa16(bb + dB[j], srcB[j] + ko, 16u);
    };

    const int NT = K / 32;
    issue(0); asm volatile("cp.async.commit_group;" ::: "memory");
    issue(1); asm volatile("cp.async.commit_group;" ::: "memory");
    issue(2); asm volatile("cp.async.commit_group;" ::: "memory");

    for (int it = 0; it < NT; it++) {
        asm volatile("cp.async.wait_group 2;" ::: "memory");
        __syncthreads();
        if (it + 3 < NT) issue(it + 3);
        asm volatile("cp.async.commit_group;" ::: "memory");

        unsigned ab = sbase + (it & 3)*24576;
        unsigned bb = ab + 8192;
        #pragma unroll
        for (int g = 0; g < 2; g++) {
            unsigned a[4][4], b[4][4];
            #pragma unroll
            for (int mt = 0; mt < 4; mt++) ldsm4(a[mt], ab + offA[mt][g]);
            #pragma unroll
            for (int q = 0; q < 4; q++) ldsm4(b[q], bb + offB[q][g]);
            #pragma unroll
            for (int mt = 0; mt < 4; mt++)
                #pragma unroll
                for (int nt = 0; nt < 8; nt++)
                    mma_f16(acc[mt][nt], a[mt], &b[nt >> 1][(nt & 1)*2]);
        }
    }

    // ---- epilogue ----
    #pragma unroll
    for (int mt = 0; mt < 4; mt++) {
        #pragma unroll
        for (int i2 = 0; i2 < 2; i2++) {
            int gm = bm + wm*64 + mt*16 + gid + i2*8;
            if (gm >= Meff) continue;
            int trow = 0; float wgt = 0.f; float* Ct = nullptr;
            if (MODE == 4) { trow = gidx[gm]; wgt = gwt[gm]; Ct = gslot[gm] ? ga.r1 : ga.r0; }
            #pragma unroll
            for (int nt = 0; nt < 8; nt++) {
                int gn = bn + wn*64 + nt*8 + tig*2;
                float v0 = acc[mt][nt][i2*2 + 0];
                float v1 = acc[mt][nt][i2*2 + 1];
                size_t o = (size_t)gm * ldc + gn;
                if (MODE == 1) {
                    v0 = v0 / (1.f + expf(-v0));
                    v1 = v1 / (1.f + expf(-v1));
                } else if (MODE == 2) {
                    __half2 a2 = *(const __half2*)((const __half*)ga.aux[z] + o);
                    v0 *= __low2float(a2); v1 *= __high2float(a2);
                } else if (MODE == 3) {
                    float2 a2 = *(const float2*)((const float*)ga.aux[z] + o);
                    v0 += a2.x; v1 += a2.y;
                } else if (MODE == 5) {
                    v0 *= 0.03125f; v1 *= 0.03125f;
                }
                if (MODE == 4) {
                    float2 w2; w2.x = wgt*v0; w2.y = wgt*v1;
                    *(float2*)(Ct + (size_t)trow * ldc + gn) = w2;
                } else if (OHALF) {
                    *(__half2*)((__half*)ga.C[z] + o) = __floats2half2_rn(v0, v1);
                } else {
                    float2 w2; w2.x = v0; w2.y = v1;
                    *(float2*)((float*)ga.C[z] + o) = w2;
                }
            }
        }
    }
}

// ---------------- final add ----------------
__global__ void final_add_kernel(const float* __restrict__ a, const float* __restrict__ b,
                                 const float* __restrict__ c, const float* __restrict__ d,
                                 float* __restrict__ out) {
    size_t i = (size_t)blockIdx.x * blockDim.x + threadIdx.x;
    out[i] = a[i] + b[i] + c[i] + d[i];
}

// ---------------- launch ----------------
extern "C" void kernel_launch(void* const* d_in, const int* in_sizes, int n_in,
                              void* d_out, int out_size) {
    (void)in_sizes; (void)n_in; (void)out_size;
    const float* x         = (const float*)d_in[0];
    const float* ln1w      = (const float*)d_in[1];
    const float* ln2w      = (const float*)d_in[2];
    const float* kv_proj_d = (const float*)d_in[3];
    const float* q_proj_d  = (const float*)d_in[4];
    const float* v_proj_u  = (const float*)d_in[7];
    const float* rope_k    = (const float*)d_in[8];
    const float* rope_q    = (const float*)d_in[9];
    const float* o_proj    = (const float*)d_in[10];
    const float* router_w  = (const float*)d_in[11];
    const float* router_b  = (const float*)d_in[12];
    const float* sh_gate   = (const float*)d_in[13];
    const float* sh_up     = (const float*)d_in[14];
    const float* sh_down   = (const float*)d_in[15];
    const float* ex_gate   = (const float*)d_in[16];
    const float* ex_up     = (const float*)d_in[17];
    const float* ex_down   = (const float*)d_in[18];
    float* out = (float*)d_out;

    __half *w16,*h16,*qlat16,*kvlat16,*vT16,*q16,*k16,*sc16,*y16,*h2_16,*gbuf16;
    float *h2,*x1,*shb,*r0,*r1,*gwt;
    int *cnt,*gidx,*gslot;
    cudaGetSymbolAddress((void**)&w16, g_w16);
    cudaGetSymbolAddress((void**)&h16, g_h16);
    cudaGetSymbolAddress((void**)&qlat16, g_qlat16);
    cudaGetSymbolAddress((void**)&kvlat16, g_kvlat16);
    cudaGetSymbolAddress((void**)&vT16, g_vT16);
    cudaGetSymbolAddress((void**)&q16, g_q16);
    cudaGetSymbolAddress((void**)&k16, g_k16);
    cudaGetSymbolAddress((void**)&sc16, g_sc16);
    cudaGetSymbolAddress((void**)&y16, g_y16);
    cudaGetSymbolAddress((void**)&h2_16, g_h2_16);
    cudaGetSymbolAddress((void**)&gbuf16, g_gbuf16);
    cudaGetSymbolAddress((void**)&h2, g_h2);
    cudaGetSymbolAddress((void**)&x1, g_x1);
    cudaGetSymbolAddress((void**)&shb, g_shb);
    cudaGetSymbolAddress((void**)&r0, g_r0);
    cudaGetSymbolAddress((void**)&r1, g_r1);
    cudaGetSymbolAddress((void**)&cnt, g_cnt);
    cudaGetSymbolAddress((void**)&gidx, g_gidx);
    cudaGetSymbolAddress((void**)&gwt, g_gwt);
    cudaGetSymbolAddress((void**)&gslot, g_gslot);

    const size_t ESL = (size_t)BTd * Fd;   // per-expert gbuf16 slice

    // raise dynamic smem limit (idempotent)
    cudaFuncSetAttribute(gemm5<0,false,true>,  cudaFuncAttributeMaxDynamicSharedMemorySize, SMEM_BYTES);
    cudaFuncSetAttribute(gemm5<5,false,true>,  cudaFuncAttributeMaxDynamicSharedMemorySize, SMEM_BYTES);
    cudaFuncSetAttribute(gemm5<3,false,false>, cudaFuncAttributeMaxDynamicSharedMemorySize, SMEM_BYTES);
    cudaFuncSetAttribute(gemm5<1,false,true>,  cudaFuncAttributeMaxDynamicSharedMemorySize, SMEM_BYTES);
    cudaFuncSetAttribute(gemm5<2,false,true>,  cudaFuncAttributeMaxDynamicSharedMemorySize, SMEM_BYTES);
    cudaFuncSetAttribute(gemm5<0,false,false>, cudaFuncAttributeMaxDynamicSharedMemorySize, SMEM_BYTES);
    cudaFuncSetAttribute(gemm5<1,true,true>,   cudaFuncAttributeMaxDynamicSharedMemorySize, SMEM_BYTES);
    cudaFuncSetAttribute(gemm5<2,true,true>,   cudaFuncAttributeMaxDynamicSharedMemorySize, SMEM_BYTES);
    cudaFuncSetAttribute(gemm5<4,false,false>, cudaFuncAttributeMaxDynamicSharedMemorySize, SMEM_BYTES);

    // ---- weight conversion (fp32 -> fp16 pool) ----
    {
        CVT cv;
        cv.src[0] = q_proj_d;  cv.dst[0] = w16 + W_QPD; cv.n[0] = Ld*Hd;
        cv.src[1] = kv_proj_d; cv.dst[1] = w16 + W_KVD; cv.n[1] = Ld*Hd;
        cv.src[2] = v_proj_u;  cv.dst[2] = w16 + W_VPU; cv.n[2] = Hd*Ld;
        cv.src[3] = rope_q;    cv.dst[3] = w16 + W_RQ;  cv.n[3] = Hd*Ld;
        cv.src[4] = rope_k;    cv.dst[4] = w16 + W_RK;  cv.n[4] = Hd*Hd;
        cv.src[5] = o_proj;    cv.dst[5] = w16 + W_OPJ; cv.n[5] = Hd*Hd;
        cv.src[6] = sh_gate;   cv.dst[6] = w16 + W_SHG; cv.n[6] = Fd*Hd;
        cv.src[7] = sh_up;     cv.dst[7] = w16 + W_SHU; cv.n[7] = Fd*Hd;
        cv.src[8] = sh_down;   cv.dst[8] = w16 + W_SHD; cv.n[8] = Hd*Fd;
        cv.src[9] = ex_gate;   cv.dst[9] = w16 + W_EXG; cv.n[9] = Ed*Fd*Hd;
        cv.src[10]= ex_up;     cv.dst[10]= w16 + W_EXU; cv.n[10]= Ed*Fd*Hd;
        cv.src[11]= ex_down;   cv.dst[11]= w16 + W_EXD; cv.n[11]= Ed*Hd*Fd;
        int mx = Ed*Fd*Hd/8;
        cvt_kernel<<<dim3((mx + 255)/256, 12), 256>>>(cv);
    }

    zero_cnt_kernel<<<1, 32>>>();
    ln_kernel<<<BTd, 256>>>(x, ln1w, h16, nullptr);

    // qlat + kvlat (z=2), N=256
    {
        GA ga = {};
        ga.A[0] = h16;           ga.A[1] = h16;
        ga.B[0] = w16 + W_QPD;   ga.B[1] = w16 + W_KVD;
        ga.C[0] = qlat16;        ga.C[1] = kvlat16;
        ga.M = BTd; ga.N = Ld; ga.K = Hd; ga.lda = Hd; ga.ldb = Hd; ga.ldc = Ld;
        gemm5<0,false,true><<<dim3(Ld/256, BTd/128, 2), 256, SMEM_BYTES>>>(ga);
    }
    // vT[b] = v_proj_u @ kvlat[b]^T  (M=Hd, N=Td, K=Ld)
    {
        GA ga = {};
        for (int b = 0; b < Bd; b++) {
            ga.A[b] = w16 + W_VPU;
            ga.B[b] = kvlat16 + (size_t)b*Td*Ld;
            ga.C[b] = vT16 + (size_t)b*Hd*Td;
        }
        ga.M = Hd; ga.N = Td; ga.K = Ld; ga.lda = Ld; ga.ldb = Ld; ga.ldc = Td;
        gemm5<0,false,true><<<dim3(Td/256, Hd/128, Bd), 256, SMEM_BYTES>>>(ga);
    }
    // q_r = qlat @ rope_q.T
    {
        GA ga = {};
        ga.A[0] = qlat16; ga.B[0] = w16 + W_RQ; ga.C[0] = q16;
        ga.M = BTd; ga.N = Hd; ga.K = Ld; ga.lda = Ld; ga.ldb = Ld; ga.ldc = Hd;
        gemm5<0,false,true><<<dim3(Hd/256, BTd/128, 1), 256, SMEM_BYTES>>>(ga);
    }
    // k_r = h @ rope_k.T
    {
        GA ga = {};
        ga.A[0] = h16; ga.B[0] = w16 + W_RK; ga.C[0] = k16;
        ga.M = BTd; ga.N = Hd; ga.K = Hd; ga.lda = Hd; ga.ldb = Hd; ga.ldc = Hd;
        gemm5<0,false,true><<<dim3(Hd/256, BTd/128, 1), 256, SMEM_BYTES>>>(ga);
    }

    rope_kernel<<<BTd, 256>>>(q16, k16);

    // scores (z=2, causal)
    {
        GA ga = {};
        for (int b = 0; b < Bd; b++) {
            ga.A[b] = q16 + (size_t)b*Td*Hd;
            ga.B[b] = k16 + (size_t)b*Td*Hd;
            ga.C[b] = sc16 + (size_t)b*Td*Td;
        }
        ga.M = Td; ga.N = Td; ga.K = Hd; ga.lda = Hd; ga.ldb = Hd; ga.ldc = Td;
        gemm5<5,false,true><<<dim3(Td/256, Td/128, Bd), 256, SMEM_BYTES>>>(ga);
    }
    softmax_kernel<<<dim3(Td, Bd), 256>>>(sc16);
    // PV (z=2): y[b] = attn[b] @ vT[b]^T
    {
        GA ga = {};
        for (int b = 0; b < Bd; b++) {
            ga.A[b] = sc16 + (size_t)b*Td*Td;
            ga.B[b] = vT16 + (size_t)b*Hd*Td;
            ga.C[b] = y16 + (size_t)b*Td*Hd;
        }
        ga.M = Td; ga.N = Hd; ga.K = Td; ga.lda = Td; ga.ldb = Td; ga.ldc = Hd;
        gemm5<0,false,true><<<dim3(Hd/256, Td/128, Bd), 256, SMEM_BYTES>>>(ga);
    }
    // x1 = x + y @ o_proj.T  (fp32 out)
    {
        GA ga = {};
        ga.A[0] = y16; ga.B[0] = w16 + W_OPJ; ga.C[0] = x1; ga.aux[0] = x;
        ga.M = BTd; ga.N = Hd; ga.K = Hd; ga.lda = Hd; ga.ldb = Hd; ga.ldc = Hd;
        gemm5<3,false,false><<<dim3(Hd/256, BTd/128, 1), 256, SMEM_BYTES>>>(ga);
    }

    // ---- MoE ----
    ln_kernel<<<BTd, 256>>>(x1, ln2w, h2_16, h2);
    router_kernel<<<BTd, 256>>>(h2, router_w, router_b);

    __half* shg = gbuf16 + (size_t)7 * ESL;
    // shared gate (silu)
    {
        GA ga = {};
        ga.A[0] = h2_16; ga.B[0] = w16 + W_SHG; ga.C[0] = shg;
        ga.M = BTd; ga.N = Fd; ga.K = Hd; ga.lda = Hd; ga.ldb = Hd; ga.ldc = Fd;
        gemm5<1,false,true><<<dim3(Fd/256, BTd/128, 1), 256, SMEM_BYTES>>>(ga);
    }
    // shared up (in-place multiply)
    {
        GA ga = {};
        ga.A[0] = h2_16; ga.B[0] = w16 + W_SHU; ga.C[0] = shg; ga.aux[0] = shg;
        ga.M = BTd; ga.N = Fd; ga.K = Hd; ga.lda = Hd; ga.ldb = Hd; ga.ldc = Fd;
        gemm5<2,false,true><<<dim3(Fd/256, BTd/128, 1), 256, SMEM_BYTES>>>(ga);
    }
    // shared down (fp32 out)
    {
        GA ga = {};
        ga.A[0] = shg; ga.B[0] = w16 + W_SHD; ga.C[0] = shb;
        ga.M = BTd; ga.N = Hd; ga.K = Fd; ga.lda = Fd; ga.ldb = Fd; ga.ldc = Hd;
        gemm5<0,false,false><<<dim3(Hd/256, BTd/128, 1), 256, SMEM_BYTES>>>(ga);
    }

    // routed experts, all 7 batched per stage
    {
        GA ga = {};
        for (int e = 0; e < Ed; e++) {
            ga.A[e] = h2_16;
            ga.B[e] = w16 + W_EXG + (size_t)e * Fd * Hd;
            ga.C[e] = gbuf16 + (size_t)e * ESL;
        }
        ga.M = BTd; ga.N = Fd; ga.K = Hd; ga.lda = Hd; ga.ldb = Hd; ga.ldc = Fd;
        ga.gcnt = cnt; ga.gidx = gidx; ga.gwt = gwt; ga.gslot = gslot;
        gemm5<1,true,true><<<dim3(Fd/256, BTd/128, Ed), 256, SMEM_BYTES>>>(ga);
    }
    {
        GA ga = {};
        for (int e = 0; e < Ed; e++) {
            ga.A[e] = h2_16;
            ga.B[e] = w16 + W_EXU + (size_t)e * Fd * Hd;
            ga.C[e] = gbuf16 + (size_t)e * ESL;
            ga.aux[e] = gbuf16 + (size_t)e * ESL;
        }
        ga.M = BTd; ga.N = Fd; ga.K = Hd; ga.lda = Hd; ga.ldb = Hd; ga.ldc = Fd;
        ga.gcnt = cnt; ga.gidx = gidx; ga.gwt = gwt; ga.gslot = gslot;
        gemm5<2,true,true><<<dim3(Fd/256, BTd/128, Ed), 256, SMEM_BYTES>>>(ga);
    }
    {
        GA ga = {};
        for (int e = 0; e < Ed; e++) {
            ga.A[e] = gbuf16 + (size_t)e * ESL;
            ga.B[e] = w16 + W_EXD + (size_t)e * Hd * Fd;
        }
        ga.r0 = r0; ga.r1 = r1;
        ga.M = BTd; ga.N = Hd; ga.K = Fd; ga.lda = Fd; ga.ldb = Fd; ga.ldc = Hd;
        ga.gcnt = cnt; ga.gidx = gidx; ga.gwt = gwt; ga.gslot = gslot;
        gemm5<4,false,false><<<dim3(Hd/256, BTd/128, Ed), 256, SMEM_BYTES>>>(ga);
    }

    final_add_kernel<<<(BTd * Hd) / 256, 256>>>(x1, shb, r0, r1, out);
}

// round 11
// speedup vs baseline: 3.1377x; 1.1276x over previous
#include <cuda_runtime.h>
#include <cuda_fp16.h>
#include <math.h>

#define Bd 2
#define Td 2048
#define Hd 1024
#define Ld 256
#define Fd 2048
#define Ed 7
#define BTd (Bd*Td)

// weight fp16 pool offsets (in halves)
#define W_QPD 0
#define W_KVD 262144
#define W_VPU 524288
#define W_RQ  786432
#define W_RK  1048576
#define W_OPJ 2097152
#define W_SHG 3145728
#define W_SHU 5242880
#define W_SHD 7340032
#define W_EXG 9437184
#define W_EXU 24117248
#define W_EXD 38797312
#define W_TOT 53477376

#define SMEM_BYTES 98304   // 4 stages x (A 8KB + B 16KB)

// ---------------- scratch (device globals; no allocation) ----------------
__device__ __half g_w16[W_TOT];
__device__ __half g_h16[BTd*Hd];
__device__ __half g_qlat16[BTd*Ld];
__device__ __half g_kvlat16[BTd*Ld];
__device__ __half g_vT16[BTd*Hd];      // [Bd][Hd][Td]
__device__ __half g_q16[BTd*Hd];
__device__ __half g_k16[BTd*Hd];
__device__ __half g_sc16[(size_t)Bd*Td*Td];
__device__ __half g_y16[BTd*Hd];
__device__ __half g_h2_16[BTd*Hd];
__device__ __half g_gbuf16[(size_t)8*BTd*Fd];  // 7 routed + 1 shared slices
__device__ float  g_h2[BTd*Hd];
__device__ float  g_x1[BTd*Hd];
__device__ float  g_shb[BTd*Hd];
__device__ float  g_r0[BTd*Hd];
__device__ float  g_r1[BTd*Hd];
__device__ int    g_cnt[Ed];
__device__ int    g_gidx[Ed*BTd];
__device__ float  g_gwt[Ed*BTd];
__device__ int    g_gslot[Ed*BTd];

// ---------------- fp16 helpers ----------------
__device__ __forceinline__ unsigned f2h2(float lo, float hi) {
    __half2 h = __floats2half2_rn(lo, hi);
    return *(unsigned*)&h;
}

// ---------------- weight conversion ----------------
struct CVT {
    const float* src[12];
    __half* dst[12];
    int n[12];
};

__global__ void cvt_kernel(CVT cv) {
    int seg = blockIdx.y;
    int idx = blockIdx.x * 256 + threadIdx.x;
    int n8 = cv.n[seg] >> 3;
    if (idx >= n8) return;
    const float4* s = (const float4*)cv.src[seg];
    float4 f1 = s[2*idx], f2 = s[2*idx+1];
    uint4 o;
    o.x = f2h2(f1.x, f1.y); o.y = f2h2(f1.z, f1.w);
    o.z = f2h2(f2.x, f2.y); o.w = f2h2(f2.z, f2.w);
    ((uint4*)cv.dst[seg])[idx] = o;
}

// ---------------- block reduce ----------------
template<bool DOMAX>
__device__ __forceinline__ float blockReduce(float v) {
    __shared__ float sh[8];
    __shared__ float res;
    int lane = threadIdx.x & 31, w = threadIdx.x >> 5;
    #pragma unroll
    for (int o = 16; o; o >>= 1) {
        float t = __shfl_xor_sync(0xffffffffu, v, o);
        v = DOMAX ? fmaxf(v, t) : v + t;
    }
    if (lane == 0) sh[w] = v;
    __syncthreads();
    if (w == 0) {
        v = (lane < (int)(blockDim.x >> 5)) ? sh[lane] : (DOMAX ? -3.4e38f : 0.f);
        #pragma unroll
        for (int o = 4; o; o >>= 1) {
            float t = __shfl_xor_sync(0xffffffffu, v, o);
            v = DOMAX ? fmaxf(v, t) : v + t;
        }
        if (lane == 0) res = v;
    }
    __syncthreads();
    return res;
}

// ---------------- layernorm (fp16 out, optional fp32 copy) ----------------
__global__ void ln_kernel(const float* __restrict__ x, const float* __restrict__ w,
                          __half* __restrict__ o16, float* __restrict__ o32) {
    int row = blockIdx.x;
    const float* xr = x + (size_t)row * Hd;
    int t = threadIdx.x;
    float v[4];
    float s = 0.f;
    #pragma unroll
    for (int i = 0; i < 4; i++) { v[i] = xr[t + 256*i]; s += v[i]; }
    s = blockReduce<false>(s);
    float mu = s * (1.f / Hd);
    float q = 0.f;
    #pragma unroll
    for (int i = 0; i < 4; i++) { float d = v[i] - mu; q += d * d; }
    q = blockReduce<false>(q);
    float rs = rsqrtf(q * (1.f / Hd) + 1e-5f);
    #pragma unroll
    for (int i = 0; i < 4; i++) {
        float val = (v[i] - mu) * rs * w[t + 256*i];
        o16[(size_t)row*Hd + t + 256*i] = __float2half_rn(val);
        if (o32) o32[(size_t)row*Hd + t + 256*i] = val;
    }
}

// ---------------- rope (fp16 in/out) ----------------
__global__ void rope_kernel(__half* __restrict__ q, __half* __restrict__ k) {
    int row = blockIdx.x;
    int t = row % Td;
    size_t base = (size_t)row * Hd;
    #pragma unroll
    for (int it = 0; it < 2; it++) {
        int p = threadIdx.x + 256 * it;
        double invf = exp(-(double)(2 * p) / 1024.0 * 9.210340371976184);
        float f = (float)t * (float)invf;
        float c = cosf(f), s = sinf(f);
        float q1 = __half2float(q[base + p]), q2 = __half2float(q[base + p + 512]);
        q[base + p]       = __float2half_rn(q1 * c - q2 * s);
        q[base + p + 512] = __float2half_rn(q2 * c + q1 * s);
        float k1 = __half2float(k[base + p]), k2 = __half2float(k[base + p + 512]);
        k[base + p]       = __float2half_rn(k1 * c - k2 * s);
        k[base + p + 512] = __float2half_rn(k2 * c + k1 * s);
    }
}

// ---------------- softmax (causal, fp16 in/out, fp32 math) ----------------
__global__ void softmax_kernel(__half* __restrict__ sc) {
    int b = blockIdx.y, i = blockIdx.x;
    __half* row = sc + ((size_t)b * Td + i) * Td;
    int t = threadIdx.x;
    int n = i + 1;
    float mx = -3.4e38f;
    for (int j = t; j < n; j += 256) mx = fmaxf(mx, __half2float(row[j]));
    mx = blockReduce<true>(mx);
    float s = 0.f;
    for (int j = t; j < n; j += 256) s += expf(__half2float(row[j]) - mx);
    s = blockReduce<false>(s);
    float inv = 1.f / s;
    for (int j = t; j < Td; j += 256) {
        float v = (j < n) ? expf(__half2float(row[j]) - mx) * inv : 0.f;
        row[j] = __float2half_rn(v);
    }
}

// ---------------- router + top2 gather lists ----------------
__global__ void zero_cnt_kernel() {
    if (threadIdx.x < Ed) g_cnt[threadIdx.x] = 0;
}

__global__ void router_kernel(const float* __restrict__ h2, const float* __restrict__ rw,
                              const float* __restrict__ rb) {
    int m = blockIdx.x;
    int w = threadIdx.x >> 5, lane = threadIdx.x & 31;
    __shared__ float probs[Ed];
    if (w < Ed) {
        const float* hv = h2 + (size_t)m * Hd;
        const float* wv = rw + (size_t)w * Hd;
        float s = 0.f;
        for (int j = lane; j < Hd; j += 32) s += hv[j] * wv[j];
        #pragma unroll
        for (int o = 16; o; o >>= 1) s += __shfl_xor_sync(0xffffffffu, s, o);
        if (lane == 0) probs[w] = 1.f / (1.f + expf(-(s + rb[w])));
    }
    __syncthreads();
    if (threadIdx.x == 0) {
        int e0 = 0; float p0 = probs[0];
        for (int e = 1; e < Ed; e++) if (probs[e] > p0) { p0 = probs[e]; e0 = e; }
        int e1 = -1; float p1 = -3.4e38f;
        for (int e = 0; e < Ed; e++) if (e != e0 && probs[e] > p1) { p1 = probs[e]; e1 = e; }
        int pos = atomicAdd(&g_cnt[e0], 1);
        g_gidx[e0*BTd + pos] = m; g_gwt[e0*BTd + pos] = p0; g_gslot[e0*BTd + pos] = 0;
        pos = atomicAdd(&g_cnt[e1], 1);
        g_gidx[e1*BTd + pos] = m; g_gwt[e1*BTd + pos] = p1; g_gslot[e1*BTd + pos] = 1;
    }
}

// ---------------- mma / ldmatrix / cp.async ----------------
__device__ __forceinline__ void mma_f16(float* d, const unsigned* a, const unsigned* b) {
    asm volatile(
        "mma.sync.aligned.m16n8k16.row.col.f32.f16.f16.f32 "
        "{%0,%1,%2,%3}, {%4,%5,%6,%7}, {%8,%9}, {%0,%1,%2,%3};"
        : "+f"(d[0]), "+f"(d[1]), "+f"(d[2]), "+f"(d[3])
        : "r"(a[0]), "r"(a[1]), "r"(a[2]), "r"(a[3]), "r"(b[0]), "r"(b[1]));
}

__device__ __forceinline__ void ldsm4(unsigned* r, unsigned addr) {
    asm volatile("ldmatrix.sync.aligned.m8n8.x4.shared.b16 {%0,%1,%2,%3}, [%4];"
        : "=r"(r[0]), "=r"(r[1]), "=r"(r[2]), "=r"(r[3]) : "r"(addr));
}

__device__ __forceinline__ void cpa16(unsigned dst, const void* src, unsigned sz) {
    asm volatile("cp.async.cg.shared.global [%0], [%1], 16, %2;"
        :: "r"(dst), "l"(src), "r"(sz) : "memory");
}

__device__ __forceinline__ unsigned smem_u32(const void* p) {
    unsigned a;
    asm("{ .reg .u64 t; cvta.to.shared.u64 t, %1; cvt.u32.u64 %0, t; }" : "=r"(a) : "l"(p));
    return a;
}

// crosswise swizzle: 16B chunk (row, c) -> byte offset within a tile buffer
__device__ __forceinline__ unsigned swz(int row, int c) {
    int line = row >> 1;
    return (unsigned)(line*128 + (((((row & 1) << 2) | c) ^ (line & 7)) << 4));
}

// per-z pointer tables for batched launches
struct GA {
    const void* A[8];
    const void* B[8];
    void*       C[8];
    const void* aux[8];
    float* r0; float* r1;
    int M, N, K, lda, ldb, ldc;
    const int* gcnt; const int* gidx; const float* gwt; const int* gslot;
};

// ---------------- fp16 mma GEMM, 128x256 tile, 512 thr, cp.async 4-stage --
// C = A @ B^T, A [M,K] half, B [N,K] half, row-major.
// 16 warps, 4x4 grid, warp tile 32x64. Smem per stage: A 8KB + B 16KB
// (crosswise-swizzled 16B chunks). Fragments via ldmatrix.x4.
// MODE 0: C=v  1: silu  2: C=v*aux  3: C=v+aux(f32)
//      4: scatter w*v to (r0|r1)[gidx] (f32)   5: C=v/32, causal tile skip
template<int MODE, bool GATHER, bool OHALF>
__global__ void __launch_bounds__(512) gemm6(GA ga) {
    const int z = blockIdx.z;
    const int bm = blockIdx.y * 128;
    const int bn = blockIdx.x * 256;
    if (MODE == 5 && bn > bm + 127) return;

    int Meff = ga.M;
    const int* gidx = nullptr; const float* gwt = nullptr; const int* gslot = nullptr;
    if (GATHER || MODE == 4) {
        Meff = ga.gcnt[z];
        gidx = ga.gidx + z * BTd;
        gwt  = ga.gwt  + z * BTd;
        gslot= ga.gslot+ z * BTd;
    }
    if (bm >= Meff) return;

    const __half* __restrict__ A  = (const __half*)ga.A[z];
    const __half* __restrict__ Bm = (const __half*)ga.B[z];
    const int K = ga.K, lda = ga.lda, ldb = ga.ldb, ldc = ga.ldc;

    extern __shared__ __align__(16) unsigned char smraw[];
    const unsigned sbase = smem_u32(smraw);

    const int tid = threadIdx.x;
    const int lane = tid & 31, wid = tid >> 5;
    const int wm = wid & 3, wn = wid >> 2;      // 4 x 4 warps, 32x64 each
    const int gid = lane >> 2, tig = lane & 3;

    // ---- cp.async source setup (chunk c = tid&3 covers halves c*8..c*8+7) ----
    const int tid4 = tid >> 2, cA = tid & 3;
    // A: one row per thread-quad (128 rows)
    const __half* srcA; unsigned szA; unsigned dA;
    {
        int lr = tid4;
        int gr = bm + lr;
        bool val = gr < Meff;
        int sr = val ? (GATHER ? gidx[gr] : gr) : 0;
        srcA = A + (size_t)sr * lda + cA * 8;
        szA = val ? 16u : 0u;
        dA = swz(lr, cA);
    }
    // B: two rows per thread-quad (256 rows)
    const __half* srcB[2]; unsigned dB[2];
    #pragma unroll
    for (int j = 0; j < 2; j++) {
        int lr = tid4 + 128*j;
        srcB[j] = Bm + (size_t)(bn + lr) * ldb + cA * 8;
        dB[j] = swz(lr, cA);
    }

    // ---- ldmatrix per-lane offsets (stage-relative) ----
    unsigned offA[2][2], offB[4][2];
    #pragma unroll
    for (int mt = 0; mt < 2; mt++) {
        int row = wm*32 + mt*16 + ((lane >> 3) & 1)*8 + (lane & 7);
        #pragma unroll
        for (int g = 0; g < 2; g++)
            offA[mt][g] = swz(row, g*2 + ((lane >> 4) & 1));
    }
    #pragma unroll
    for (int q = 0; q < 4; q++) {
        int row = wn*64 + q*16 + ((lane >> 4) & 1)*8 + (lane & 7);
        #pragma unroll
        for (int g = 0; g < 2; g++)
            offB[q][g] = swz(row, g*2 + ((lane >> 3) & 1));
    }

    float acc[2][8][4];
    #pragma unroll
    for (int i = 0; i < 2; i++)
        #pragma unroll
        for (int j = 0; j < 8; j++)
            #pragma unroll
            for (int l = 0; l < 4; l++) acc[i][j][l] = 0.f;

    auto issue = [&](int it) {
        int s = it & 3;
        unsigned ab = sbase + s*24576;
        unsigned bb = ab + 8192;
        size_t ko = (size_t)it * 32;
        cpa16(ab + dA, srcA + ko, szA);
        cpa16(bb + dB[0], srcB[0] + ko, 16u);
        cpa16(bb + dB[1], srcB[1] + ko, 16u);
    };

    const int NT = K / 32;
    issue(0); asm volatile("cp.async.commit_group;" ::: "memory");
    issue(1); asm volatile("cp.async.commit_group;" ::: "memory");
    issue(2); asm volatile("cp.async.commit_group;" ::: "memory");

    for (int it = 0; it < NT; it++) {
        asm volatile("cp.async.wait_group 2;" ::: "memory");
        __syncthreads();
        if (it + 3 < NT) issue(it + 3);
        asm volatile("cp.async.commit_group;" ::: "memory");

        unsigned ab = sbase + (it & 3)*24576;
        unsigned bb = ab + 8192;
        #pragma unroll
        for (int g = 0; g < 2; g++) {
            unsigned a[2][4], b[4][4];
            #pragma unroll
            for (int mt = 0; mt < 2; mt++) ldsm4(a[mt], ab + offA[mt][g]);
            #pragma unroll
            for (int q = 0; q < 4; q++) ldsm4(b[q], bb + offB[q][g]);
            #pragma unroll
            for (int mt = 0; mt < 2; mt++)
                #pragma unroll
                for (int nt = 0; nt < 8; nt++)
                    mma_f16(acc[mt][nt], a[mt], &b[nt >> 1][(nt & 1)*2]);
        }
    }

    // ---- epilogue ----
    #pragma unroll
    for (int mt = 0; mt < 2; mt++) {
        #pragma unroll
        for (int i2 = 0; i2 < 2; i2++) {
            int gm = bm + wm*32 + mt*16 + gid + i2*8;
            if (gm >= Meff) continue;
            int trow = 0; float wgt = 0.f; float* Ct = nullptr;
            if (MODE == 4) { trow = gidx[gm]; wgt = gwt[gm]; Ct = gslot[gm] ? ga.r1 : ga.r0; }
            #pragma unroll
            for (int nt = 0; nt < 8; nt++) {
                int gn = bn + wn*64 + nt*8 + tig*2;
                float v0 = acc[mt][nt][i2*2 + 0];
                float v1 = acc[mt][nt][i2*2 + 1];
                size_t o = (size_t)gm * ldc + gn;
                if (MODE == 1) {
                    v0 = v0 / (1.f + expf(-v0));
                    v1 = v1 / (1.f + expf(-v1));
                } else if (MODE == 2) {
                    __half2 a2 = *(const __half2*)((const __half*)ga.aux[z] + o);
                    v0 *= __low2float(a2); v1 *= __high2float(a2);
                } else if (MODE == 3) {
                    float2 a2 = *(const float2*)((const float*)ga.aux[z] + o);
                    v0 += a2.x; v1 += a2.y;
                } else if (MODE == 5) {
                    v0 *= 0.03125f; v1 *= 0.03125f;
                }
                if (MODE == 4) {
                    float2 w2; w2.x = wgt*v0; w2.y = wgt*v1;
                    *(float2*)(Ct + (size_t)trow * ldc + gn) = w2;
                } else if (OHALF) {
                    *(__half2*)((__half*)ga.C[z] + o) = __floats2half2_rn(v0, v1);
                } else {
                    float2 w2; w2.x = v0; w2.y = v1;
                    *(float2*)((float*)ga.C[z] + o) = w2;
                }
            }
        }
    }
}

// ---------------- final add ----------------
__global__ void final_add_kernel(const float* __restrict__ a, const float* __restrict__ b,
                                 const float* __restrict__ c, const float* __restrict__ d,
                                 float* __restrict__ out) {
    size_t i = (size_t)blockIdx.x * blockDim.x + threadIdx.x;
    out[i] = a[i] + b[i] + c[i] + d[i];
}

// ---------------- launch ----------------
extern "C" void kernel_launch(void* const* d_in, const int* in_sizes, int n_in,
                              void* d_out, int out_size) {
    (void)in_sizes; (void)n_in; (void)out_size;
    const float* x         = (const float*)d_in[0];
    const float* ln1w      = (const float*)d_in[1];
    const float* ln2w      = (const float*)d_in[2];
    const float* kv_proj_d = (const float*)d_in[3];
    const float* q_proj_d  = (const float*)d_in[4];
    const float* v_proj_u  = (const float*)d_in[7];
    const float* rope_k    = (const float*)d_in[8];
    const float* rope_q    = (const float*)d_in[9];
    const float* o_proj    = (const float*)d_in[10];
    const float* router_w  = (const float*)d_in[11];
    const float* router_b  = (const float*)d_in[12];
    const float* sh_gate   = (const float*)d_in[13];
    const float* sh_up     = (const float*)d_in[14];
    const float* sh_down   = (const float*)d_in[15];
    const float* ex_gate   = (const float*)d_in[16];
    const float* ex_up     = (const float*)d_in[17];
    const float* ex_down   = (const float*)d_in[18];
    float* out = (float*)d_out;

    __half *w16,*h16,*qlat16,*kvlat16,*vT16,*q16,*k16,*sc16,*y16,*h2_16,*gbuf16;
    float *h2,*x1,*shb,*r0,*r1,*gwt;
    int *cnt,*gidx,*gslot;
    cudaGetSymbolAddress((void**)&w16, g_w16);
    cudaGetSymbolAddress((void**)&h16, g_h16);
    cudaGetSymbolAddress((void**)&qlat16, g_qlat16);
    cudaGetSymbolAddress((void**)&kvlat16, g_kvlat16);
    cudaGetSymbolAddress((void**)&vT16, g_vT16);
    cudaGetSymbolAddress((void**)&q16, g_q16);
    cudaGetSymbolAddress((void**)&k16, g_k16);
    cudaGetSymbolAddress((void**)&sc16, g_sc16);
    cudaGetSymbolAddress((void**)&y16, g_y16);
    cudaGetSymbolAddress((void**)&h2_16, g_h2_16);
    cudaGetSymbolAddress((void**)&gbuf16, g_gbuf16);
    cudaGetSymbolAddress((void**)&h2, g_h2);
    cudaGetSymbolAddress((void**)&x1, g_x1);
    cudaGetSymbolAddress((void**)&shb, g_shb);
    cudaGetSymbolAddress((void**)&r0, g_r0);
    cudaGetSymbolAddress((void**)&r1, g_r1);
    cudaGetSymbolAddress((void**)&cnt, g_cnt);
    cudaGetSymbolAddress((void**)&gidx, g_gidx);
    cudaGetSymbolAddress((void**)&gwt, g_gwt);
    cudaGetSymbolAddress((void**)&gslot, g_gslot);

    const size_t ESL = (size_t)BTd * Fd;   // per-expert gbuf16 slice

    // raise dynamic smem limit (idempotent)
    cudaFuncSetAttribute(gemm6<0,false,true>,  cudaFuncAttributeMaxDynamicSharedMemorySize, SMEM_BYTES);
    cudaFuncSetAttribute(gemm6<5,false,true>,  cudaFuncAttributeMaxDynamicSharedMemorySize, SMEM_BYTES);
    cudaFuncSetAttribute(gemm6<3,false,false>, cudaFuncAttributeMaxDynamicSharedMemorySize, SMEM_BYTES);
    cudaFuncSetAttribute(gemm6<1,false,true>,  cudaFuncAttributeMaxDynamicSharedMemorySize, SMEM_BYTES);
    cudaFuncSetAttribute(gemm6<2,false,true>,  cudaFuncAttributeMaxDynamicSharedMemorySize, SMEM_BYTES);
    cudaFuncSetAttribute(gemm6<0,false,false>, cudaFuncAttributeMaxDynamicSharedMemorySize, SMEM_BYTES);
    cudaFuncSetAttribute(gemm6<1,true,true>,   cudaFuncAttributeMaxDynamicSharedMemorySize, SMEM_BYTES);
    cudaFuncSetAttribute(gemm6<2,true,true>,   cudaFuncAttributeMaxDynamicSharedMemorySize, SMEM_BYTES);
    cudaFuncSetAttribute(gemm6<4,false,false>, cudaFuncAttributeMaxDynamicSharedMemorySize, SMEM_BYTES);

    // ---- weight conversion (fp32 -> fp16 pool) ----
    {
        CVT cv;
        cv.src[0] = q_proj_d;  cv.dst[0] = w16 + W_QPD; cv.n[0] = Ld*Hd;
        cv.src[1] = kv_proj_d; cv.dst[1] = w16 + W_KVD; cv.n[1] = Ld*Hd;
        cv.src[2] = v_proj_u;  cv.dst[2] = w16 + W_VPU; cv.n[2] = Hd*Ld;
        cv.src[3] = rope_q;    cv.dst[3] = w16 + W_RQ;  cv.n[3] = Hd*Ld;
        cv.src[4] = rope_k;    cv.dst[4] = w16 + W_RK;  cv.n[4] = Hd*Hd;
        cv.src[5] = o_proj;    cv.dst[5] = w16 + W_OPJ; cv.n[5] = Hd*Hd;
        cv.src[6] = sh_gate;   cv.dst[6] = w16 + W_SHG; cv.n[6] = Fd*Hd;
        cv.src[7] = sh_up;     cv.dst[7] = w16 + W_SHU; cv.n[7] = Fd*Hd;
        cv.src[8] = sh_down;   cv.dst[8] = w16 + W_SHD; cv.n[8] = Hd*Fd;
        cv.src[9] = ex_gate;   cv.dst[9] = w16 + W_EXG; cv.n[9] = Ed*Fd*Hd;
        cv.src[10]= ex_up;     cv.dst[10]= w16 + W_EXU; cv.n[10]= Ed*Fd*Hd;
        cv.src[11]= ex_down;   cv.dst[11]= w16 + W_EXD; cv.n[11]= Ed*Hd*Fd;
        int mx = Ed*Fd*Hd/8;
        cvt_kernel<<<dim3((mx + 255)/256, 12), 256>>>(cv);
    }

    zero_cnt_kernel<<<1, 32>>>();
    ln_kernel<<<BTd, 256>>>(x, ln1w, h16, nullptr);

    // qlat + kvlat (z=2), N=256
    {
        GA ga = {};
        ga.A[0] = h16;           ga.A[1] = h16;
        ga.B[0] = w16 + W_QPD;   ga.B[1] = w16 + W_KVD;
        ga.C[0] = qlat16;        ga.C[1] = kvlat16;
        ga.M = BTd; ga.N = Ld; ga.K = Hd; ga.lda = Hd; ga.ldb = Hd; ga.ldc = Ld;
        gemm6<0,false,true><<<dim3(Ld/256, BTd/128, 2), 512, SMEM_BYTES>>>(ga);
    }
    // vT[b] = v_proj_u @ kvlat[b]^T  (M=Hd, N=Td, K=Ld)
    {
        GA ga = {};
        for (int b = 0; b < Bd; b++) {
            ga.A[b] = w16 + W_VPU;
            ga.B[b] = kvlat16 + (size_t)b*Td*Ld;
            ga.C[b] = vT16 + (size_t)b*Hd*Td;
        }
        ga.M = Hd; ga.N = Td; ga.K = Ld; ga.lda = Ld; ga.ldb = Ld; ga.ldc = Td;
        gemm6<0,false,true><<<dim3(Td/256, Hd/128, Bd), 512, SMEM_BYTES>>>(ga);
    }
    // q_r = qlat @ rope_q.T
    {
        GA ga = {};
        ga.A[0] = qlat16; ga.B[0] = w16 + W_RQ; ga.C[0] = q16;
        ga.M = BTd; ga.N = Hd; ga.K = Ld; ga.lda = Ld; ga.ldb = Ld; ga.ldc = Hd;
        gemm6<0,false,true><<<dim3(Hd/256, BTd/128, 1), 512, SMEM_BYTES>>>(ga);
    }
    // k_r = h @ rope_k.T
    {
        GA ga = {};
        ga.A[0] = h16; ga.B[0] = w16 + W_RK; ga.C[0] = k16;
        ga.M = BTd; ga.N = Hd; ga.K = Hd; ga.lda = Hd; ga.ldb = Hd; ga.ldc = Hd;
        gemm6<0,false,true><<<dim3(Hd/256, BTd/128, 1), 512, SMEM_BYTES>>>(ga);
    }

    rope_kernel<<<BTd, 256>>>(q16, k16);

    // scores (z=2, causal)
    {
        GA ga = {};
        for (int b = 0; b < Bd; b++) {
            ga.A[b] = q16 + (size_t)b*Td*Hd;
            ga.B[b] = k16 + (size_t)b*Td*Hd;
            ga.C[b] = sc16 + (size_t)b*Td*Td;
        }
        ga.M = Td; ga.N = Td; ga.K = Hd; ga.lda = Hd; ga.ldb = Hd; ga.ldc = Td;
        gemm6<5,false,true><<<dim3(Td/256, Td/128, Bd), 512, SMEM_BYTES>>>(ga);
    }
    softmax_kernel<<<dim3(Td, Bd), 256>>>(sc16);
    // PV (z=2): y[b] = attn[b] @ vT[b]^T
    {
        GA ga = {};
        for (int b = 0; b < Bd; b++) {
            ga.A[b] = sc16 + (size_t)b*Td*Td;
            ga.B[b] = vT16 + (size_t)b*Hd*Td;
            ga.C[b] = y16 + (size_t)b*Td*Hd;
        }
        ga.M = Td; ga.N = Hd; ga.K = Td; ga.lda = Td; ga.ldb = Td; ga.ldc = Hd;
        gemm6<0,false,true><<<dim3(Hd/256, Td/128, Bd), 512, SMEM_BYTES>>>(ga);
    }
    // x1 = x + y @ o_proj.T  (fp32 out)
    {
        GA ga = {};
        ga.A[0] = y16; ga.B[0] = w16 + W_OPJ; ga.C[0] = x1; ga.aux[0] = x;
        ga.M = BTd; ga.N = Hd; ga.K = Hd; ga.lda = Hd; ga.ldb = Hd; ga.ldc = Hd;
        gemm6<3,false,false><<<dim3(Hd/256, BTd/128, 1), 512, SMEM_BYTES>>>(ga);
    }

    // ---- MoE ----
    ln_kernel<<<BTd, 256>>>(x1, ln2w, h2_16, h2);
    router_kernel<<<BTd, 256>>>(h2, router_w, router_b);

    __half* shg = gbuf16 + (size_t)7 * ESL;
    // shared gate (silu)
    {
        GA ga = {};
        ga.A[0] = h2_16; ga.B[0] = w16 + W_SHG; ga.C[0] = shg;
        ga.M = BTd; ga.N = Fd; ga.K = Hd; ga.lda = Hd; ga.ldb = Hd; ga.ldc = Fd;
        gemm6<1,false,true><<<dim3(Fd/256, BTd/128, 1), 512, SMEM_BYTES>>>(ga);
    }
    // shared up (in-place multiply)
    {
        GA ga = {};
        ga.A[0] = h2_16; ga.B[0] = w16 + W_SHU; ga.C[0] = shg; ga.aux[0] = shg;
        ga.M = BTd; ga.N = Fd; ga.K = Hd; ga.lda = Hd; ga.ldb = Hd; ga.ldc = Fd;
        gemm6<2,false,true><<<dim3(Fd/256, BTd/128, 1), 512, SMEM_BYTES>>>(ga);
    }
    // shared down (fp32 out)
    {
        GA ga = {};
        ga.A[0] = shg; ga.B[0] = w16 + W_SHD; ga.C[0] = shb;
        ga.M = BTd; ga.N = Hd; ga.K = Fd; ga.lda = Fd; ga.ldb = Fd; ga.ldc = Hd;
        gemm6<0,false,false><<<dim3(Hd/256, BTd/128, 1), 512, SMEM_BYTES>>>(ga);
    }

    // routed experts, all 7 batched per stage
    {
        GA ga = {};
        for (int e = 0; e < Ed; e++) {
            ga.A[e] = h2_16;
            ga.B[e] = w16 + W_EXG + (size_t)e * Fd * Hd;
            ga.C[e] = gbuf16 + (size_t)e * ESL;
        }
        ga.M = BTd; ga.N = Fd; ga.K = Hd; ga.lda = Hd; ga.ldb = Hd; ga.ldc = Fd;
        ga.gcnt = cnt; ga.gidx = gidx; ga.gwt = gwt; ga.gslot = gslot;
        gemm6<1,true,true><<<dim3(Fd/256, BTd/128, Ed), 512, SMEM_BYTES>>>(ga);
    }
    {
        GA ga = {};
        for (int e = 0; e < Ed; e++) {
            ga.A[e] = h2_16;
            ga.B[e] = w16 + W_EXU + (size_t)e * Fd * Hd;
            ga.C[e] = gbuf16 + (size_t)e * ESL;
            ga.aux[e] = gbuf16 + (size_t)e * ESL;
        }
        ga.M = BTd; ga.N = Fd; ga.K = Hd; ga.lda = Hd; ga.ldb = Hd; ga.ldc = Fd;
        ga.gcnt = cnt; ga.gidx = gidx; ga.gwt = gwt; ga.gslot = gslot;
        gemm6<2,true,true><<<dim3(Fd/256, BTd/128, Ed), 512, SMEM_BYTES>>>(ga);
    }
    {
        GA ga = {};
        for (int e = 0; e < Ed; e++) {
            ga.A[e] = gbuf16 + (size_t)e * ESL;
            ga.B[e] = w16 + W_EXD + (size_t)e * Hd * Fd;
        }
        ga.r0 = r0; ga.r1 = r1;
        ga.M = BTd; ga.N = Hd; ga.K = Fd; ga.lda = Fd; ga.ldb = Fd; ga.ldc = Hd;
        ga.gcnt = cnt; ga.gidx = gidx; ga.gwt = gwt; ga.gslot = gslot;
        gemm6<4,false,false><<<dim3(Hd/256, BTd/128, Ed), 512, SMEM_BYTES>>>(ga);
    }

    final_add_kernel<<<(BTd * Hd) / 256, 256>>>(x1, shb, r0, r1, out);
}

// round 12
// speedup vs baseline: 3.1510x; 1.0042x over previous
#include <cuda_runtime.h>
#include <cuda_fp16.h>
#include <math.h>

#define Bd 2
#define Td 2048
#define Hd 1024
#define Ld 256
#define Fd 2048
#define Ed 7
#define BTd (Bd*Td)

// weight fp16 pool offsets (in halves)
#define W_QPD 0
#define W_KVD 262144
#define W_VPU 524288
#define W_RQ  786432
#define W_RK  1048576
#define W_OPJ 2097152
#define W_SHG 3145728
#define W_SHU 5242880
#define W_SHD 7340032
#define W_EXG 9437184
#define W_EXU 24117248
#define W_EXD 38797312
#define W_TOT 53477376

#define SMEM_BYTES 98304   // 4 stages x (A 8KB + B 16KB)

// ---------------- scratch (device globals; no allocation) ----------------
__device__ __half g_w16[W_TOT];
__device__ __half g_h16[BTd*Hd];
__device__ __half g_qlat16[BTd*Ld];
__device__ __half g_kvlat16[BTd*Ld];
__device__ __half g_vT16[BTd*Hd];      // [Bd][Hd][Td]
__device__ __half g_q16[BTd*Hd];
__device__ __half g_k16[BTd*Hd];
__device__ __half g_sc16[(size_t)Bd*Td*Td];
__device__ __half g_y16[BTd*Hd];
__device__ __half g_h2_16[BTd*Hd];
__device__ __half g_gbuf16[(size_t)8*BTd*Fd];  // 7 routed + 1 shared slices
__device__ float  g_h2[BTd*Hd];
__device__ float  g_x1[BTd*Hd];
__device__ float  g_shb[BTd*Hd];
__device__ float  g_r0[BTd*Hd];
__device__ float  g_r1[BTd*Hd];
__device__ int    g_cnt[Ed];
__device__ int    g_gidx[Ed*BTd];
__device__ float  g_gwt[Ed*BTd];
__device__ int    g_gslot[Ed*BTd];

// ---------------- fp16 helpers ----------------
__device__ __forceinline__ unsigned f2h2(float lo, float hi) {
    __half2 h = __floats2half2_rn(lo, hi);
    return *(unsigned*)&h;
}

// ---------------- weight conversion ----------------
struct CVT {
    const float* src[12];
    __half* dst[12];
    int n[12];
};

__global__ void cvt_kernel(CVT cv) {
    int seg = blockIdx.y;
    int idx = blockIdx.x * 256 + threadIdx.x;
    int n8 = cv.n[seg] >> 3;
    if (idx >= n8) return;
    const float4* s = (const float4*)cv.src[seg];
    float4 f1 = s[2*idx], f2 = s[2*idx+1];
    uint4 o;
    o.x = f2h2(f1.x, f1.y); o.y = f2h2(f1.z, f1.w);
    o.z = f2h2(f2.x, f2.y); o.w = f2h2(f2.z, f2.w);
    ((uint4*)cv.dst[seg])[idx] = o;
}

// ---------------- block reduce ----------------
template<bool DOMAX>
__device__ __forceinline__ float blockReduce(float v) {
    __shared__ float sh[8];
    __shared__ float res;
    int lane = threadIdx.x & 31, w = threadIdx.x >> 5;
    #pragma unroll
    for (int o = 16; o; o >>= 1) {
        float t = __shfl_xor_sync(0xffffffffu, v, o);
        v = DOMAX ? fmaxf(v, t) : v + t;
    }
    if (lane == 0) sh[w] = v;
    __syncthreads();
    if (w == 0) {
        v = (lane < (int)(blockDim.x >> 5)) ? sh[lane] : (DOMAX ? -3.4e38f : 0.f);
        #pragma unroll
        for (int o = 4; o; o >>= 1) {
            float t = __shfl_xor_sync(0xffffffffu, v, o);
            v = DOMAX ? fmaxf(v, t) : v + t;
        }
        if (lane == 0) res = v;
    }
    __syncthreads();
    return res;
}

// ---------------- layernorm (fp16 out, optional fp32 copy) ----------------
__global__ void ln_kernel(const float* __restrict__ x, const float* __restrict__ w,
                          __half* __restrict__ o16, float* __restrict__ o32) {
    int row = blockIdx.x;
    const float* xr = x + (size_t)row * Hd;
    int t = threadIdx.x;
    float v[4];
    float s = 0.f;
    #pragma unroll
    for (int i = 0; i < 4; i++) { v[i] = xr[t + 256*i]; s += v[i]; }
    s = blockReduce<false>(s);
    float mu = s * (1.f / Hd);
    float q = 0.f;
    #pragma unroll
    for (int i = 0; i < 4; i++) { float d = v[i] - mu; q += d * d; }
    q = blockReduce<false>(q);
    float rs = rsqrtf(q * (1.f / Hd) + 1e-5f);
    #pragma unroll
    for (int i = 0; i < 4; i++) {
        float val = (v[i] - mu) * rs * w[t + 256*i];
        o16[(size_t)row*Hd + t + 256*i] = __float2half_rn(val);
        if (o32) o32[(size_t)row*Hd + t + 256*i] = val;
    }
}

// ---------------- rope (fp16 in/out) ----------------
__global__ void rope_kernel(__half* __restrict__ q, __half* __restrict__ k) {
    int row = blockIdx.x;
    int t = row % Td;
    size_t base = (size_t)row * Hd;
    #pragma unroll
    for (int it = 0; it < 2; it++) {
        int p = threadIdx.x + 256 * it;
        double invf = exp(-(double)(2 * p) / 1024.0 * 9.210340371976184);
        float f = (float)t * (float)invf;
        float c = cosf(f), s = sinf(f);
        float q1 = __half2float(q[base + p]), q2 = __half2float(q[base + p + 512]);
        q[base + p]       = __float2half_rn(q1 * c - q2 * s);
        q[base + p + 512] = __float2half_rn(q2 * c + q1 * s);
        float k1 = __half2float(k[base + p]), k2 = __half2float(k[base + p + 512]);
        k[base + p]       = __float2half_rn(k1 * c - k2 * s);
        k[base + p + 512] = __float2half_rn(k2 * c + k1 * s);
    }
}

// ---------------- softmax (causal, fp16, single pass) ----------------
__global__ void softmax_kernel(__half* __restrict__ sc) {
    int b = blockIdx.y, i = blockIdx.x;
    __half* row = sc + ((size_t)b * Td + i) * Td;
    int t = threadIdx.x;
    int n = i + 1;
    uint4 u = *(const uint4*)(row + t*8);
    __half2* hp = (__half2*)&u;
    float v[8];
    #pragma unroll
    for (int j = 0; j < 4; j++) {
        v[2*j]   = __low2float(hp[j]);
        v[2*j+1] = __high2float(hp[j]);
    }
    float mx = -3.4e38f;
    #pragma unroll
    for (int j = 0; j < 8; j++)
        if (t*8 + j < n) mx = fmaxf(mx, v[j]);
    mx = blockReduce<true>(mx);
    float s = 0.f;
    #pragma unroll
    for (int j = 0; j < 8; j++) {
        float e = (t*8 + j < n) ? expf(v[j] - mx) : 0.f;
        v[j] = e; s += e;
    }
    s = blockReduce<false>(s);
    float inv = 1.f / s;
    #pragma unroll
    for (int j = 0; j < 4; j++)
        hp[j] = __floats2half2_rn(v[2*j]*inv, v[2*j+1]*inv);
    *(uint4*)(row + t*8) = u;
}

// ---------------- router + top2 gather lists ----------------
__global__ void zero_cnt_kernel() {
    if (threadIdx.x < Ed) g_cnt[threadIdx.x] = 0;
}

__global__ void router_kernel(const float* __restrict__ h2, const float* __restrict__ rw,
                              const float* __restrict__ rb) {
    int m = blockIdx.x;
    int w = threadIdx.x >> 5, lane = threadIdx.x & 31;
    __shared__ float probs[Ed];
    if (w < Ed) {
        const float* hv = h2 + (size_t)m * Hd;
        const float* wv = rw + (size_t)w * Hd;
        float s = 0.f;
        for (int j = lane; j < Hd; j += 32) s += hv[j] * wv[j];
        #pragma unroll
        for (int o = 16; o; o >>= 1) s += __shfl_xor_sync(0xffffffffu, s, o);
        if (lane == 0) probs[w] = 1.f / (1.f + expf(-(s + rb[w])));
    }
    __syncthreads();
    if (threadIdx.x == 0) {
        int e0 = 0; float p0 = probs[0];
        for (int e = 1; e < Ed; e++) if (probs[e] > p0) { p0 = probs[e]; e0 = e; }
        int e1 = -1; float p1 = -3.4e38f;
        for (int e = 0; e < Ed; e++) if (e != e0 && probs[e] > p1) { p1 = probs[e]; e1 = e; }
        int pos = atomicAdd(&g_cnt[e0], 1);
        g_gidx[e0*BTd + pos] = m; g_gwt[e0*BTd + pos] = p0; g_gslot[e0*BTd + pos] = 0;
        pos = atomicAdd(&g_cnt[e1], 1);
        g_gidx[e1*BTd + pos] = m; g_gwt[e1*BTd + pos] = p1; g_gslot[e1*BTd + pos] = 1;
    }
}

// ---------------- mma / ldmatrix / cp.async ----------------
__device__ __forceinline__ void mma_f16(float* d, const unsigned* a, const unsigned* b) {
    asm volatile(
        "mma.sync.aligned.m16n8k16.row.col.f32.f16.f16.f32 "
        "{%0,%1,%2,%3}, {%4,%5,%6,%7}, {%8,%9}, {%0,%1,%2,%3};"
        : "+f"(d[0]), "+f"(d[1]), "+f"(d[2]), "+f"(d[3])
        : "r"(a[0]), "r"(a[1]), "r"(a[2]), "r"(a[3]), "r"(b[0]), "r"(b[1]));
}

__device__ __forceinline__ void ldsm4(unsigned* r, unsigned addr) {
    asm volatile("ldmatrix.sync.aligned.m8n8.x4.shared.b16 {%0,%1,%2,%3}, [%4];"
        : "=r"(r[0]), "=r"(r[1]), "=r"(r[2]), "=r"(r[3]) : "r"(addr));
}

__device__ __forceinline__ void cpa16(unsigned dst, const void* src, unsigned sz) {
    asm volatile("cp.async.cg.shared.global [%0], [%1], 16, %2;"
        :: "r"(dst), "l"(src), "r"(sz) : "memory");
}

__device__ __forceinline__ unsigned smem_u32(const void* p) {
    unsigned a;
    asm("{ .reg .u64 t; cvta.to.shared.u64 t, %1; cvt.u32.u64 %0, t; }" : "=r"(a) : "l"(p));
    return a;
}

// crosswise swizzle: 16B chunk (row, c) -> byte offset within a tile buffer
__device__ __forceinline__ unsigned swz(int row, int c) {
    int line = row >> 1;
    return (unsigned)(line*128 + (((((row & 1) << 2) | c) ^ (line & 7)) << 4));
}

// per-z dims + pointer tables for heterogeneous batched launches
struct GA {
    const void* A[8];
    const void* B[8];
    void*       C[8];
    const void* aux[8];
    float* r0; float* r1;
    int M[8], N[8], K[8], lda[8], ldb[8], ldc[8];
    int ngather;   // z < ngather -> A rows gathered via gidx, Meff = gcnt[z]
    const int* gcnt; const int* gidx; const float* gwt; const int* gslot;
};

// ---------------- fp16 mma GEMM, 128x256 tile, 512 thr, cp.async 4-stage --
// C = A @ B^T, per-z shapes. 16 warps, 4x4 grid, warp tile 32x64.
// MODE 0: C=v  1: silu  2: C=v*aux  3: C=v+aux(f32)
//      4: scatter w*v to (r0|r1)[gidx] (f32)   5: C=v/32, causal tile skip
// KLIM: clamp K to bm+128 (causal PV)
template<int MODE, bool OHALF, bool KLIM>
__global__ void __launch_bounds__(512) gemm7(GA ga) {
    const int z = blockIdx.z;
    const int bm = blockIdx.y * 128;
    const int bn = blockIdx.x * 256;
    const int Mz = ga.M[z], Nz = ga.N[z];
    if (bn >= Nz || bm >= Mz) return;
    if (MODE == 5 && bn > bm + 127) return;

    const bool gath = z < ga.ngather;
    int Meff = Mz;
    const int* gidx = nullptr; const float* gwt = nullptr; const int* gslot = nullptr;
    if (gath || MODE == 4) {
        Meff = ga.gcnt[z];
        gidx = ga.gidx + z * BTd;
        gwt  = ga.gwt  + z * BTd;
        gslot= ga.gslot+ z * BTd;
    }
    if (bm >= Meff) return;

    const __half* __restrict__ A  = (const __half*)ga.A[z];
    const __half* __restrict__ Bm = (const __half*)ga.B[z];
    int K = ga.K[z];
    if (KLIM) K = (bm + 128 < K) ? bm + 128 : K;
    const int lda = ga.lda[z], ldb = ga.ldb[z], ldc = ga.ldc[z];

    extern __shared__ __align__(16) unsigned char smraw[];
    const unsigned sbase = smem_u32(smraw);

    const int tid = threadIdx.x;
    const int lane = tid & 31, wid = tid >> 5;
    const int wm = wid & 3, wn = wid >> 2;      // 4 x 4 warps, 32x64 each
    const int gid = lane >> 2, tig = lane & 3;

    // ---- cp.async source setup ----
    const int tid4 = tid >> 2, cA = tid & 3;
    const __half* srcA; unsigned szA; unsigned dA;
    {
        int lr = tid4;
        int gr = bm + lr;
        bool val = gr < Meff;
        int sr = val ? (gath ? gidx[gr] : gr) : 0;
        srcA = A + (size_t)sr * lda + cA * 8;
        szA = val ? 16u : 0u;
        dA = swz(lr, cA);
    }
    const __half* srcB[2]; unsigned dB[2]; unsigned szB[2];
    #pragma unroll
    for (int j = 0; j < 2; j++) {
        int lr = tid4 + 128*j;
        int gr = bn + lr;
        bool val = gr < Nz;
        srcB[j] = Bm + (size_t)(val ? gr : 0) * ldb + cA * 8;
        szB[j] = val ? 16u : 0u;
        dB[j] = swz(lr, cA);
    }

    // ---- ldmatrix per-lane offsets (stage-relative) ----
    unsigned offA[2][2], offB[4][2];
    #pragma unroll
    for (int mt = 0; mt < 2; mt++) {
        int row = wm*32 + mt*16 + ((lane >> 3) & 1)*8 + (lane & 7);
        #pragma unroll
        for (int g = 0; g < 2; g++)
            offA[mt][g] = swz(row, g*2 + ((lane >> 4) & 1));
    }
    #pragma unroll
    for (int q = 0; q < 4; q++) {
        int row = wn*64 + q*16 + ((lane >> 4) & 1)*8 + (lane & 7);
        #pragma unroll
        for (int g = 0; g < 2; g++)
            offB[q][g] = swz(row, g*2 + ((lane >> 3) & 1));
    }

    float acc[2][8][4];
    #pragma unroll
    for (int i = 0; i < 2; i++)
        #pragma unroll
        for (int j = 0; j < 8; j++)
            #pragma unroll
            for (int l = 0; l < 4; l++) acc[i][j][l] = 0.f;

    auto issue = [&](int it) {
        int s = it & 3;
        unsigned ab = sbase + s*24576;
        unsigned bb = ab + 8192;
        size_t ko = (size_t)it * 32;
        cpa16(ab + dA, srcA + ko, szA);
        cpa16(bb + dB[0], srcB[0] + ko, szB[0]);
        cpa16(bb + dB[1], srcB[1] + ko, szB[1]);
    };

    const int NT = K / 32;
    issue(0); asm volatile("cp.async.commit_group;" ::: "memory");
    issue(1); asm volatile("cp.async.commit_group;" ::: "memory");
    issue(2); asm volatile("cp.async.commit_group;" ::: "memory");

    for (int it = 0; it < NT; it++) {
        asm volatile("cp.async.wait_group 2;" ::: "memory");
        __syncthreads();
        if (it + 3 < NT) issue(it + 3);
        asm volatile("cp.async.commit_group;" ::: "memory");

        unsigned ab = sbase + (it & 3)*24576;
        unsigned bb = ab + 8192;
        #pragma unroll
        for (int g = 0; g < 2; g++) {
            unsigned a[2][4], b[4][4];
            #pragma unroll
            for (int mt = 0; mt < 2; mt++) ldsm4(a[mt], ab + offA[mt][g]);
            #pragma unroll
            for (int q = 0; q < 4; q++) ldsm4(b[q], bb + offB[q][g]);
            #pragma unroll
            for (int mt = 0; mt < 2; mt++)
                #pragma unroll
                for (int nt = 0; nt < 8; nt++)
                    mma_f16(acc[mt][nt], a[mt], &b[nt >> 1][(nt & 1)*2]);
        }
    }

    // ---- epilogue ----
    #pragma unroll
    for (int mt = 0; mt < 2; mt++) {
        #pragma unroll
        for (int i2 = 0; i2 < 2; i2++) {
            int gm = bm + wm*32 + mt*16 + gid + i2*8;
            if (gm >= Meff) continue;
            int trow = 0; float wgt = 0.f; float* Ct = nullptr;
            if (MODE == 4) { trow = gidx[gm]; wgt = gwt[gm]; Ct = gslot[gm] ? ga.r1 : ga.r0; }
            #pragma unroll
            for (int nt = 0; nt < 8; nt++) {
                int gn = bn + wn*64 + nt*8 + tig*2;
                if (gn >= Nz) continue;
                float v0 = acc[mt][nt][i2*2 + 0];
                float v1 = acc[mt][nt][i2*2 + 1];
                size_t o = (size_t)gm * ldc + gn;
                if (MODE == 1) {
                    v0 = v0 / (1.f + expf(-v0));
                    v1 = v1 / (1.f + expf(-v1));
                } else if (MODE == 2) {
                    __half2 a2 = *(const __half2*)((const __half*)ga.aux[z] + o);
                    v0 *= __low2float(a2); v1 *= __high2float(a2);
                } else if (MODE == 3) {
                    float2 a2 = *(const float2*)((const float*)ga.aux[z] + o);
                    v0 += a2.x; v1 += a2.y;
                } else if (MODE == 5) {
                    v0 *= 0.03125f; v1 *= 0.03125f;
                }
                if (MODE == 4) {
                    float2 w2; w2.x = wgt*v0; w2.y = wgt*v1;
                    *(float2*)(Ct + (size_t)trow * ldc + gn) = w2;
                } else if (OHALF) {
                    *(__half2*)((__half*)ga.C[z] + o) = __floats2half2_rn(v0, v1);
                } else {
                    float2 w2; w2.x = v0; w2.y = v1;
                    *(float2*)((float*)ga.C[z] + o) = w2;
                }
            }
        }
    }
}

// ---------------- final add ----------------
__global__ void final_add_kernel(const float* __restrict__ a, const float* __restrict__ b,
                                 const float* __restrict__ c, const float* __restrict__ d,
                                 float* __restrict__ out) {
    size_t i = (size_t)blockIdx.x * blockDim.x + threadIdx.x;
    out[i] = a[i] + b[i] + c[i] + d[i];
}

// ---------------- launch ----------------
extern "C" void kernel_launch(void* const* d_in, const int* in_sizes, int n_in,
                              void* d_out, int out_size) {
    (void)in_sizes; (void)n_in; (void)out_size;
    const float* x         = (const float*)d_in[0];
    const float* ln1w      = (const float*)d_in[1];
    const float* ln2w      = (const float*)d_in[2];
    const float* kv_proj_d = (const float*)d_in[3];
    const float* q_proj_d  = (const float*)d_in[4];
    const float* v_proj_u  = (const float*)d_in[7];
    const float* rope_k    = (const float*)d_in[8];
    const float* rope_q    = (const float*)d_in[9];
    const float* o_proj    = (const float*)d_in[10];
    const float* router_w  = (const float*)d_in[11];
    const float* router_b  = (const float*)d_in[12];
    const float* sh_gate   = (const float*)d_in[13];
    const float* sh_up     = (const float*)d_in[14];
    const float* sh_down   = (const float*)d_in[15];
    const float* ex_gate   = (const float*)d_in[16];
    const float* ex_up     = (const float*)d_in[17];
    const float* ex_down   = (const float*)d_in[18];
    float* out = (float*)d_out;

    __half *w16,*h16,*qlat16,*kvlat16,*vT16,*q16,*k16,*sc16,*y16,*h2_16,*gbuf16;
    float *h2,*x1,*shb,*r0,*r1,*gwt;
    int *cnt,*gidx,*gslot;
    cudaGetSymbolAddress((void**)&w16, g_w16);
    cudaGetSymbolAddress((void**)&h16, g_h16);
    cudaGetSymbolAddress((void**)&qlat16, g_qlat16);
    cudaGetSymbolAddress((void**)&kvlat16, g_kvlat16);
    cudaGetSymbolAddress((void**)&vT16, g_vT16);
    cudaGetSymbolAddress((void**)&q16, g_q16);
    cudaGetSymbolAddress((void**)&k16, g_k16);
    cudaGetSymbolAddress((void**)&sc16, g_sc16);
    cudaGetSymbolAddress((void**)&y16, g_y16);
    cudaGetSymbolAddress((void**)&h2_16, g_h2_16);
    cudaGetSymbolAddress((void**)&gbuf16, g_gbuf16);
    cudaGetSymbolAddress((void**)&h2, g_h2);
    cudaGetSymbolAddress((void**)&x1, g_x1);
    cudaGetSymbolAddress((void**)&shb, g_shb);
    cudaGetSymbolAddress((void**)&r0, g_r0);
    cudaGetSymbolAddress((void**)&r1, g_r1);
    cudaGetSymbolAddress((void**)&cnt, g_cnt);
    cudaGetSymbolAddress((void**)&gidx, g_gidx);
    cudaGetSymbolAddress((void**)&gwt, g_gwt);
    cudaGetSymbolAddress((void**)&gslot, g_gslot);

    const size_t ESL = (size_t)BTd * Fd;   // per-expert gbuf16 slice

    // raise dynamic smem limit (idempotent)
    cudaFuncSetAttribute(gemm7<0,true,false>,  cudaFuncAttributeMaxDynamicSharedMemorySize, SMEM_BYTES);
    cudaFuncSetAttribute(gemm7<0,true,true>,   cudaFuncAttributeMaxDynamicSharedMemorySize, SMEM_BYTES);
    cudaFuncSetAttribute(gemm7<5,true,false>,  cudaFuncAttributeMaxDynamicSharedMemorySize, SMEM_BYTES);
    cudaFuncSetAttribute(gemm7<3,false,false>, cudaFuncAttributeMaxDynamicSharedMemorySize, SMEM_BYTES);
    cudaFuncSetAttribute(gemm7<1,true,false>,  cudaFuncAttributeMaxDynamicSharedMemorySize, SMEM_BYTES);
    cudaFuncSetAttribute(gemm7<2,true,false>,  cudaFuncAttributeMaxDynamicSharedMemorySize, SMEM_BYTES);
    cudaFuncSetAttribute(gemm7<0,false,false>, cudaFuncAttributeMaxDynamicSharedMemorySize, SMEM_BYTES);
    cudaFuncSetAttribute(gemm7<4,false,false>, cudaFuncAttributeMaxDynamicSharedMemorySize, SMEM_BYTES);

    // ---- weight conversion (fp32 -> fp16 pool) ----
    {
        CVT cv;
        cv.src[0] = q_proj_d;  cv.dst[0] = w16 + W_QPD; cv.n[0] = Ld*Hd;
        cv.src[1] = kv_proj_d; cv.dst[1] = w16 + W_KVD; cv.n[1] = Ld*Hd;
        cv.src[2] = v_proj_u;  cv.dst[2] = w16 + W_VPU; cv.n[2] = Hd*Ld;
        cv.src[3] = rope_q;    cv.dst[3] = w16 + W_RQ;  cv.n[3] = Hd*Ld;
        cv.src[4] = rope_k;    cv.dst[4] = w16 + W_RK;  cv.n[4] = Hd*Hd;
        cv.src[5] = o_proj;    cv.dst[5] = w16 + W_OPJ; cv.n[5] = Hd*Hd;
        cv.src[6] = sh_gate;   cv.dst[6] = w16 + W_SHG; cv.n[6] = Fd*Hd;
        cv.src[7] = sh_up;     cv.dst[7] = w16 + W_SHU; cv.n[7] = Fd*Hd;
        cv.src[8] = sh_down;   cv.dst[8] = w16 + W_SHD; cv.n[8] = Hd*Fd;
        cv.src[9] = ex_gate;   cv.dst[9] = w16 + W_EXG; cv.n[9] = Ed*Fd*Hd;
        cv.src[10]= ex_up;     cv.dst[10]= w16 + W_EXU; cv.n[10]= Ed*Fd*Hd;
        cv.src[11]= ex_down;   cv.dst[11]= w16 + W_EXD; cv.n[11]= Ed*Hd*Fd;
        int mx = Ed*Fd*Hd/8;
        cvt_kernel<<<dim3((mx + 255)/256, 12), 256>>>(cv);
    }

    zero_cnt_kernel<<<1, 32>>>();
    ln_kernel<<<BTd, 256>>>(x, ln1w, h16, nullptr);

    // merged: qlat (z0), kvlat (z1), k_r (z2)
    {
        GA ga = {};
        ga.A[0] = h16; ga.A[1] = h16; ga.A[2] = h16;
        ga.B[0] = w16 + W_QPD; ga.B[1] = w16 + W_KVD; ga.B[2] = w16 + W_RK;
        ga.C[0] = qlat16; ga.C[1] = kvlat16; ga.C[2] = k16;
        for (int zz = 0; zz < 3; zz++) {
            ga.M[zz] = BTd; ga.K[zz] = Hd; ga.lda[zz] = Hd; ga.ldb[zz] = Hd;
        }
        ga.N[0] = Ld; ga.N[1] = Ld; ga.N[2] = Hd;
        ga.ldc[0] = Ld; ga.ldc[1] = Ld; ga.ldc[2] = Hd;
        gemm7<0,true,false><<<dim3(Hd/256, BTd/128, 3), 512, SMEM_BYTES>>>(ga);
    }
    // merged: vT b0 (z0), vT b1 (z1), q_r (z2)
    {
        GA ga = {};
        for (int b = 0; b < Bd; b++) {
            ga.A[b] = w16 + W_VPU;
            ga.B[b] = kvlat16 + (size_t)b*Td*Ld;
            ga.C[b] = vT16 + (size_t)b*Hd*Td;
            ga.M[b] = Hd; ga.N[b] = Td; ga.K[b] = Ld;
            ga.lda[b] = Ld; ga.ldb[b] = Ld; ga.ldc[b] = Td;
        }
        ga.A[2] = qlat16; ga.B[2] = w16 + W_RQ; ga.C[2] = q16;
        ga.M[2] = BTd; ga.N[2] = Hd; ga.K[2] = Ld;
        ga.lda[2] = Ld; ga.ldb[2] = Ld; ga.ldc[2] = Hd;
        gemm7<0,true,false><<<dim3(Td/256, BTd/128, 3), 512, SMEM_BYTES>>>(ga);
    }

    rope_kernel<<<BTd, 256>>>(q16, k16);

    // scores (z=2, causal tile skip)
    {
        GA ga = {};
        for (int b = 0; b < Bd; b++) {
            ga.A[b] = q16 + (size_t)b*Td*Hd;
            ga.B[b] = k16 + (size_t)b*Td*Hd;
            ga.C[b] = sc16 + (size_t)b*Td*Td;
            ga.M[b] = Td; ga.N[b] = Td; ga.K[b] = Hd;
            ga.lda[b] = Hd; ga.ldb[b] = Hd; ga.ldc[b] = Td;
        }
        gemm7<5,true,false><<<dim3(Td/256, Td/128, Bd), 512, SMEM_BYTES>>>(ga);
    }
    softmax_kernel<<<dim3(Td, Bd), 256>>>(sc16);
    // PV (z=2): y[b] = attn[b] @ vT[b]^T, causal K-limit
    {
        GA ga = {};
        for (int b = 0; b < Bd; b++) {
            ga.A[b] = sc16 + (size_t)b*Td*Td;
            ga.B[b] = vT16 + (size_t)b*Hd*Td;
            ga.C[b] = y16 + (size_t)b*Td*Hd;
            ga.M[b] = Td; ga.N[b] = Hd; ga.K[b] = Td;
            ga.lda[b] = Td; ga.ldb[b] = Td; ga.ldc[b] = Hd;
        }
        gemm7<0,true,true><<<dim3(Hd/256, Td/128, Bd), 512, SMEM_BYTES>>>(ga);
    }
    // x1 = x + y @ o_proj.T  (fp32 out)
    {
        GA ga = {};
        ga.A[0] = y16; ga.B[0] = w16 + W_OPJ; ga.C[0] = x1; ga.aux[0] = x;
        ga.M[0] = BTd; ga.N[0] = Hd; ga.K[0] = Hd;
        ga.lda[0] = Hd; ga.ldb[0] = Hd; ga.ldc[0] = Hd;
        gemm7<3,false,false><<<dim3(Hd/256, BTd/128, 1), 512, SMEM_BYTES>>>(ga);
    }

    // ---- MoE ----
    ln_kernel<<<BTd, 256>>>(x1, ln2w, h2_16, h2);
    router_kernel<<<BTd, 256>>>(h2, router_w, router_b);

    __half* shg = gbuf16 + (size_t)7 * ESL;
    // merged gate (silu): z0..6 routed experts (gathered), z7 shared (dense)
    {
        GA ga = {};
        for (int e = 0; e < Ed; e++) {
            ga.A[e] = h2_16;
            ga.B[e] = w16 + W_EXG + (size_t)e * Fd * Hd;
            ga.C[e] = gbuf16 + (size_t)e * ESL;
        }
        ga.A[7] = h2_16; ga.B[7] = w16 + W_SHG; ga.C[7] = shg;
        for (int zz = 0; zz < 8; zz++) {
            ga.M[zz] = BTd; ga.N[zz] = Fd; ga.K[zz] = Hd;
            ga.lda[zz] = Hd; ga.ldb[zz] = Hd; ga.ldc[zz] = Fd;
        }
        ga.ngather = Ed;
        ga.gcnt = cnt; ga.gidx = gidx; ga.gwt = gwt; ga.gslot = gslot;
        gemm7<1,true,false><<<dim3(Fd/256, BTd/128, 8), 512, SMEM_BYTES>>>(ga);
    }
    // merged up (in-place multiply): z0..6 routed (gathered), z7 shared
    {
        GA ga = {};
        for (int e = 0; e < Ed; e++) {
            ga.A[e] = h2_16;
            ga.B[e] = w16 + W_EXU + (size_t)e * Fd * Hd;
            ga.C[e] = gbuf16 + (size_t)e * ESL;
            ga.aux[e] = gbuf16 + (size_t)e * ESL;
        }
        ga.A[7] = h2_16; ga.B[7] = w16 + W_SHU; ga.C[7] = shg; ga.aux[7] = shg;
        for (int zz = 0; zz < 8; zz++) {
            ga.M[zz] = BTd; ga.N[zz] = Fd; ga.K[zz] = Hd;
            ga.lda[zz] = Hd; ga.ldb[zz] = Hd; ga.ldc[zz] = Fd;
        }
        ga.ngather = Ed;
        ga.gcnt = cnt; ga.gidx = gidx; ga.gwt = gwt; ga.gslot = gslot;
        gemm7<2,true,false><<<dim3(Fd/256, BTd/128, 8), 512, SMEM_BYTES>>>(ga);
    }
    // shared down (fp32 out)
    {
        GA ga = {};
        ga.A[0] = shg; ga.B[0] = w16 + W_SHD; ga.C[0] = shb;
        ga.M[0] = BTd; ga.N[0] = Hd; ga.K[0] = Fd;
        ga.lda[0] = Fd; ga.ldb[0] = Fd; ga.ldc[0] = Hd;
        gemm7<0,false,false><<<dim3(Hd/256, BTd/128, 1), 512, SMEM_BYTES>>>(ga);
    }
    // expert down (scatter), z0..6
    {
        GA ga = {};
        for (int e = 0; e < Ed; e++) {
            ga.A[e] = gbuf16 + (size_t)e * ESL;
            ga.B[e] = w16 + W_EXD + (size_t)e * Hd * Fd;
            ga.M[e] = BTd; ga.N[e] = Hd; ga.K[e] = Fd;
            ga.lda[e] = Fd; ga.ldb[e] = Fd; ga.ldc[e] = Hd;
        }
        ga.r0 = r0; ga.r1 = r1;
        ga.ngather = 0;
        ga.gcnt = cnt; ga.gidx = gidx; ga.gwt = gwt; ga.gslot = gslot;
        gemm7<4,false,false><<<dim3(Hd/256, BTd/128, Ed), 512, SMEM_BYTES>>>(ga);
    }

    final_add_kernel<<<(BTd * Hd) / 256, 256>>>(x1, shb, r0, r1, out);
}